// round 1
// baseline (speedup 1.0000x reference)
#include <cuda_runtime.h>
#include <math.h>
#include <cstdint>

// ---- problem constants (fixed shapes) ----
#define NND 8192      // nodes
#define NF  512       // in features
#define NH  64        // hidden
#define NRel 16       // relations
#define NBase 30      // bases
#define NE  524288    // edges
#define NBc 64        // conversations (batch)
#define NL  128       // seq len
#define NDm 576       // D_EMO = 512+64
#define NC  7         // classes

// ---- scratch (static device memory; no allocations allowed) ----
__device__ float g_Wt[NF * NRel * NH];            // [512][1024]  W transposed: Wt[k][r*64+h]
__device__ float g_xw[(size_t)NND * NRel * NH];   // [8192][1024]
__device__ float g_agg[NND * NH];
__device__ float g_deg[NND];
__device__ float g_h1[NND * NH];
__device__ float g_y[NND * NH];
__device__ float g_nb[NND * NH];
__device__ float g_emo[(size_t)NND * NDm];
__device__ float g_Q[(size_t)NND * NDm];
__device__ float g_S[(size_t)NBc * NL * NL];
__device__ float g_att[(size_t)NND * NDm];
__device__ float g_hid[NND * NH];

// ============================================================
// Generic tiled fp32 GEMM: C = A[M,K] @ B[K,N]  (+bias[n]) (+D[m,n]) (relu)
// BM=128, BN=64, BK=16, 256 threads, 8x4 per-thread microtile.
// Requires: M%128==0, N%64==0, K%16==0 (true for all call sites),
// all leading dims %4==0, base pointers 16B aligned.
// blockIdx.z = batch index with given strides.
// ============================================================
template <bool ADD_D, bool BIAS, bool RELU>
__global__ void __launch_bounds__(256)
gemm_kernel(const float* __restrict__ A, int lda, long long sA,
            const float* __restrict__ B, int ldb, long long sB,
            float* __restrict__ C, int ldc, long long sC,
            const float* __restrict__ D, int ldd,
            const float* __restrict__ bias,
            int M, int N, int K)
{
    constexpr int BM = 128, BN = 64, BK = 16;
    __shared__ float As[BK][BM];
    __shared__ float Bs[BK][BN];

    const int bz = blockIdx.z;
    A += sA * bz; B += sB * bz; C += sC * bz;

    const int m0 = blockIdx.y * BM;
    const int n0 = blockIdx.x * BN;
    const int t  = threadIdx.x;
    const int tr = t >> 4;           // 0..15 (m-group)
    const int tc = t & 15;           // 0..15 (n-group)
    const int arow = t >> 1;         // 0..127
    const int acol = (t & 1) * 8;    // 0 or 8
    const int brow = t >> 4;         // 0..15
    const int bcol = (t & 15) * 4;   // 0..60

    float acc[8][4];
#pragma unroll
    for (int i = 0; i < 8; i++)
#pragma unroll
        for (int j = 0; j < 4; j++) acc[i][j] = 0.f;

    for (int k0 = 0; k0 < K; k0 += BK) {
        float4 av0 = *(const float4*)(A + (long long)(m0 + arow) * lda + k0 + acol);
        float4 av1 = *(const float4*)(A + (long long)(m0 + arow) * lda + k0 + acol + 4);
        float4 bv  = *(const float4*)(B + (long long)(k0 + brow) * ldb + n0 + bcol);

        As[acol + 0][arow] = av0.x; As[acol + 1][arow] = av0.y;
        As[acol + 2][arow] = av0.z; As[acol + 3][arow] = av0.w;
        As[acol + 4][arow] = av1.x; As[acol + 5][arow] = av1.y;
        As[acol + 6][arow] = av1.z; As[acol + 7][arow] = av1.w;
        *(float4*)&Bs[brow][bcol] = bv;
        __syncthreads();

#pragma unroll
        for (int kk = 0; kk < BK; kk++) {
            float4 a0 = *(const float4*)&As[kk][tr * 8];
            float4 a1 = *(const float4*)&As[kk][tr * 8 + 4];
            float4 b0 = *(const float4*)&Bs[kk][tc * 4];
            float a[8] = {a0.x, a0.y, a0.z, a0.w, a1.x, a1.y, a1.z, a1.w};
            float bb[4] = {b0.x, b0.y, b0.z, b0.w};
#pragma unroll
            for (int i = 0; i < 8; i++)
#pragma unroll
                for (int j = 0; j < 4; j++)
                    acc[i][j] = fmaf(a[i], bb[j], acc[i][j]);
        }
        __syncthreads();
    }

#pragma unroll
    for (int i = 0; i < 8; i++) {
        const int m = m0 + tr * 8 + i;
#pragma unroll
        for (int j = 0; j < 4; j++) {
            const int n = n0 + tc * 4 + j;
            float v = acc[i][j];
            if (BIAS)  v += bias[n];
            if (ADD_D) v += D[(long long)m * ldd + n];
            if (RELU)  v = fmaxf(v, 0.f);
            C[(long long)m * ldc + n] = v;
        }
    }
}

// ============================================================
// Wt[k][r*64+h] = sum_b comp[r][b] * basis[b][k][h]
// ============================================================
__global__ void wt_kernel(const float* __restrict__ comp,
                          const float* __restrict__ basis,
                          float* __restrict__ Wt)
{
    int idx = blockIdx.x * 256 + threadIdx.x;      // 524288 total
    int h = idx & 63;
    int r = (idx >> 6) & 15;
    int k = idx >> 10;
    float acc = 0.f;
#pragma unroll
    for (int b = 0; b < NBase; b++)
        acc = fmaf(comp[r * NBase + b], basis[((long long)b * NF + k) * NH + h], acc);
    Wt[(long long)k * (NRel * NH) + r * NH + h] = acc;
}

__global__ void zero_kernel(float* p, int n)
{
    int i = blockIdx.x * 256 + threadIdx.x;
    if (i < n) p[i] = 0.f;
}

// copy x into emo[:, 0:512]
__global__ void copy_x_kernel(const float* __restrict__ x, float* __restrict__ emo)
{
    long long i = (long long)blockIdx.x * 256 + threadIdx.x;   // 8192*512 total
    int n = (int)(i >> 9);
    int c = (int)(i & 511);
    emo[(long long)n * NDm + c] = x[i];
}

// RGCN message scatter: agg[dst] += xw[src, etype]; deg[dst] += 1
// 16 threads per edge, 4 floats per thread.
__global__ void scatter_rgcn(const int* __restrict__ ei, const int* __restrict__ et,
                             const float* __restrict__ xw,
                             float* __restrict__ agg, float* __restrict__ deg)
{
    int t = threadIdx.x;
    int lane = t & 15;
    long long e = (long long)blockIdx.x * 16 + (t >> 4);
    if (e >= NE) return;
    int src = ei[e];
    int dst = ei[NE + e];
    int r = et[e];
    float4 v = *(const float4*)(xw + (long long)src * (NRel * NH) + r * NH + lane * 4);
    float* o = agg + (long long)dst * NH + lane * 4;
    atomicAdd(o + 0, v.x); atomicAdd(o + 1, v.y);
    atomicAdd(o + 2, v.z); atomicAdd(o + 3, v.w);
    if (lane == 0) atomicAdd(&deg[dst], 1.0f);
}

// GraphConv scatter: nb[dst] += y[src]
__global__ void scatter_gc(const int* __restrict__ ei, const float* __restrict__ y,
                           float* __restrict__ nb)
{
    int t = threadIdx.x;
    int lane = t & 15;
    long long e = (long long)blockIdx.x * 16 + (t >> 4);
    if (e >= NE) return;
    int src = ei[e];
    int dst = ei[NE + e];
    float4 v = *(const float4*)(y + (long long)src * NH + lane * 4);
    float* o = nb + (long long)dst * NH + lane * 4;
    atomicAdd(o + 0, v.x); atomicAdd(o + 1, v.y);
    atomicAdd(o + 2, v.z); atomicAdd(o + 3, v.w);
}

__global__ void divdeg_kernel(float* __restrict__ agg, const float* __restrict__ deg)
{
    int i = blockIdx.x * 256 + threadIdx.x;    // 8192*64
    agg[i] /= fmaxf(deg[i >> 6], 1.0f);
}

// ============================================================
// scores: per conversation b, S[b][q][k] = tanh( (Q_q . M_k) * u_k^2 )
// 128x128x576 NT-gemm per block; 256 threads, 8x8 microtile.
// ============================================================
__global__ void __launch_bounds__(256)
scores_kernel(const float* __restrict__ Q, const float* __restrict__ emo,
              const float* __restrict__ um, float* __restrict__ S)
{
    constexpr int BK = 32;
    __shared__ float Qs[BK][NL];
    __shared__ float Ms[BK][NL];

    const int b = blockIdx.x;
    const float* Qb = Q + (long long)b * NL * NDm;
    const float* Mb = emo + (long long)b * NL * NDm;
    const int t = threadIdx.x;
    const int tq = t >> 4, tk = t & 15;
    const int row = t >> 1;
    const int c0 = (t & 1) * 16;

    float acc[8][8];
#pragma unroll
    for (int i = 0; i < 8; i++)
#pragma unroll
        for (int j = 0; j < 8; j++) acc[i][j] = 0.f;

    for (int d0 = 0; d0 < NDm; d0 += BK) {
#pragma unroll
        for (int i = 0; i < 4; i++) {
            float4 qv = *(const float4*)(Qb + (long long)row * NDm + d0 + c0 + i * 4);
            float4 mv = *(const float4*)(Mb + (long long)row * NDm + d0 + c0 + i * 4);
            Qs[c0 + i * 4 + 0][row] = qv.x; Qs[c0 + i * 4 + 1][row] = qv.y;
            Qs[c0 + i * 4 + 2][row] = qv.z; Qs[c0 + i * 4 + 3][row] = qv.w;
            Ms[c0 + i * 4 + 0][row] = mv.x; Ms[c0 + i * 4 + 1][row] = mv.y;
            Ms[c0 + i * 4 + 2][row] = mv.z; Ms[c0 + i * 4 + 3][row] = mv.w;
        }
        __syncthreads();
#pragma unroll
        for (int kk = 0; kk < BK; kk++) {
            float4 q0 = *(const float4*)&Qs[kk][tq * 8];
            float4 q1 = *(const float4*)&Qs[kk][tq * 8 + 4];
            float4 m0 = *(const float4*)&Ms[kk][tk * 8];
            float4 m1 = *(const float4*)&Ms[kk][tk * 8 + 4];
            float qa[8] = {q0.x, q0.y, q0.z, q0.w, q1.x, q1.y, q1.z, q1.w};
            float ma[8] = {m0.x, m0.y, m0.z, m0.w, m1.x, m1.y, m1.z, m1.w};
#pragma unroll
            for (int i = 0; i < 8; i++)
#pragma unroll
                for (int j = 0; j < 8; j++)
                    acc[i][j] = fmaf(qa[i], ma[j], acc[i][j]);
        }
        __syncthreads();
    }

#pragma unroll
    for (int i = 0; i < 8; i++) {
        int q = tq * 8 + i;
#pragma unroll
        for (int j = 0; j < 8; j++) {
            int k = tk * 8 + j;
            float u = um[b * NL + k];
            S[((long long)b * NL + q) * NL + k] = tanhf(acc[i][j] * u * u);
        }
    }
}

// softmax over k (128) per (b,q) row, with umask re-weighting + renorm.
__global__ void softmax_kernel(float* __restrict__ S, const float* __restrict__ um)
{
    __shared__ float red[NL];
    const int row = blockIdx.x;        // b*128 + q
    const int b = row >> 7;
    const int k = threadIdx.x;

    float s = S[(long long)row * NL + k];
    red[k] = s; __syncthreads();
#pragma unroll
    for (int o = 64; o > 0; o >>= 1) { if (k < o) red[k] = fmaxf(red[k], red[k + o]); __syncthreads(); }
    float mx = red[0]; __syncthreads();

    float e = expf(s - mx);
    red[k] = e; __syncthreads();
#pragma unroll
    for (int o = 64; o > 0; o >>= 1) { if (k < o) red[k] += red[k + o]; __syncthreads(); }
    float sum1 = red[0]; __syncthreads();

    float a = (e / sum1) * um[b * NL + k];
    red[k] = a; __syncthreads();
#pragma unroll
    for (int o = 64; o > 0; o >>= 1) { if (k < o) red[k] += red[k + o]; __syncthreads(); }
    float sum2 = red[0];

    S[(long long)row * NL + k] = a / sum2;
}

// head: logits = hidden[n] @ Ws + bs ; log_softmax over 7 classes
__global__ void head_kernel(const float* __restrict__ hid, const float* __restrict__ Ws,
                            const float* __restrict__ bsv, float* __restrict__ out)
{
    int n = blockIdx.x * blockDim.x + threadIdx.x;
    if (n >= NND) return;
    float lg[NC];
#pragma unroll
    for (int c = 0; c < NC; c++) lg[c] = bsv[c];
    const float* h = hid + (long long)n * NH;
#pragma unroll 8
    for (int k = 0; k < NH; k++) {
        float hv = h[k];
#pragma unroll
        for (int c = 0; c < NC; c++) lg[c] = fmaf(hv, Ws[k * NC + c], lg[c]);
    }
    float mx = lg[0];
#pragma unroll
    for (int c = 1; c < NC; c++) mx = fmaxf(mx, lg[c]);
    float ssum = 0.f;
#pragma unroll
    for (int c = 0; c < NC; c++) ssum += expf(lg[c] - mx);
    float lse = mx + logf(ssum);
#pragma unroll
    for (int c = 0; c < NC; c++) out[(long long)n * NC + c] = lg[c] - lse;
}

// ============================================================
extern "C" void kernel_launch(void* const* d_in, const int* in_sizes, int n_in,
                              void* d_out, int out_size)
{
    const float* x      = (const float*)d_in[0];
    const int*   ei     = (const int*)d_in[1];
    const int*   et     = (const int*)d_in[3];
    const float* umask  = (const float*)d_in[5];
    const float* basis  = (const float*)d_in[8];
    const float* comp   = (const float*)d_in[9];
    const float* root   = (const float*)d_in[10];
    const float* bias1  = (const float*)d_in[11];
    const float* w_nbr  = (const float*)d_in[12];
    const float* w_root = (const float*)d_in[13];
    const float* bias2  = (const float*)d_in[14];
    const float* Wm     = (const float*)d_in[15];
    const float* bm     = (const float*)d_in[16];
    const float* Wl     = (const float*)d_in[17];
    const float* bl     = (const float*)d_in[18];
    const float* Ws     = (const float*)d_in[19];
    const float* bs     = (const float*)d_in[20];
    float* out = (float*)d_out;

    float *Wt, *xw, *agg, *deg, *h1, *y, *nb, *emo, *Q, *S, *att, *hid;
    cudaGetSymbolAddress((void**)&Wt,  g_Wt);
    cudaGetSymbolAddress((void**)&xw,  g_xw);
    cudaGetSymbolAddress((void**)&agg, g_agg);
    cudaGetSymbolAddress((void**)&deg, g_deg);
    cudaGetSymbolAddress((void**)&h1,  g_h1);
    cudaGetSymbolAddress((void**)&y,   g_y);
    cudaGetSymbolAddress((void**)&nb,  g_nb);
    cudaGetSymbolAddress((void**)&emo, g_emo);
    cudaGetSymbolAddress((void**)&Q,   g_Q);
    cudaGetSymbolAddress((void**)&S,   g_S);
    cudaGetSymbolAddress((void**)&att, g_att);
    cudaGetSymbolAddress((void**)&hid, g_hid);

    // ---- RGCN ----
    wt_kernel<<<(NF * NRel * NH) / 256, 256>>>(comp, basis, Wt);

    // xw = x @ Wt   [8192,512] x [512,1024]
    gemm_kernel<false, false, false><<<dim3(1024 / 64, NND / 128, 1), 256>>>(
        x, NF, 0, Wt, NRel * NH, 0, xw, NRel * NH, 0, nullptr, 0, nullptr, NND, NRel * NH, NF);

    copy_x_kernel<<<(NND * NF) / 256, 256>>>(x, emo);

    zero_kernel<<<(NND * NH + 255) / 256, 256>>>(agg, NND * NH);
    zero_kernel<<<(NND + 255) / 256, 256>>>(deg, NND);
    zero_kernel<<<(NND * NH + 255) / 256, 256>>>(nb, NND * NH);

    scatter_rgcn<<<NE / 16, 256>>>(ei, et, xw, agg, deg);
    divdeg_kernel<<<(NND * NH) / 256, 256>>>(agg, deg);

    // h1 = agg/deg + x @ root + bias1
    gemm_kernel<true, true, false><<<dim3(1, NND / 128, 1), 256>>>(
        x, NF, 0, root, NH, 0, h1, NH, 0, agg, NH, bias1, NND, NH, NF);

    // ---- GraphConv ----
    // y = h1 @ w_nbr
    gemm_kernel<false, false, false><<<dim3(1, NND / 128, 1), 256>>>(
        h1, NH, 0, w_nbr, NH, 0, y, NH, 0, nullptr, 0, nullptr, NND, NH, NH);

    scatter_gc<<<NE / 16, 256>>>(ei, y, nb);

    // h2 = nb + h1 @ w_root + bias2  -> written into emo[:, 512:576]
    gemm_kernel<true, true, false><<<dim3(1, NND / 128, 1), 256>>>(
        h1, NH, 0, w_root, NH, 0, emo + NF, NDm, 0, nb, NH, bias2, NND, NH, NH);

    // ---- attention ----
    // Q = emo @ Wm + bm
    gemm_kernel<false, true, false><<<dim3(NDm / 64, NND / 128, 1), 256>>>(
        emo, NDm, 0, Wm, NDm, 0, Q, NDm, 0, nullptr, 0, bm, NND, NDm, NDm);

    scores_kernel<<<NBc, 256>>>(Q, emo, umask, S);
    softmax_kernel<<<NND, NL>>>(S, umask);

    // att_b = alpha_b @ emo_b   (batched over 64 conversations)
    gemm_kernel<false, false, false><<<dim3(NDm / 64, 1, NBc), 256>>>(
        S, NL, (long long)NL * NL, emo, NDm, (long long)NL * NDm,
        att, NDm, (long long)NL * NDm, nullptr, 0, nullptr, NL, NDm, NL);

    // hidden = relu(att @ Wl + bl)
    gemm_kernel<false, true, true><<<dim3(1, NND / 128, 1), 256>>>(
        att, NDm, 0, Wl, NH, 0, hid, NH, 0, nullptr, 0, bl, NND, NH, NDm);

    head_kernel<<<NND / 128, 128>>>(hid, Ws, bs, out);

    (void)in_sizes; (void)n_in; (void)out_size;
}

// round 2
// speedup vs baseline: 1.0339x; 1.0339x over previous
#include <cuda_runtime.h>
#include <math.h>
#include <cstdint>

// ---- problem constants (fixed shapes) ----
#define NND 8192      // nodes
#define NF  512       // in features
#define NH  64        // hidden
#define NRel 16       // relations
#define NBase 30      // bases
#define NE  524288    // edges
#define NBc 64        // conversations (batch)
#define NL  128       // seq len
#define NDm 576       // D_EMO = 512+64
#define NC  7         // classes

// ---- scratch (static device memory; no allocations allowed) ----
__device__ float g_Wt[NF * NRel * NH];            // [512][1024]
__device__ float g_xw[(size_t)NND * NRel * NH];   // [8192][1024]
__device__ float g_agg[NND * NH];
__device__ float g_h1[NND * NH];
__device__ float g_y[NND * NH];
__device__ float g_nb[NND * NH];
__device__ float g_emo[(size_t)NND * NDm];
__device__ float g_Q[(size_t)NND * NDm];
__device__ float g_S[(size_t)NBc * NL * NL];
__device__ float g_att[(size_t)NND * NDm];
__device__ float g_hid[NND * NH];
// CSR scratch
__device__ int g_cnt[NND];
__device__ int g_off[NND + 1];
__device__ int g_cur[NND];
__device__ int g_eidx[NE];    // packed src*16 + rel

// ---- f32x2 packed-FMA helpers ----
__device__ __forceinline__ unsigned long long pk2(float lo, float hi) {
    unsigned long long r;
    asm("mov.b64 %0, {%1, %2};" : "=l"(r) : "f"(lo), "f"(hi));
    return r;
}
__device__ __forceinline__ unsigned long long fma2(unsigned long long a,
                                                   unsigned long long b,
                                                   unsigned long long c) {
    unsigned long long d;
    asm("fma.rn.f32x2 %0, %1, %2, %3;" : "=l"(d) : "l"(a), "l"(b), "l"(c));
    return d;
}
__device__ __forceinline__ float2 up2(unsigned long long v) {
    float2 f;
    asm("mov.b64 {%0, %1}, %2;" : "=f"(f.x), "=f"(f.y) : "l"(v));
    return f;
}

// ============================================================
// f32x2 tiled GEMM: C = A[M,K] @ B[K,N] (+bias[n]) (+D) (relu)
// BM=128, BK=16, 8x8 microtile, accumulators n-packed in b64.
// BN=64 -> 128 threads ; BN=128 -> 256 threads.
// Requires M%128==0, N%BN==0, K%16==0, lda/ldb/ldc/ldd %4==0.
// ============================================================
template <int BN, int THREADS, bool ADD_D, bool BIAS, bool RELU>
__global__ void __launch_bounds__(THREADS)
gemm_f2(const float* __restrict__ A, int lda, long long sA,
        const float* __restrict__ B, int ldb, long long sB,
        float* __restrict__ C, int ldc, long long sC,
        const float* __restrict__ D, int ldd,
        const float* __restrict__ bias,
        int M, int N, int K)
{
    constexpr int BM = 128, BK = 16;
    constexpr int NCOL = BN / 8;               // microtile columns in block
    constexpr int EPTA = BM * BK / THREADS;    // A floats per thread (16 or 8)
    constexpr int FA = EPTA / 4;
    __shared__ float As[BK][BM];
    __shared__ float Bs[BK][BN];

    const int bz = blockIdx.z;
    A += sA * bz; B += sB * bz; C += sC * bz;

    const int m0 = blockIdx.y * BM;
    const int n0 = blockIdx.x * BN;
    const int t = threadIdx.x;
    const int tr = t / NCOL;   // 0..15
    const int tc = t % NCOL;

    unsigned long long acc[8][4];
#pragma unroll
    for (int i = 0; i < 8; i++)
#pragma unroll
        for (int q = 0; q < 4; q++) acc[i][q] = 0ull;

    for (int k0 = 0; k0 < K; k0 += BK) {
#pragma unroll
        for (int f = 0; f < FA; f++) {
            int idx = t * EPTA + f * 4;
            int ar = idx / BK, ac = idx % BK;
            float4 v = *(const float4*)(A + (size_t)(m0 + ar) * lda + k0 + ac);
            As[ac + 0][ar] = v.x; As[ac + 1][ar] = v.y;
            As[ac + 2][ar] = v.z; As[ac + 3][ar] = v.w;
        }
#pragma unroll
        for (int f = 0; f < 2; f++) {
            int idx = t * 8 + f * 4;
            int br = idx / BN, bc = idx % BN;
            *(float4*)&Bs[br][bc] =
                *(const float4*)(B + (size_t)(k0 + br) * ldb + n0 + bc);
        }
        __syncthreads();

#pragma unroll
        for (int kk = 0; kk < BK; kk++) {
            float4 a0 = *(const float4*)&As[kk][tr * 8];
            float4 a1 = *(const float4*)&As[kk][tr * 8 + 4];
            float av[8] = {a0.x, a0.y, a0.z, a0.w, a1.x, a1.y, a1.z, a1.w};
            unsigned long long b2[4];
#pragma unroll
            for (int q = 0; q < 4; q++)
                b2[q] = *(const unsigned long long*)&Bs[kk][tc * 8 + q * 2];
#pragma unroll
            for (int i = 0; i < 8; i++) {
                unsigned long long ad = pk2(av[i], av[i]);
#pragma unroll
                for (int q = 0; q < 4; q++)
                    acc[i][q] = fma2(ad, b2[q], acc[i][q]);
            }
        }
        __syncthreads();
    }

#pragma unroll
    for (int i = 0; i < 8; i++) {
        const int m = m0 + tr * 8 + i;
#pragma unroll
        for (int q = 0; q < 4; q++) {
            const int n = n0 + tc * 8 + q * 2;
            float2 v = up2(acc[i][q]);
            if (BIAS)  { v.x += bias[n]; v.y += bias[n + 1]; }
            if (ADD_D) { v.x += D[(size_t)m * ldd + n];
                         v.y += D[(size_t)m * ldd + n + 1]; }
            if (RELU)  { v.x = fmaxf(v.x, 0.f); v.y = fmaxf(v.y, 0.f); }
            *(float2*)&C[(size_t)m * ldc + n] = v;
        }
    }
}

// ============================================================
// Wt[k][r*64+h] = sum_b comp[r][b] * basis[b][k][h]
// ============================================================
__global__ void wt_kernel(const float* __restrict__ comp,
                          const float* __restrict__ basis,
                          float* __restrict__ Wt)
{
    int idx = blockIdx.x * 256 + threadIdx.x;      // 524288 total
    int h = idx & 63;
    int r = (idx >> 6) & 15;
    int k = idx >> 10;
    float acc = 0.f;
#pragma unroll
    for (int b = 0; b < NBase; b++)
        acc = fmaf(comp[r * NBase + b], basis[((long long)b * NF + k) * NH + h], acc);
    Wt[(long long)k * (NRel * NH) + r * NH + h] = acc;
}

// copy x into emo[:, 0:512]
__global__ void copy_x_kernel(const float* __restrict__ x, float* __restrict__ emo)
{
    long long i = (long long)blockIdx.x * 256 + threadIdx.x;   // 8192*512 total
    int n = (int)(i >> 9);
    int c = (int)(i & 511);
    emo[(long long)n * NDm + c] = x[i];
}

// ---- CSR build ----
__global__ void zero_cnt_kernel(int* cnt)
{
    int i = blockIdx.x * 256 + threadIdx.x;
    if (i < NND) cnt[i] = 0;
}

__global__ void hist_kernel(const int* __restrict__ ei, int* __restrict__ cnt)
{
    int i = blockIdx.x * 256 + threadIdx.x;
    if (i < NE) atomicAdd(&cnt[ei[NE + i]], 1);
}

// single-block inclusive scan over 8192 counts -> off[1..8192], cur = exclusive
__global__ void __launch_bounds__(1024)
scan_kernel(const int* __restrict__ cnt, int* __restrict__ off, int* __restrict__ cur)
{
    __shared__ int s[NND];
    int t = threadIdx.x;
    for (int i = t; i < NND; i += 1024) s[i] = cnt[i];
    __syncthreads();
    for (int d = 1; d < NND; d <<= 1) {
        int v[8];
#pragma unroll
        for (int k = 0; k < 8; k++) {
            int i = t + k * 1024;
            v[k] = (i >= d) ? s[i - d] : 0;
        }
        __syncthreads();
#pragma unroll
        for (int k = 0; k < 8; k++) s[t + k * 1024] += v[k];
        __syncthreads();
    }
    for (int i = t; i < NND; i += 1024) {
        off[i + 1] = s[i];
        cur[i] = (i == 0) ? 0 : s[i - 1];
    }
    if (t == 0) off[0] = 0;
}

__global__ void fill_kernel(const int* __restrict__ ei, const int* __restrict__ et,
                            int* __restrict__ cur, int* __restrict__ eidx)
{
    int i = blockIdx.x * 256 + threadIdx.x;
    if (i >= NE) return;
    int dst = ei[NE + i];
    int pos = atomicAdd(&cur[dst], 1);
    eidx[pos] = ei[i] * 16 + et[i];
}

// ---- CSR gathers (no atomics) ----
// one block (64 threads) per node; thread = hidden column
__global__ void __launch_bounds__(64)
rgcn_gather(const int* __restrict__ off, const int* __restrict__ eidx,
            const float* __restrict__ xw, float* __restrict__ agg)
{
    const int n = blockIdx.x;
    const int h = threadIdx.x;
    const int beg = off[n], end = off[n + 1];
    float acc = 0.f;
    int e = beg;
    for (; e + 4 <= end; e += 4) {
        int p0 = eidx[e], p1 = eidx[e + 1], p2 = eidx[e + 2], p3 = eidx[e + 3];
        float v0 = xw[(size_t)(p0 >> 4) * 1024 + (p0 & 15) * 64 + h];
        float v1 = xw[(size_t)(p1 >> 4) * 1024 + (p1 & 15) * 64 + h];
        float v2 = xw[(size_t)(p2 >> 4) * 1024 + (p2 & 15) * 64 + h];
        float v3 = xw[(size_t)(p3 >> 4) * 1024 + (p3 & 15) * 64 + h];
        acc += v0 + v1 + v2 + v3;
    }
    for (; e < end; e++) {
        int p = eidx[e];
        acc += xw[(size_t)(p >> 4) * 1024 + (p & 15) * 64 + h];
    }
    agg[n * NH + h] = acc / fmaxf((float)(end - beg), 1.f);
}

__global__ void __launch_bounds__(64)
gc_gather(const int* __restrict__ off, const int* __restrict__ eidx,
          const float* __restrict__ y, float* __restrict__ nb)
{
    const int n = blockIdx.x;
    const int h = threadIdx.x;
    const int beg = off[n], end = off[n + 1];
    float acc = 0.f;
    int e = beg;
    for (; e + 4 <= end; e += 4) {
        int p0 = eidx[e], p1 = eidx[e + 1], p2 = eidx[e + 2], p3 = eidx[e + 3];
        acc += y[(p0 >> 4) * NH + h] + y[(p1 >> 4) * NH + h]
             + y[(p2 >> 4) * NH + h] + y[(p3 >> 4) * NH + h];
    }
    for (; e < end; e++)
        acc += y[(eidx[e] >> 4) * NH + h];
    nb[n * NH + h] = acc;
}

// ============================================================
// scores: S[b][q][k] = tanh( (Q_q . M_k) * u_k^2 ), f32x2 inner loop
// ============================================================
__global__ void __launch_bounds__(256)
scores_kernel(const float* __restrict__ Q, const float* __restrict__ emo,
              const float* __restrict__ um, float* __restrict__ S)
{
    constexpr int BK = 32;
    __shared__ float Qs[BK][NL];
    __shared__ float Ms[BK][NL];

    const int b = blockIdx.x;
    const float* Qb = Q + (long long)b * NL * NDm;
    const float* Mb = emo + (long long)b * NL * NDm;
    const int t = threadIdx.x;
    const int tq = t >> 4, tk = t & 15;
    const int row = t >> 1;
    const int c0 = (t & 1) * 16;

    unsigned long long acc[8][4];
#pragma unroll
    for (int i = 0; i < 8; i++)
#pragma unroll
        for (int j = 0; j < 4; j++) acc[i][j] = 0ull;

    for (int d0 = 0; d0 < NDm; d0 += BK) {
#pragma unroll
        for (int i = 0; i < 4; i++) {
            float4 qv = *(const float4*)(Qb + (long long)row * NDm + d0 + c0 + i * 4);
            float4 mv = *(const float4*)(Mb + (long long)row * NDm + d0 + c0 + i * 4);
            Qs[c0 + i * 4 + 0][row] = qv.x; Qs[c0 + i * 4 + 1][row] = qv.y;
            Qs[c0 + i * 4 + 2][row] = qv.z; Qs[c0 + i * 4 + 3][row] = qv.w;
            Ms[c0 + i * 4 + 0][row] = mv.x; Ms[c0 + i * 4 + 1][row] = mv.y;
            Ms[c0 + i * 4 + 2][row] = mv.z; Ms[c0 + i * 4 + 3][row] = mv.w;
        }
        __syncthreads();
#pragma unroll
        for (int kk = 0; kk < BK; kk++) {
            float4 q0 = *(const float4*)&Qs[kk][tq * 8];
            float4 q1 = *(const float4*)&Qs[kk][tq * 8 + 4];
            float qa[8] = {q0.x, q0.y, q0.z, q0.w, q1.x, q1.y, q1.z, q1.w};
            unsigned long long m2[4];
#pragma unroll
            for (int j = 0; j < 4; j++)
                m2[j] = *(const unsigned long long*)&Ms[kk][tk * 8 + j * 2];
#pragma unroll
            for (int i = 0; i < 8; i++) {
                unsigned long long qd = pk2(qa[i], qa[i]);
#pragma unroll
                for (int j = 0; j < 4; j++)
                    acc[i][j] = fma2(qd, m2[j], acc[i][j]);
            }
        }
        __syncthreads();
    }

#pragma unroll
    for (int i = 0; i < 8; i++) {
        int q = tq * 8 + i;
#pragma unroll
        for (int j = 0; j < 4; j++) {
            float2 v = up2(acc[i][j]);
            int k = tk * 8 + j * 2;
            float u0 = um[b * NL + k], u1 = um[b * NL + k + 1];
            S[((long long)b * NL + q) * NL + k]     = tanhf(v.x * u0 * u0);
            S[((long long)b * NL + q) * NL + k + 1] = tanhf(v.y * u1 * u1);
        }
    }
}

// softmax over k (128) per (b,q) row, with umask re-weighting + renorm.
__global__ void softmax_kernel(float* __restrict__ S, const float* __restrict__ um)
{
    __shared__ float red[NL];
    const int row = blockIdx.x;        // b*128 + q
    const int b = row >> 7;
    const int k = threadIdx.x;

    float s = S[(long long)row * NL + k];
    red[k] = s; __syncthreads();
#pragma unroll
    for (int o = 64; o > 0; o >>= 1) { if (k < o) red[k] = fmaxf(red[k], red[k + o]); __syncthreads(); }
    float mx = red[0]; __syncthreads();

    float e = expf(s - mx);
    red[k] = e; __syncthreads();
#pragma unroll
    for (int o = 64; o > 0; o >>= 1) { if (k < o) red[k] += red[k + o]; __syncthreads(); }
    float sum1 = red[0]; __syncthreads();

    float a = (e / sum1) * um[b * NL + k];
    red[k] = a; __syncthreads();
#pragma unroll
    for (int o = 64; o > 0; o >>= 1) { if (k < o) red[k] += red[k + o]; __syncthreads(); }
    float sum2 = red[0];

    S[(long long)row * NL + k] = a / sum2;
}

// head: logits = hidden[n] @ Ws + bs ; log_softmax over 7 classes
__global__ void head_kernel(const float* __restrict__ hid, const float* __restrict__ Ws,
                            const float* __restrict__ bsv, float* __restrict__ out)
{
    int n = blockIdx.x * blockDim.x + threadIdx.x;
    if (n >= NND) return;
    float lg[NC];
#pragma unroll
    for (int c = 0; c < NC; c++) lg[c] = bsv[c];
    const float* h = hid + (long long)n * NH;
#pragma unroll 8
    for (int k = 0; k < NH; k++) {
        float hv = h[k];
#pragma unroll
        for (int c = 0; c < NC; c++) lg[c] = fmaf(hv, Ws[k * NC + c], lg[c]);
    }
    float mx = lg[0];
#pragma unroll
    for (int c = 1; c < NC; c++) mx = fmaxf(mx, lg[c]);
    float ssum = 0.f;
#pragma unroll
    for (int c = 0; c < NC; c++) ssum += expf(lg[c] - mx);
    float lse = mx + logf(ssum);
#pragma unroll
    for (int c = 0; c < NC; c++) out[(long long)n * NC + c] = lg[c] - lse;
}

// ============================================================
extern "C" void kernel_launch(void* const* d_in, const int* in_sizes, int n_in,
                              void* d_out, int out_size)
{
    const float* x      = (const float*)d_in[0];
    const int*   ei     = (const int*)d_in[1];
    const int*   et     = (const int*)d_in[3];
    const float* umask  = (const float*)d_in[5];
    const float* basis  = (const float*)d_in[8];
    const float* comp   = (const float*)d_in[9];
    const float* root   = (const float*)d_in[10];
    const float* bias1  = (const float*)d_in[11];
    const float* w_nbr  = (const float*)d_in[12];
    const float* w_root = (const float*)d_in[13];
    const float* bias2  = (const float*)d_in[14];
    const float* Wm     = (const float*)d_in[15];
    const float* bm     = (const float*)d_in[16];
    const float* Wl     = (const float*)d_in[17];
    const float* bl     = (const float*)d_in[18];
    const float* Ws     = (const float*)d_in[19];
    const float* bs     = (const float*)d_in[20];
    float* out = (float*)d_out;

    float *Wt, *xw, *agg, *h1, *y, *nb, *emo, *Q, *S, *att, *hid;
    int *cnt, *off, *cur, *eidx;
    cudaGetSymbolAddress((void**)&Wt,  g_Wt);
    cudaGetSymbolAddress((void**)&xw,  g_xw);
    cudaGetSymbolAddress((void**)&agg, g_agg);
    cudaGetSymbolAddress((void**)&h1,  g_h1);
    cudaGetSymbolAddress((void**)&y,   g_y);
    cudaGetSymbolAddress((void**)&nb,  g_nb);
    cudaGetSymbolAddress((void**)&emo, g_emo);
    cudaGetSymbolAddress((void**)&Q,   g_Q);
    cudaGetSymbolAddress((void**)&S,   g_S);
    cudaGetSymbolAddress((void**)&att, g_att);
    cudaGetSymbolAddress((void**)&hid, g_hid);
    cudaGetSymbolAddress((void**)&cnt, g_cnt);
    cudaGetSymbolAddress((void**)&off, g_off);
    cudaGetSymbolAddress((void**)&cur, g_cur);
    cudaGetSymbolAddress((void**)&eidx, g_eidx);

    // ---- CSR build (independent of GEMMs) ----
    zero_cnt_kernel<<<NND / 256, 256>>>(cnt);
    hist_kernel<<<NE / 256, 256>>>(ei, cnt);
    scan_kernel<<<1, 1024>>>(cnt, off, cur);
    fill_kernel<<<NE / 256, 256>>>(ei, et, cur, eidx);

    // ---- RGCN ----
    wt_kernel<<<(NF * NRel * NH) / 256, 256>>>(comp, basis, Wt);

    // xw = x @ Wt   [8192,512] x [512,1024]
    gemm_f2<128, 256, false, false, false><<<dim3(1024 / 128, NND / 128, 1), 256>>>(
        x, NF, 0, Wt, NRel * NH, 0, xw, NRel * NH, 0, nullptr, 0, nullptr,
        NND, NRel * NH, NF);

    copy_x_kernel<<<(NND * NF) / 256, 256>>>(x, emo);

    rgcn_gather<<<NND, 64>>>(off, eidx, xw, agg);

    // h1 = agg + x @ root + bias1
    gemm_f2<64, 128, true, true, false><<<dim3(1, NND / 128, 1), 128>>>(
        x, NF, 0, root, NH, 0, h1, NH, 0, agg, NH, bias1, NND, NH, NF);

    // ---- GraphConv ----
    gemm_f2<64, 128, false, false, false><<<dim3(1, NND / 128, 1), 128>>>(
        h1, NH, 0, w_nbr, NH, 0, y, NH, 0, nullptr, 0, nullptr, NND, NH, NH);

    gc_gather<<<NND, 64>>>(off, eidx, y, nb);

    // h2 = nb + h1 @ w_root + bias2  -> emo[:, 512:576]
    gemm_f2<64, 128, true, true, false><<<dim3(1, NND / 128, 1), 128>>>(
        h1, NH, 0, w_root, NH, 0, emo + NF, NDm, 0, nb, NH, bias2, NND, NH, NH);

    // ---- attention ----
    // Q = emo @ Wm + bm  [8192,576]x[576,576]
    gemm_f2<64, 128, false, true, false><<<dim3(NDm / 64, NND / 128, 1), 128>>>(
        emo, NDm, 0, Wm, NDm, 0, Q, NDm, 0, nullptr, 0, bm, NND, NDm, NDm);

    scores_kernel<<<NBc, 256>>>(Q, emo, umask, S);
    softmax_kernel<<<NND, NL>>>(S, umask);

    // att_b = alpha_b @ emo_b   (batched over 64 conversations)
    gemm_f2<64, 128, false, false, false><<<dim3(NDm / 64, 1, NBc), 128>>>(
        S, NL, (long long)NL * NL, emo, NDm, (long long)NL * NDm,
        att, NDm, (long long)NL * NDm, nullptr, 0, nullptr, NL, NDm, NL);

    // hidden = relu(att @ Wl + bl)
    gemm_f2<64, 128, false, true, true><<<dim3(1, NND / 128, 1), 128>>>(
        att, NDm, 0, Wl, NH, 0, hid, NH, 0, nullptr, 0, bl, NND, NH, NDm);

    head_kernel<<<NND / 128, 128>>>(hid, Ws, bs, out);

    (void)in_sizes; (void)n_in; (void)out_size;
}

// round 4
// speedup vs baseline: 1.8642x; 1.8030x over previous
#include <cuda_runtime.h>
#include <cuda_bf16.h>
#include <math.h>
#include <cstdint>

// ---- problem constants ----
#define NND 8192
#define NF  512
#define NH  64
#define NRel 16
#define NBase 30
#define NE  524288
#define NBc 64
#define NL  128
#define NDm 576
#define NC  7
#define KC  64          // K chunk (bf16 elems) staged in SMEM

typedef __nv_bfloat16 bf16;
typedef unsigned int u32;

// ---- static device scratch ----
__device__ __align__(16) bf16 g_xh[(size_t)NND * NF];
__device__ __align__(16) bf16 g_xl[(size_t)NND * NF];
__device__ __align__(16) bf16 g_WtTh[1024 * 512];
__device__ __align__(16) bf16 g_WtTl[1024 * 512];
__device__ __align__(16) bf16 g_rootTh[64 * 512];
__device__ __align__(16) bf16 g_rootTl[64 * 512];
__device__ __align__(16) bf16 g_wnbrTh[64 * 64];
__device__ __align__(16) bf16 g_wnbrTl[64 * 64];
__device__ __align__(16) bf16 g_wrootTh[64 * 64];
__device__ __align__(16) bf16 g_wrootTl[64 * 64];
__device__ __align__(16) bf16 g_WmTh[576 * 576];
__device__ __align__(16) bf16 g_WmTl[576 * 576];
__device__ __align__(16) bf16 g_WlTh[64 * 576];
__device__ __align__(16) bf16 g_WlTl[64 * 576];
__device__ __align__(16) bf16 g_h1h[NND * NH];
__device__ __align__(16) bf16 g_h1l[NND * NH];
__device__ __align__(16) bf16 g_emoh[(size_t)NND * NDm];
__device__ __align__(16) bf16 g_emol[(size_t)NND * NDm];
__device__ __align__(16) bf16 g_emoTh[(size_t)NBc * NDm * NL];
__device__ __align__(16) bf16 g_emoTl[(size_t)NBc * NDm * NL];
__device__ __align__(16) bf16 g_Qh[(size_t)NND * NDm];
__device__ __align__(16) bf16 g_Ql[(size_t)NND * NDm];
__device__ __align__(16) bf16 g_Sh[NND * NL];
__device__ __align__(16) bf16 g_Sl[NND * NL];
__device__ __align__(16) bf16 g_atth[(size_t)NND * NDm];
__device__ __align__(16) bf16 g_attl[(size_t)NND * NDm];

__device__ __align__(16) float g_xw[(size_t)NND * NRel * NH];
__device__ __align__(16) float g_agg[NND * NH];
__device__ __align__(16) float g_y[NND * NH];
__device__ __align__(16) float g_nb[NND * NH];
__device__ __align__(16) float g_S[(size_t)NND * NL];
__device__ __align__(16) float g_hid[NND * NH];
// CSR
__device__ int g_cnt[NND];
__device__ int g_off[NND + 1];
__device__ int g_cur[NND];
__device__ int g_eidx[NE];

__device__ __forceinline__ void split_pair(float v, bf16& h, bf16& l) {
    h = __float2bfloat16(v);
    l = __float2bfloat16(v - __bfloat162float(h));
}

__device__ __forceinline__ void mma16816(float* d, const u32* a, const u32* b) {
    asm volatile(
        "mma.sync.aligned.m16n8k16.row.col.f32.bf16.bf16.f32 "
        "{%0,%1,%2,%3}, {%4,%5,%6,%7}, {%8,%9}, {%0,%1,%2,%3};"
        : "+f"(d[0]), "+f"(d[1]), "+f"(d[2]), "+f"(d[3])
        : "r"(a[0]), "r"(a[1]), "r"(a[2]), "r"(a[3]), "r"(b[0]), "r"(b[1]));
}

// ============================================================
// Warp-MMA 3xBF16 GEMM: C[M,N] = A @ B^T (A:[m][k], B:[n][k], hi/lo pairs)
// Block tile 128 x NT, warp tile 32 x 64, KC=64 staged in padded SMEM.
// THREADS = NT*2 (128 or 256). Grid: (N/NT, M/128, batch).
// ============================================================
#define ROWU 36   // u32 per padded SMEM row (64 bf16 + 8 pad)
#define ROWB 144  // bytes per padded SMEM row

template <int NT, int THREADS, bool ADD_D, bool BIAS, bool RELU, bool TANH_UM, bool OUT_PAIR>
__global__ void __launch_bounds__(THREADS)
mmt(const bf16* __restrict__ Ah, const bf16* __restrict__ Al, int lda, long long sA,
    const bf16* __restrict__ Bh, const bf16* __restrict__ Bl, int ldb, long long sB,
    float* __restrict__ C, bf16* __restrict__ Ch, bf16* __restrict__ Cl,
    int ldc, long long sC,
    const float* __restrict__ D, int ldd,
    const float* __restrict__ bias, const float* __restrict__ um,
    int K)
{
    extern __shared__ char smem[];
    float* ums = (float*)smem;                       // [NT]
    char* sAh = smem + 512;
    char* sAl = sAh + 128 * ROWB;
    char* sBh = sAl + 128 * ROWB;
    char* sBl = sBh + NT * ROWB;

    const int tid = threadIdx.x;
    const int wid = tid >> 5, lane = tid & 31;
    const int warpM = wid & 3;                       // 4 warps over M=128
    const int warpN = wid >> 2;                      // 1 or 2 over N
    const int g = lane >> 2, tg = lane & 3;
    const int bz = blockIdx.z;
    const int m0 = blockIdx.y * 128;
    const int n0 = blockIdx.x * NT;

    Ah += sA * bz; Al += sA * bz; Bh += sB * bz; Bl += sB * bz;

    if (TANH_UM && tid < NT) ums[tid] = um[bz * NL + n0 + tid];

    float acc[2][8][4];
#pragma unroll
    for (int i = 0; i < 2; i++)
#pragma unroll
        for (int j = 0; j < 8; j++)
#pragma unroll
            for (int q = 0; q < 4; q++) acc[i][j][q] = 0.f;

    const size_t ldab = (size_t)lda * 2;
    const size_t ldbb = (size_t)ldb * 2;

    for (int kc = 0; kc < K; kc += KC) {
        const char* aH = (const char*)(Ah + (size_t)m0 * lda + kc);
        const char* aL = (const char*)(Al + (size_t)m0 * lda + kc);
        const char* bH = (const char*)(Bh + (size_t)n0 * ldb + kc);
        const char* bL = (const char*)(Bl + (size_t)n0 * ldb + kc);
        __syncthreads();
#pragma unroll
        for (int f = 0; f < 1024 / THREADS; f++) {
            int id = tid + f * THREADS;
            int row = id >> 3, c16 = (id & 7) << 4;
            *(uint4*)(sAh + row * ROWB + c16) = *(const uint4*)(aH + (size_t)row * ldab + c16);
            *(uint4*)(sAl + row * ROWB + c16) = *(const uint4*)(aL + (size_t)row * ldab + c16);
        }
#pragma unroll
        for (int f = 0; f < NT * 8 / THREADS; f++) {
            int id = tid + f * THREADS;
            int row = id >> 3, c16 = (id & 7) << 4;
            *(uint4*)(sBh + row * ROWB + c16) = *(const uint4*)(bH + (size_t)row * ldbb + c16);
            *(uint4*)(sBl + row * ROWB + c16) = *(const uint4*)(bL + (size_t)row * ldbb + c16);
        }
        __syncthreads();

        const u32* Ah32 = (const u32*)sAh;
        const u32* Al32 = (const u32*)sAl;
        const u32* Bh32 = (const u32*)sBh;
        const u32* Bl32 = (const u32*)sBl;

#pragma unroll
        for (int ks = 0; ks < KC / 16; ks++) {
            const int kb = ks * 8 + tg;
            u32 ah[2][4], al[2][4];
#pragma unroll
            for (int mi = 0; mi < 2; mi++) {
                const int rb = warpM * 32 + mi * 16 + g;
                ah[mi][0] = Ah32[(rb)     * ROWU + kb];
                ah[mi][1] = Ah32[(rb + 8) * ROWU + kb];
                ah[mi][2] = Ah32[(rb)     * ROWU + kb + 4];
                ah[mi][3] = Ah32[(rb + 8) * ROWU + kb + 4];
                al[mi][0] = Al32[(rb)     * ROWU + kb];
                al[mi][1] = Al32[(rb + 8) * ROWU + kb];
                al[mi][2] = Al32[(rb)     * ROWU + kb + 4];
                al[mi][3] = Al32[(rb + 8) * ROWU + kb + 4];
            }
#pragma unroll
            for (int ni = 0; ni < 8; ni++) {
                const int nb = warpN * 64 + ni * 8 + g;
                u32 bh[2], bl[2];
                bh[0] = Bh32[nb * ROWU + kb];
                bh[1] = Bh32[nb * ROWU + kb + 4];
                bl[0] = Bl32[nb * ROWU + kb];
                bl[1] = Bl32[nb * ROWU + kb + 4];
#pragma unroll
                for (int mi = 0; mi < 2; mi++) {
                    mma16816(acc[mi][ni], ah[mi], bh);
                    mma16816(acc[mi][ni], ah[mi], bl);
                    mma16816(acc[mi][ni], al[mi], bh);
                }
            }
        }
    }

    // ---- epilogue ----
#pragma unroll
    for (int mi = 0; mi < 2; mi++) {
        const int r0 = m0 + warpM * 32 + mi * 16 + g;
#pragma unroll
        for (int ni = 0; ni < 8; ni++) {
            const int cl = warpN * 64 + ni * 8 + 2 * tg;   // col within block tile
            const int n = n0 + cl;
#pragma unroll
            for (int half = 0; half < 2; half++) {
                const int m = r0 + half * 8;
                float v0 = acc[mi][ni][half * 2];
                float v1 = acc[mi][ni][half * 2 + 1];
                if (BIAS) { v0 += bias[n]; v1 += bias[n + 1]; }
                if (ADD_D) {
                    v0 += D[(size_t)m * ldd + n];
                    v1 += D[(size_t)m * ldd + n + 1];
                }
                if (TANH_UM) {
                    float u0 = ums[cl], u1 = ums[cl + 1];
                    v0 = tanhf(v0 * u0 * u0);
                    v1 = tanhf(v1 * u1 * u1);
                }
                if (RELU) { v0 = fmaxf(v0, 0.f); v1 = fmaxf(v1, 0.f); }
                const size_t base = (size_t)sC * bz + (size_t)m * ldc + n;
                if (OUT_PAIR) {
                    bf16 h0, l0, h1, l1;
                    split_pair(v0, h0, l0);
                    split_pair(v1, h1, l1);
                    *(__nv_bfloat162*)&Ch[base] = __nv_bfloat162(h0, h1);
                    *(__nv_bfloat162*)&Cl[base] = __nv_bfloat162(l0, l1);
                } else {
                    float2 f2; f2.x = v0; f2.y = v1;
                    *(float2*)&C[base] = f2;
                }
            }
        }
    }
}

// ============================================================
// conversion / transpose kernels
// ============================================================
__global__ void cvt_pair_kernel(const float* __restrict__ src,
                                bf16* __restrict__ hi, bf16* __restrict__ lo, int n)
{
    int i = blockIdx.x * 256 + threadIdx.x;
    if (i < n) { bf16 h, l; split_pair(src[i], h, l); hi[i] = h; lo[i] = l; }
}

// src fp32 [R][C] -> dst pair [C][R]
__global__ void tcvt_kernel(const float* __restrict__ src,
                            bf16* __restrict__ hi, bf16* __restrict__ lo, int R, int C)
{
    int i = blockIdx.x * 256 + threadIdx.x;
    if (i >= R * C) return;
    int rr = i / C, cc = i % C;
    bf16 h, l; split_pair(src[i], h, l);
    hi[(size_t)cc * R + rr] = h;
    lo[(size_t)cc * R + rr] = l;
}

// WtT pairs: WtT[n=r*64+h][k] = sum_b comp[r][b]*basis[b][k][h]
__global__ void wt_kernel(const float* __restrict__ comp,
                          const float* __restrict__ basis,
                          bf16* __restrict__ Wh, bf16* __restrict__ Wl)
{
    int idx = blockIdx.x * 256 + threadIdx.x;   // 524288
    int h = idx & 63, rr = (idx >> 6) & 15, k = idx >> 10;
    float acc = 0.f;
#pragma unroll
    for (int b = 0; b < NBase; b++)
        acc = fmaf(comp[rr * NBase + b], basis[((size_t)b * NF + k) * NH + h], acc);
    bf16 hh, ll; split_pair(acc, hh, ll);
    size_t o = (size_t)(rr * 64 + h) * 512 + k;
    Wh[o] = hh; Wl[o] = ll;
}

// emo pair cols [0,512) = x pairs
__global__ void copy_x_kernel(const bf16* __restrict__ xh, const bf16* __restrict__ xl,
                              bf16* __restrict__ eh, bf16* __restrict__ el)
{
    int id = blockIdx.x * 256 + threadIdx.x;    // 8192*64
    int row = id >> 6, c = id & 63;
    *(uint4*)&eh[(size_t)row * NDm + c * 8] = *(const uint4*)&xh[(size_t)row * NF + c * 8];
    *(uint4*)&el[(size_t)row * NDm + c * 8] = *(const uint4*)&xl[(size_t)row * NF + c * 8];
}

// emoT pairs: [b][d][t] from emo pairs [b*128+t][d]
__global__ void emoT_kernel(const bf16* __restrict__ eh, const bf16* __restrict__ el,
                            bf16* __restrict__ th, bf16* __restrict__ tl)
{
    __shared__ unsigned short sh[32][33], sl[32][33];
    const int b = blockIdx.z;
    const int d0 = blockIdx.x * 32, t0 = blockIdx.y * 32;
    const int tx = threadIdx.x, ty = threadIdx.y;
#pragma unroll
    for (int q = 0; q < 4; q++) {
        int row = ty * 4 + q;
        size_t src = (size_t)(b * NL + t0 + row) * NDm + d0 + tx;
        sh[row][tx] = ((const unsigned short*)eh)[src];
        sl[row][tx] = ((const unsigned short*)el)[src];
    }
    __syncthreads();
#pragma unroll
    for (int q = 0; q < 4; q++) {
        int row = ty * 4 + q;
        size_t dst = (size_t)b * NDm * NL + (size_t)(d0 + row) * NL + t0 + tx;
        ((unsigned short*)th)[dst] = sh[tx][row];
        ((unsigned short*)tl)[dst] = sl[tx][row];
    }
}

// ---- CSR build ----
__global__ void zero_cnt_kernel(int* cnt)
{
    int i = blockIdx.x * 256 + threadIdx.x;
    if (i < NND) cnt[i] = 0;
}
__global__ void hist_kernel(const int* __restrict__ ei, int* __restrict__ cnt)
{
    int i = blockIdx.x * 256 + threadIdx.x;
    if (i < NE) atomicAdd(&cnt[ei[NE + i]], 1);
}
__global__ void __launch_bounds__(1024)
scan_kernel(const int* __restrict__ cnt, int* __restrict__ off, int* __restrict__ cur)
{
    __shared__ int s[NND];
    int t = threadIdx.x;
    for (int i = t; i < NND; i += 1024) s[i] = cnt[i];
    __syncthreads();
    for (int d = 1; d < NND; d <<= 1) {
        int v[8];
#pragma unroll
        for (int k = 0; k < 8; k++) {
            int i = t + k * 1024;
            v[k] = (i >= d) ? s[i - d] : 0;
        }
        __syncthreads();
#pragma unroll
        for (int k = 0; k < 8; k++) s[t + k * 1024] += v[k];
        __syncthreads();
    }
    for (int i = t; i < NND; i += 1024) {
        off[i + 1] = s[i];
        cur[i] = (i == 0) ? 0 : s[i - 1];
    }
    if (t == 0) off[0] = 0;
}
__global__ void fill_kernel(const int* __restrict__ ei, const int* __restrict__ et,
                            int* __restrict__ cur, int* __restrict__ eidx)
{
    int i = blockIdx.x * 256 + threadIdx.x;
    if (i >= NE) return;
    int dst = ei[NE + i];
    int pos = atomicAdd(&cur[dst], 1);
    eidx[pos] = ei[i] * 16 + et[i];
}

// ---- CSR gathers ----
__global__ void __launch_bounds__(64)
rgcn_gather(const int* __restrict__ off, const int* __restrict__ eidx,
            const float* __restrict__ xw, float* __restrict__ agg)
{
    const int n = blockIdx.x, h = threadIdx.x;
    const int beg = off[n], end = off[n + 1];
    float acc = 0.f;
    int e = beg;
    for (; e + 4 <= end; e += 4) {
        int p0 = eidx[e], p1 = eidx[e + 1], p2 = eidx[e + 2], p3 = eidx[e + 3];
        acc += xw[(size_t)(p0 >> 4) * 1024 + (p0 & 15) * 64 + h]
             + xw[(size_t)(p1 >> 4) * 1024 + (p1 & 15) * 64 + h]
             + xw[(size_t)(p2 >> 4) * 1024 + (p2 & 15) * 64 + h]
             + xw[(size_t)(p3 >> 4) * 1024 + (p3 & 15) * 64 + h];
    }
    for (; e < end; e++) {
        int p = eidx[e];
        acc += xw[(size_t)(p >> 4) * 1024 + (p & 15) * 64 + h];
    }
    agg[n * NH + h] = acc / fmaxf((float)(end - beg), 1.f);
}
__global__ void __launch_bounds__(64)
gc_gather(const int* __restrict__ off, const int* __restrict__ eidx,
          const float* __restrict__ y, float* __restrict__ nb)
{
    const int n = blockIdx.x, h = threadIdx.x;
    const int beg = off[n], end = off[n + 1];
    float acc = 0.f;
    int e = beg;
    for (; e + 4 <= end; e += 4) {
        int p0 = eidx[e], p1 = eidx[e + 1], p2 = eidx[e + 2], p3 = eidx[e + 3];
        acc += y[(p0 >> 4) * NH + h] + y[(p1 >> 4) * NH + h]
             + y[(p2 >> 4) * NH + h] + y[(p3 >> 4) * NH + h];
    }
    for (; e < end; e++) acc += y[(eidx[e] >> 4) * NH + h];
    nb[n * NH + h] = acc;
}

// softmax over k per (b,q): softmax(S)*u, renorm; emit bf16 pairs
__global__ void softmax_kernel(const float* __restrict__ S, const float* __restrict__ um,
                               bf16* __restrict__ Sh, bf16* __restrict__ Sl)
{
    __shared__ float red[NL];
    const int row = blockIdx.x;
    const int b = row >> 7;
    const int k = threadIdx.x;

    float s = S[(size_t)row * NL + k];
    red[k] = s; __syncthreads();
#pragma unroll
    for (int o = 64; o > 0; o >>= 1) { if (k < o) red[k] = fmaxf(red[k], red[k + o]); __syncthreads(); }
    float mx = red[0]; __syncthreads();

    float e = expf(s - mx);
    red[k] = e; __syncthreads();
#pragma unroll
    for (int o = 64; o > 0; o >>= 1) { if (k < o) red[k] += red[k + o]; __syncthreads(); }
    float sum1 = red[0]; __syncthreads();

    float a = (e / sum1) * um[b * NL + k];
    red[k] = a; __syncthreads();
#pragma unroll
    for (int o = 64; o > 0; o >>= 1) { if (k < o) red[k] += red[k + o]; __syncthreads(); }
    float sum2 = red[0];

    bf16 h, l; split_pair(a / sum2, h, l);
    Sh[(size_t)row * NL + k] = h;
    Sl[(size_t)row * NL + k] = l;
}

// head: logits = hid @ Ws + bs ; log_softmax
__global__ void head_kernel(const float* __restrict__ hid, const float* __restrict__ Ws,
                            const float* __restrict__ bsv, float* __restrict__ out)
{
    int n = blockIdx.x * blockDim.x + threadIdx.x;
    if (n >= NND) return;
    float lg[NC];
#pragma unroll
    for (int c = 0; c < NC; c++) lg[c] = bsv[c];
    const float* h = hid + (size_t)n * NH;
#pragma unroll 8
    for (int k = 0; k < NH; k++) {
        float hv = h[k];
#pragma unroll
        for (int c = 0; c < NC; c++) lg[c] = fmaf(hv, Ws[k * NC + c], lg[c]);
    }
    float mx = lg[0];
#pragma unroll
    for (int c = 1; c < NC; c++) mx = fmaxf(mx, lg[c]);
    float ssum = 0.f;
#pragma unroll
    for (int c = 0; c < NC; c++) ssum += expf(lg[c] - mx);
    float lse = mx + logf(ssum);
#pragma unroll
    for (int c = 0; c < NC; c++) out[(size_t)n * NC + c] = lg[c] - lse;
}

// ============================================================
extern "C" void kernel_launch(void* const* d_in, const int* in_sizes, int n_in,
                              void* d_out, int out_size)
{
    const float* x      = (const float*)d_in[0];
    const int*   ei     = (const int*)d_in[1];
    const int*   et     = (const int*)d_in[3];
    const float* umask  = (const float*)d_in[5];
    const float* basis  = (const float*)d_in[8];
    const float* comp   = (const float*)d_in[9];
    const float* root   = (const float*)d_in[10];
    const float* bias1  = (const float*)d_in[11];
    const float* w_nbr  = (const float*)d_in[12];
    const float* w_root = (const float*)d_in[13];
    const float* bias2  = (const float*)d_in[14];
    const float* Wm     = (const float*)d_in[15];
    const float* bm     = (const float*)d_in[16];
    const float* Wl     = (const float*)d_in[17];
    const float* bl     = (const float*)d_in[18];
    const float* Ws     = (const float*)d_in[19];
    const float* bs     = (const float*)d_in[20];
    float* out = (float*)d_out;

#define SYM(T, v, s) T* v; cudaGetSymbolAddress((void**)&v, s)
    SYM(bf16, xh, g_xh); SYM(bf16, xl, g_xl);
    SYM(bf16, WtTh, g_WtTh); SYM(bf16, WtTl, g_WtTl);
    SYM(bf16, rootTh, g_rootTh); SYM(bf16, rootTl, g_rootTl);
    SYM(bf16, wnbrTh, g_wnbrTh); SYM(bf16, wnbrTl, g_wnbrTl);
    SYM(bf16, wrootTh, g_wrootTh); SYM(bf16, wrootTl, g_wrootTl);
    SYM(bf16, WmTh, g_WmTh); SYM(bf16, WmTl, g_WmTl);
    SYM(bf16, WlTh, g_WlTh); SYM(bf16, WlTl, g_WlTl);
    SYM(bf16, h1h, g_h1h); SYM(bf16, h1l, g_h1l);
    SYM(bf16, emoh, g_emoh); SYM(bf16, emol, g_emol);
    SYM(bf16, emoTh, g_emoTh); SYM(bf16, emoTl, g_emoTl);
    SYM(bf16, Qh, g_Qh); SYM(bf16, Ql, g_Ql);
    SYM(bf16, Sh, g_Sh); SYM(bf16, Sl, g_Sl);
    SYM(bf16, atth, g_atth); SYM(bf16, attl, g_attl);
    SYM(float, xw, g_xw); SYM(float, agg, g_agg); SYM(float, y, g_y);
    SYM(float, nb, g_nb); SYM(float, S, g_S); SYM(float, hid, g_hid);
    SYM(int, cnt, g_cnt); SYM(int, off, g_off); SYM(int, cur, g_cur);
    SYM(int, eidx, g_eidx);
#undef SYM

    const int SZ64  = 512 + 2 * 128 * ROWB + 2 * 64 * ROWB;    // 55808
    const int SZ128 = 512 + 2 * 128 * ROWB + 2 * 128 * ROWB;   // 74240

#define SETSM(KERN, SZ) cudaFuncSetAttribute((const void*)(KERN), \
    cudaFuncAttributeMaxDynamicSharedMemorySize, SZ)
    SETSM((mmt<64, 128, false, false, false, false, false>), SZ64);
    SETSM((mmt<64, 128, true,  true,  false, false, true>),  SZ64);
    SETSM((mmt<64, 128, false, true,  false, false, true>),  SZ64);
    SETSM((mmt<128, 256, false, false, false, true,  false>), SZ128);
    SETSM((mmt<64, 128, false, false, false, false, true>),  SZ64);
    SETSM((mmt<64, 128, false, true,  true,  false, false>), SZ64);
#undef SETSM

    // ---- CSR build ----
    zero_cnt_kernel<<<NND / 256, 256>>>(cnt);
    hist_kernel<<<NE / 256, 256>>>(ei, cnt);
    scan_kernel<<<1, 1024>>>(cnt, off, cur);
    fill_kernel<<<NE / 256, 256>>>(ei, et, cur, eidx);

    // ---- operand prep ----
    cvt_pair_kernel<<<(NND * NF) / 256, 256>>>(x, xh, xl, NND * NF);
    wt_kernel<<<(NF * NRel * NH) / 256, 256>>>(comp, basis, WtTh, WtTl);
    tcvt_kernel<<<(512 * 64 + 255) / 256, 256>>>(root, rootTh, rootTl, 512, 64);
    tcvt_kernel<<<(64 * 64 + 255) / 256, 256>>>(w_nbr, wnbrTh, wnbrTl, 64, 64);
    tcvt_kernel<<<(64 * 64 + 255) / 256, 256>>>(w_root, wrootTh, wrootTl, 64, 64);
    tcvt_kernel<<<(576 * 576 + 255) / 256, 256>>>(Wm, WmTh, WmTl, 576, 576);
    tcvt_kernel<<<(576 * 64 + 255) / 256, 256>>>(Wl, WlTh, WlTl, 576, 64);

    // xw = x @ Wt  [8192,1024]
    mmt<64, 128, false, false, false, false, false><<<dim3(16, 64, 1), 128, SZ64>>>(
        xh, xl, 512, 0, WtTh, WtTl, 512, 0,
        xw, nullptr, nullptr, 1024, 0, nullptr, 0, nullptr, nullptr, 512);

    copy_x_kernel<<<(NND * 64) / 256, 256>>>(xh, xl, emoh, emol);

    rgcn_gather<<<NND, 64>>>(off, eidx, xw, agg);

    // h1 = agg + x@root + bias1 -> pairs
    mmt<64, 128, true, true, false, false, true><<<dim3(1, 64, 1), 128, SZ64>>>(
        xh, xl, 512, 0, rootTh, rootTl, 512, 0,
        nullptr, h1h, h1l, 64, 0, agg, 64, bias1, nullptr, 512);

    // y = h1 @ w_nbr  (fp32)
    mmt<64, 128, false, false, false, false, false><<<dim3(1, 64, 1), 128, SZ64>>>(
        h1h, h1l, 64, 0, wnbrTh, wnbrTl, 64, 0,
        y, nullptr, nullptr, 64, 0, nullptr, 0, nullptr, nullptr, 64);

    gc_gather<<<NND, 64>>>(off, eidx, y, nb);

    // h2 = nb + h1@w_root + bias2 -> emo pairs cols [512,576)
    mmt<64, 128, true, true, false, false, true><<<dim3(1, 64, 1), 128, SZ64>>>(
        h1h, h1l, 64, 0, wrootTh, wrootTl, 64, 0,
        nullptr, emoh + NF, emol + NF, NDm, 0, nb, 64, bias2, nullptr, 64);

    emoT_kernel<<<dim3(NDm / 32, NL / 32, NBc), dim3(32, 8)>>>(emoh, emol, emoTh, emoTl);

    // Q = emo @ Wm + bm -> pairs
    mmt<64, 128, false, true, false, false, true><<<dim3(9, 64, 1), 128, SZ64>>>(
        emoh, emol, NDm, 0, WmTh, WmTl, NDm, 0,
        nullptr, Qh, Ql, NDm, 0, nullptr, 0, bm, nullptr, NDm);

    // scores: per conv, S = tanh((Q . M) * u^2)  (fp32)
    mmt<128, 256, false, false, false, true, false><<<dim3(1, 1, NBc), 256, SZ128>>>(
        Qh, Ql, NDm, (long long)NL * NDm, emoh, emol, NDm, (long long)NL * NDm,
        S, nullptr, nullptr, NL, (long long)NL * NL,
        nullptr, 0, nullptr, umask, NDm);

    softmax_kernel<<<NND, NL>>>(S, umask, Sh, Sl);

    // att = alpha @ emo -> pairs  (B = emoT)
    mmt<64, 128, false, false, false, false, true><<<dim3(9, 1, NBc), 128, SZ64>>>(
        Sh, Sl, NL, (long long)NL * NL, emoTh, emoTl, NL, (long long)NDm * NL,
        nullptr, atth, attl, NDm, (long long)NL * NDm,
        nullptr, 0, nullptr, nullptr, NL);

    // hidden = relu(att @ Wl + bl)  (fp32)
    mmt<64, 128, false, true, true, false, false><<<dim3(1, 64, 1), 128, SZ64>>>(
        atth, attl, NDm, 0, WlTh, WlTl, NDm, 0,
        hid, nullptr, nullptr, 64, 0, nullptr, 0, bl, nullptr, NDm);

    head_kernel<<<NND / 128, 128>>>(hid, Ws, bs, out);

    (void)in_sizes; (void)n_in; (void)out_size;
}

// round 5
// speedup vs baseline: 2.0936x; 1.1230x over previous
#include <cuda_runtime.h>
#include <cuda_bf16.h>
#include <math.h>
#include <cstdint>

// ---- problem constants ----
#define NND 8192
#define NF  512
#define NH  64
#define NRel 16
#define NBase 30
#define NE  524288
#define NBc 64
#define NL  128
#define NDm 576
#define NC  7
#define KC  64          // K chunk (bf16 elems) per pipeline stage
#define ROW 144         // padded SMEM row bytes (128 data + 16 pad)

typedef __nv_bfloat16 bf16;
typedef unsigned int u32;

// ---- static device scratch ----
__device__ __align__(16) bf16 g_xh[(size_t)NND * NF];
__device__ __align__(16) bf16 g_xl[(size_t)NND * NF];
__device__ __align__(16) bf16 g_WtTh[1024 * 512];
__device__ __align__(16) bf16 g_WtTl[1024 * 512];
__device__ __align__(16) bf16 g_rootTh[64 * 512];
__device__ __align__(16) bf16 g_rootTl[64 * 512];
__device__ __align__(16) bf16 g_wnbrTh[64 * 64];
__device__ __align__(16) bf16 g_wnbrTl[64 * 64];
__device__ __align__(16) bf16 g_wrootTh[64 * 64];
__device__ __align__(16) bf16 g_wrootTl[64 * 64];
__device__ __align__(16) bf16 g_WmTh[576 * 576];
__device__ __align__(16) bf16 g_WmTl[576 * 576];
__device__ __align__(16) bf16 g_WlTh[64 * 576];
__device__ __align__(16) bf16 g_WlTl[64 * 576];
__device__ __align__(16) bf16 g_h1h[NND * NH];
__device__ __align__(16) bf16 g_h1l[NND * NH];
__device__ __align__(16) bf16 g_emoh[(size_t)NND * NDm];
__device__ __align__(16) bf16 g_emol[(size_t)NND * NDm];
__device__ __align__(16) bf16 g_emoTh[(size_t)NBc * NDm * NL];
__device__ __align__(16) bf16 g_emoTl[(size_t)NBc * NDm * NL];
__device__ __align__(16) bf16 g_Qh[(size_t)NND * NDm];
__device__ __align__(16) bf16 g_Ql[(size_t)NND * NDm];
__device__ __align__(16) bf16 g_Sh[NND * NL];
__device__ __align__(16) bf16 g_Sl[NND * NL];
__device__ __align__(16) bf16 g_atth[(size_t)NND * NDm];
__device__ __align__(16) bf16 g_attl[(size_t)NND * NDm];

__device__ __align__(16) float g_xw[(size_t)NND * NRel * NH];
__device__ __align__(16) float g_agg[NND * NH];
__device__ __align__(16) float g_y[NND * NH];
__device__ __align__(16) float g_nb[NND * NH];
__device__ __align__(16) float g_S[(size_t)NND * NL];
__device__ __align__(16) float g_hid[NND * NH];
// CSR
__device__ int g_cnt[NND];
__device__ int g_off[NND + 1];
__device__ int g_cur[NND];
__device__ int g_eidx[NE];

__device__ __forceinline__ void split_pair(float v, bf16& h, bf16& l) {
    h = __float2bfloat16(v);
    l = __float2bfloat16(v - __bfloat162float(h));
}

__device__ __forceinline__ u32 smem_u32(const void* p) {
    u32 a;
    asm("{ .reg .u64 t; cvta.to.shared.u64 t, %1; cvt.u32.u64 %0, t; }"
        : "=r"(a) : "l"(p));
    return a;
}

__device__ __forceinline__ void mma16816(float* d, const u32* a, const u32* b) {
    asm volatile(
        "mma.sync.aligned.m16n8k16.row.col.f32.bf16.bf16.f32 "
        "{%0,%1,%2,%3}, {%4,%5,%6,%7}, {%8,%9}, {%0,%1,%2,%3};"
        : "+f"(d[0]), "+f"(d[1]), "+f"(d[2]), "+f"(d[3])
        : "r"(a[0]), "r"(a[1]), "r"(a[2]), "r"(a[3]), "r"(b[0]), "r"(b[1]));
}

#define LDSM4(r, addr) \
    asm volatile("ldmatrix.sync.aligned.m8n8.x4.shared.b16 {%0,%1,%2,%3}, [%4];" \
        : "=r"((r)[0]), "=r"((r)[1]), "=r"((r)[2]), "=r"((r)[3]) : "r"(addr))

#define CPA(d, s) \
    asm volatile("cp.async.cg.shared.global [%0], [%1], 16;" :: "r"(d), "l"(s) : "memory")
#define CPC() asm volatile("cp.async.commit_group;" ::: "memory")
#define CPW1() asm volatile("cp.async.wait_group 1;" ::: "memory")

// ============================================================
// Pipelined warp-MMA 3xBF16 GEMM: C[M,N] = A @ B^T
// A:[m][k] hi/lo, B:[n][k] hi/lo. Block tile BM x NT, 2-stage cp.async.
// THREADS/32 warps: WN = NT/64 warps over N, rest over M.
// ============================================================
template <int BM, int NT, int THREADS,
          bool ADD_D, bool BIAS, bool RELU, bool TANH_UM, bool OUT_PAIR>
__global__ void __launch_bounds__(THREADS)
mmt(const bf16* __restrict__ Ah, const bf16* __restrict__ Al, int lda, long long sA,
    const bf16* __restrict__ Bh, const bf16* __restrict__ Bl, int ldb, long long sB,
    float* __restrict__ C, bf16* __restrict__ Ch, bf16* __restrict__ Cl,
    int ldc, long long sC,
    const float* __restrict__ D, int ldd,
    const float* __restrict__ bias, const float* __restrict__ um,
    int K)
{
    constexpr int WARPS = THREADS / 32;
    constexpr int WN = NT / 64;           // warps over N
    constexpr int WMC = WARPS / WN;       // warps over M
    constexpr int WM = BM / WMC;          // rows per warp
    constexpr int MI = WM / 16;           // m16 tiles per warp
    constexpr int STAGE_ROWS = 2 * (BM + NT);
    constexpr int STAGE_B = STAGE_ROWS * ROW;
    constexpr int CHUNKS = STAGE_ROWS * 8 / THREADS;

    extern __shared__ char smem[];
    float* ums = (float*)smem;
    const u32 sb0 = smem_u32(smem) + 512;

    const int tid = threadIdx.x;
    const int wid = tid >> 5, lane = tid & 31;
    const int warpM = wid % WMC, warpN = wid / WMC;
    const int bz = blockIdx.z;
    const int m0 = blockIdx.y * BM;
    const int n0 = blockIdx.x * NT;

    const char* pAh = (const char*)(Ah + sA * bz + (size_t)m0 * lda);
    const char* pAl = (const char*)(Al + sA * bz + (size_t)m0 * lda);
    const char* pBh = (const char*)(Bh + sB * bz + (size_t)n0 * ldb);
    const char* pBl = (const char*)(Bl + sB * bz + (size_t)n0 * ldb);
    const size_t ldab = (size_t)lda * 2;
    const size_t ldbb = (size_t)ldb * 2;

    if (TANH_UM && tid < NT) ums[tid] = um[bz * NL + n0 + tid];

    float acc[MI][8][4];
#pragma unroll
    for (int i = 0; i < MI; i++)
#pragma unroll
        for (int j = 0; j < 8; j++)
#pragma unroll
            for (int q = 0; q < 4; q++) acc[i][j][q] = 0.f;

    const int S = K / KC;

    // ---- loader ----
    auto load_stage = [&](int s) {
        const size_t kcb = (size_t)s * KC * 2;
        const u32 dst0 = sb0 + (u32)(s & 1) * STAGE_B;
#pragma unroll
        for (int f = 0; f < CHUNKS; f++) {
            int idx = tid + f * THREADS;
            int row = idx >> 3;
            int cb = (idx & 7) << 4;
            const char* src;
            if (row < BM)               src = pAh + (size_t)row * ldab + kcb + cb;
            else if (row < 2 * BM)      src = pAl + (size_t)(row - BM) * ldab + kcb + cb;
            else if (row < 2 * BM + NT) src = pBh + (size_t)(row - 2 * BM) * ldbb + kcb + cb;
            else                        src = pBl + (size_t)(row - 2 * BM - NT) * ldbb + kcb + cb;
            CPA(dst0 + (u32)row * ROW + (u32)cb, src);
        }
    };

    load_stage(0);
    CPC();

    for (int s = 0; s < S; s++) {
        if (s + 1 < S) load_stage(s + 1);
        CPC();
        CPW1();
        __syncthreads();

        const u32 base = sb0 + (u32)(s & 1) * STAGE_B;
        const u32 aOffH = base + (u32)(warpM * WM + (lane & 15)) * ROW + (u32)((lane >> 4) & 1) * 16;
        const u32 aOffL = aOffH + BM * ROW;
        const u32 bRow = (u32)((lane & 7) | ((lane & 16) >> 1));
        const u32 bOffH = base + 2 * BM * ROW + (u32)(warpN * 64) * ROW + bRow * ROW
                        + (u32)((lane >> 3) & 1) * 16;
        const u32 bOffL = bOffH + NT * ROW;

#pragma unroll
        for (int ks = 0; ks < KC / 16; ks++) {
            const u32 kb = ks * 32;
            u32 bh[4][4], bl[4][4];
#pragma unroll
            for (int nt = 0; nt < 4; nt++) {
                LDSM4(bh[nt], bOffH + nt * 16 * ROW + kb);
                LDSM4(bl[nt], bOffL + nt * 16 * ROW + kb);
            }
#pragma unroll
            for (int mi = 0; mi < MI; mi++) {
                u32 ah[4], al[4];
                LDSM4(ah, aOffH + mi * 16 * ROW + kb);
                LDSM4(al, aOffL + mi * 16 * ROW + kb);
#pragma unroll
                for (int nt = 0; nt < 4; nt++)
#pragma unroll
                    for (int half = 0; half < 2; half++) {
                        float* a4 = acc[mi][nt * 2 + half];
                        mma16816(a4, ah, &bh[nt][half * 2]);
                        mma16816(a4, ah, &bl[nt][half * 2]);
                        mma16816(a4, al, &bh[nt][half * 2]);
                    }
            }
        }
        __syncthreads();
    }

    // ---- epilogue ----
#pragma unroll
    for (int mi = 0; mi < MI; mi++) {
        const int rm = m0 + warpM * WM + mi * 16 + (lane >> 2);
#pragma unroll
        for (int ni = 0; ni < 8; ni++) {
            const int cl = warpN * 64 + ni * 8 + (lane & 3) * 2;
            const int n = n0 + cl;
#pragma unroll
            for (int half = 0; half < 2; half++) {
                const int m = rm + half * 8;
                float v0 = acc[mi][ni][half * 2];
                float v1 = acc[mi][ni][half * 2 + 1];
                if (BIAS) { v0 += bias[n]; v1 += bias[n + 1]; }
                if (ADD_D) {
                    v0 += D[(size_t)m * ldd + n];
                    v1 += D[(size_t)m * ldd + n + 1];
                }
                if (TANH_UM) {
                    float u0 = ums[cl], u1 = ums[cl + 1];
                    v0 = tanhf(v0 * u0 * u0);
                    v1 = tanhf(v1 * u1 * u1);
                }
                if (RELU) { v0 = fmaxf(v0, 0.f); v1 = fmaxf(v1, 0.f); }
                const size_t base = (size_t)sC * bz + (size_t)m * ldc + n;
                if (OUT_PAIR) {
                    bf16 h0, l0, h1, l1;
                    split_pair(v0, h0, l0);
                    split_pair(v1, h1, l1);
                    *(__nv_bfloat162*)&Ch[base] = __nv_bfloat162(h0, h1);
                    *(__nv_bfloat162*)&Cl[base] = __nv_bfloat162(l0, l1);
                } else {
                    float2 f2; f2.x = v0; f2.y = v1;
                    *(float2*)&C[base] = f2;
                }
            }
        }
    }
}

// ============================================================
// conversion / transpose kernels
// ============================================================
__global__ void cvt_pair_kernel(const float* __restrict__ src,
                                bf16* __restrict__ hi, bf16* __restrict__ lo, int n)
{
    int i = blockIdx.x * 256 + threadIdx.x;
    if (i < n) { bf16 h, l; split_pair(src[i], h, l); hi[i] = h; lo[i] = l; }
}

__global__ void tcvt_kernel(const float* __restrict__ src,
                            bf16* __restrict__ hi, bf16* __restrict__ lo, int R, int C)
{
    int i = blockIdx.x * 256 + threadIdx.x;
    if (i >= R * C) return;
    int rr = i / C, cc = i % C;
    bf16 h, l; split_pair(src[i], h, l);
    hi[(size_t)cc * R + rr] = h;
    lo[(size_t)cc * R + rr] = l;
}

__global__ void wt_kernel(const float* __restrict__ comp,
                          const float* __restrict__ basis,
                          bf16* __restrict__ Wh, bf16* __restrict__ Wl)
{
    int idx = blockIdx.x * 256 + threadIdx.x;   // 524288
    int h = idx & 63, rr = (idx >> 6) & 15, k = idx >> 10;
    float acc = 0.f;
#pragma unroll
    for (int b = 0; b < NBase; b++)
        acc = fmaf(comp[rr * NBase + b], basis[((size_t)b * NF + k) * NH + h], acc);
    bf16 hh, ll; split_pair(acc, hh, ll);
    size_t o = (size_t)(rr * 64 + h) * 512 + k;
    Wh[o] = hh; Wl[o] = ll;
}

__global__ void copy_x_kernel(const bf16* __restrict__ xh, const bf16* __restrict__ xl,
                              bf16* __restrict__ eh, bf16* __restrict__ el)
{
    int id = blockIdx.x * 256 + threadIdx.x;    // 8192*64
    int row = id >> 6, c = id & 63;
    *(uint4*)&eh[(size_t)row * NDm + c * 8] = *(const uint4*)&xh[(size_t)row * NF + c * 8];
    *(uint4*)&el[(size_t)row * NDm + c * 8] = *(const uint4*)&xl[(size_t)row * NF + c * 8];
}

__global__ void emoT_kernel(const bf16* __restrict__ eh, const bf16* __restrict__ el,
                            bf16* __restrict__ th, bf16* __restrict__ tl)
{
    __shared__ unsigned short sh[32][33], sl[32][33];
    const int b = blockIdx.z;
    const int d0 = blockIdx.x * 32, t0 = blockIdx.y * 32;
    const int tx = threadIdx.x, ty = threadIdx.y;
#pragma unroll
    for (int q = 0; q < 4; q++) {
        int row = ty * 4 + q;
        size_t src = (size_t)(b * NL + t0 + row) * NDm + d0 + tx;
        sh[row][tx] = ((const unsigned short*)eh)[src];
        sl[row][tx] = ((const unsigned short*)el)[src];
    }
    __syncthreads();
#pragma unroll
    for (int q = 0; q < 4; q++) {
        int row = ty * 4 + q;
        size_t dst = (size_t)b * NDm * NL + (size_t)(d0 + row) * NL + t0 + tx;
        ((unsigned short*)th)[dst] = sh[tx][row];
        ((unsigned short*)tl)[dst] = sl[tx][row];
    }
}

// ---- CSR build ----
__global__ void zero_cnt_kernel(int* cnt)
{
    int i = blockIdx.x * 256 + threadIdx.x;
    if (i < NND) cnt[i] = 0;
}
__global__ void hist_kernel(const int* __restrict__ ei, int* __restrict__ cnt)
{
    int i = blockIdx.x * 256 + threadIdx.x;
    if (i < NE) atomicAdd(&cnt[ei[NE + i]], 1);
}
__global__ void __launch_bounds__(1024)
scan_kernel(const int* __restrict__ cnt, int* __restrict__ off, int* __restrict__ cur)
{
    __shared__ int s[NND];
    int t = threadIdx.x;
    for (int i = t; i < NND; i += 1024) s[i] = cnt[i];
    __syncthreads();
    for (int d = 1; d < NND; d <<= 1) {
        int v[8];
#pragma unroll
        for (int k = 0; k < 8; k++) {
            int i = t + k * 1024;
            v[k] = (i >= d) ? s[i - d] : 0;
        }
        __syncthreads();
#pragma unroll
        for (int k = 0; k < 8; k++) s[t + k * 1024] += v[k];
        __syncthreads();
    }
    for (int i = t; i < NND; i += 1024) {
        off[i + 1] = s[i];
        cur[i] = (i == 0) ? 0 : s[i - 1];
    }
    if (t == 0) off[0] = 0;
}
__global__ void fill_kernel(const int* __restrict__ ei, const int* __restrict__ et,
                            int* __restrict__ cur, int* __restrict__ eidx)
{
    int i = blockIdx.x * 256 + threadIdx.x;
    if (i >= NE) return;
    int dst = ei[NE + i];
    int pos = atomicAdd(&cur[dst], 1);
    eidx[pos] = ei[i] * 16 + et[i];
}

// ---- CSR gathers ----
__global__ void __launch_bounds__(64)
rgcn_gather(const int* __restrict__ off, const int* __restrict__ eidx,
            const float* __restrict__ xw, float* __restrict__ agg)
{
    const int n = blockIdx.x, h = threadIdx.x;
    const int beg = off[n], end = off[n + 1];
    float acc = 0.f;
    int e = beg;
    for (; e + 4 <= end; e += 4) {
        int p0 = eidx[e], p1 = eidx[e + 1], p2 = eidx[e + 2], p3 = eidx[e + 3];
        acc += xw[(size_t)(p0 >> 4) * 1024 + (p0 & 15) * 64 + h]
             + xw[(size_t)(p1 >> 4) * 1024 + (p1 & 15) * 64 + h]
             + xw[(size_t)(p2 >> 4) * 1024 + (p2 & 15) * 64 + h]
             + xw[(size_t)(p3 >> 4) * 1024 + (p3 & 15) * 64 + h];
    }
    for (; e < end; e++) {
        int p = eidx[e];
        acc += xw[(size_t)(p >> 4) * 1024 + (p & 15) * 64 + h];
    }
    agg[n * NH + h] = acc / fmaxf((float)(end - beg), 1.f);
}
__global__ void __launch_bounds__(64)
gc_gather(const int* __restrict__ off, const int* __restrict__ eidx,
          const float* __restrict__ y, float* __restrict__ nb)
{
    const int n = blockIdx.x, h = threadIdx.x;
    const int beg = off[n], end = off[n + 1];
    float acc = 0.f;
    int e = beg;
    for (; e + 4 <= end; e += 4) {
        int p0 = eidx[e], p1 = eidx[e + 1], p2 = eidx[e + 2], p3 = eidx[e + 3];
        acc += y[(p0 >> 4) * NH + h] + y[(p1 >> 4) * NH + h]
             + y[(p2 >> 4) * NH + h] + y[(p3 >> 4) * NH + h];
    }
    for (; e < end; e++) acc += y[(eidx[e] >> 4) * NH + h];
    nb[n * NH + h] = acc;
}

// softmax over k per (b,q): softmax(S)*u, renorm; emit bf16 pairs
__global__ void softmax_kernel(const float* __restrict__ S, const float* __restrict__ um,
                               bf16* __restrict__ Sh, bf16* __restrict__ Sl)
{
    __shared__ float red[NL];
    const int row = blockIdx.x;
    const int b = row >> 7;
    const int k = threadIdx.x;

    float s = S[(size_t)row * NL + k];
    red[k] = s; __syncthreads();
#pragma unroll
    for (int o = 64; o > 0; o >>= 1) { if (k < o) red[k] = fmaxf(red[k], red[k + o]); __syncthreads(); }
    float mx = red[0]; __syncthreads();

    float e = expf(s - mx);
    red[k] = e; __syncthreads();
#pragma unroll
    for (int o = 64; o > 0; o >>= 1) { if (k < o) red[k] += red[k + o]; __syncthreads(); }
    float sum1 = red[0]; __syncthreads();

    float a = (e / sum1) * um[b * NL + k];
    red[k] = a; __syncthreads();
#pragma unroll
    for (int o = 64; o > 0; o >>= 1) { if (k < o) red[k] += red[k + o]; __syncthreads(); }
    float sum2 = red[0];

    bf16 h, l; split_pair(a / sum2, h, l);
    Sh[(size_t)row * NL + k] = h;
    Sl[(size_t)row * NL + k] = l;
}

// head: logits = hid @ Ws + bs ; log_softmax
__global__ void head_kernel(const float* __restrict__ hid, const float* __restrict__ Ws,
                            const float* __restrict__ bsv, float* __restrict__ out)
{
    int n = blockIdx.x * blockDim.x + threadIdx.x;
    if (n >= NND) return;
    float lg[NC];
#pragma unroll
    for (int c = 0; c < NC; c++) lg[c] = bsv[c];
    const float* h = hid + (size_t)n * NH;
#pragma unroll 8
    for (int k = 0; k < NH; k++) {
        float hv = h[k];
#pragma unroll
        for (int c = 0; c < NC; c++) lg[c] = fmaf(hv, Ws[k * NC + c], lg[c]);
    }
    float mx = lg[0];
#pragma unroll
    for (int c = 1; c < NC; c++) mx = fmaxf(mx, lg[c]);
    float ssum = 0.f;
#pragma unroll
    for (int c = 0; c < NC; c++) ssum += expf(lg[c] - mx);
    float lse = mx + logf(ssum);
#pragma unroll
    for (int c = 0; c < NC; c++) out[(size_t)n * NC + c] = lg[c] - lse;
}

// ============================================================
extern "C" void kernel_launch(void* const* d_in, const int* in_sizes, int n_in,
                              void* d_out, int out_size)
{
    const float* x      = (const float*)d_in[0];
    const int*   ei     = (const int*)d_in[1];
    const int*   et     = (const int*)d_in[3];
    const float* umask  = (const float*)d_in[5];
    const float* basis  = (const float*)d_in[8];
    const float* comp   = (const float*)d_in[9];
    const float* root   = (const float*)d_in[10];
    const float* bias1  = (const float*)d_in[11];
    const float* w_nbr  = (const float*)d_in[12];
    const float* w_root = (const float*)d_in[13];
    const float* bias2  = (const float*)d_in[14];
    const float* Wm     = (const float*)d_in[15];
    const float* bm     = (const float*)d_in[16];
    const float* Wl     = (const float*)d_in[17];
    const float* bl     = (const float*)d_in[18];
    const float* Ws     = (const float*)d_in[19];
    const float* bs     = (const float*)d_in[20];
    float* out = (float*)d_out;

#define SYM(T, v, s) T* v; cudaGetSymbolAddress((void**)&v, s)
    SYM(bf16, xh, g_xh); SYM(bf16, xl, g_xl);
    SYM(bf16, WtTh, g_WtTh); SYM(bf16, WtTl, g_WtTl);
    SYM(bf16, rootTh, g_rootTh); SYM(bf16, rootTl, g_rootTl);
    SYM(bf16, wnbrTh, g_wnbrTh); SYM(bf16, wnbrTl, g_wnbrTl);
    SYM(bf16, wrootTh, g_wrootTh); SYM(bf16, wrootTl, g_wrootTl);
    SYM(bf16, WmTh, g_WmTh); SYM(bf16, WmTl, g_WmTl);
    SYM(bf16, WlTh, g_WlTh); SYM(bf16, WlTl, g_WlTl);
    SYM(bf16, h1h, g_h1h); SYM(bf16, h1l, g_h1l);
    SYM(bf16, emoh, g_emoh); SYM(bf16, emol, g_emol);
    SYM(bf16, emoTh, g_emoTh); SYM(bf16, emoTl, g_emoTl);
    SYM(bf16, Qh, g_Qh); SYM(bf16, Ql, g_Ql);
    SYM(bf16, Sh, g_Sh); SYM(bf16, Sl, g_Sl);
    SYM(bf16, atth, g_atth); SYM(bf16, attl, g_attl);
    SYM(float, xw, g_xw); SYM(float, agg, g_agg); SYM(float, y, g_y);
    SYM(float, nb, g_nb); SYM(float, S, g_S); SYM(float, hid, g_hid);
    SYM(int, cnt, g_cnt); SYM(int, off, g_off); SYM(int, cur, g_cur);
    SYM(int, eidx, g_eidx);
#undef SYM

    // dynamic smem: 512 (ums) + 2 stages * 2*(BM+NT) rows * 144B
    const int SZ_128_128 = 512 + 2 * 2 * (128 + 128) * ROW;   // 147968
    const int SZ_128_64  = 512 + 2 * 2 * (128 + 64) * ROW;    // 111104
    const int SZ_64_64   = 512 + 2 * 2 * (64 + 64) * ROW;     // 74240

#define SETSM(KERN, SZ) cudaFuncSetAttribute((const void*)(KERN), \
    cudaFuncAttributeMaxDynamicSharedMemorySize, SZ)
    SETSM((mmt<128, 128, 256, false, false, false, false, false>), SZ_128_128);
    SETSM((mmt<64, 64, 128, true,  true,  false, false, true>),  SZ_64_64);
    SETSM((mmt<64, 64, 128, false, false, false, false, false>), SZ_64_64);
    SETSM((mmt<128, 64, 128, false, true,  false, false, true>),  SZ_128_64);
    SETSM((mmt<128, 128, 256, false, false, false, true,  false>), SZ_128_128);
    SETSM((mmt<128, 64, 128, false, false, false, false, true>),  SZ_128_64);
    SETSM((mmt<64, 64, 128, false, true,  true,  false, false>), SZ_64_64);
#undef SETSM

    // ---- operand prep (ordered so the xw GEMM is the 4th launch for ncu) ----
    cvt_pair_kernel<<<(NND * NF) / 256, 256>>>(x, xh, xl, NND * NF);
    wt_kernel<<<(NF * NRel * NH) / 256, 256>>>(comp, basis, WtTh, WtTl);
    tcvt_kernel<<<(512 * 64 + 255) / 256, 256>>>(root, rootTh, rootTl, 512, 64);

    // xw = x @ Wt  [8192,1024], K=512
    mmt<128, 128, 256, false, false, false, false, false>
        <<<dim3(8, 64, 1), 256, SZ_128_128>>>(
        xh, xl, 512, 0, WtTh, WtTl, 512, 0,
        xw, nullptr, nullptr, 1024, 0, nullptr, 0, nullptr, nullptr, 512);

    // ---- CSR build ----
    zero_cnt_kernel<<<NND / 256, 256>>>(cnt);
    hist_kernel<<<NE / 256, 256>>>(ei, cnt);
    scan_kernel<<<1, 1024>>>(cnt, off, cur);
    fill_kernel<<<NE / 256, 256>>>(ei, et, cur, eidx);

    tcvt_kernel<<<(64 * 64 + 255) / 256, 256>>>(w_nbr, wnbrTh, wnbrTl, 64, 64);
    tcvt_kernel<<<(64 * 64 + 255) / 256, 256>>>(w_root, wrootTh, wrootTl, 64, 64);
    tcvt_kernel<<<(576 * 576 + 255) / 256, 256>>>(Wm, WmTh, WmTl, 576, 576);
    tcvt_kernel<<<(576 * 64 + 255) / 256, 256>>>(Wl, WlTh, WlTl, 576, 64);
    copy_x_kernel<<<(NND * 64) / 256, 256>>>(xh, xl, emoh, emol);

    rgcn_gather<<<NND, 64>>>(off, eidx, xw, agg);

    // h1 = agg + x@root + bias1 -> pairs  (K=512)
    mmt<64, 64, 128, true, true, false, false, true>
        <<<dim3(1, 128, 1), 128, SZ_64_64>>>(
        xh, xl, 512, 0, rootTh, rootTl, 512, 0,
        nullptr, h1h, h1l, 64, 0, agg, 64, bias1, nullptr, 512);

    // y = h1 @ w_nbr  (fp32, K=64)
    mmt<64, 64, 128, false, false, false, false, false>
        <<<dim3(1, 128, 1), 128, SZ_64_64>>>(
        h1h, h1l, 64, 0, wnbrTh, wnbrTl, 64, 0,
        y, nullptr, nullptr, 64, 0, nullptr, 0, nullptr, nullptr, 64);

    gc_gather<<<NND, 64>>>(off, eidx, y, nb);

    // h2 = nb + h1@w_root + bias2 -> emo pairs cols [512,576)  (K=64)
    mmt<64, 64, 128, true, true, false, false, true>
        <<<dim3(1, 128, 1), 128, SZ_64_64>>>(
        h1h, h1l, 64, 0, wrootTh, wrootTl, 64, 0,
        nullptr, emoh + NF, emol + NF, NDm, 0, nb, 64, bias2, nullptr, 64);

    emoT_kernel<<<dim3(NDm / 32, NL / 32, NBc), dim3(32, 8)>>>(emoh, emol, emoTh, emoTl);

    // Q = emo @ Wm + bm -> pairs  (K=576)
    mmt<128, 64, 128, false, true, false, false, true>
        <<<dim3(9, 64, 1), 128, SZ_128_64>>>(
        emoh, emol, NDm, 0, WmTh, WmTl, NDm, 0,
        nullptr, Qh, Ql, NDm, 0, nullptr, 0, bm, nullptr, NDm);

    // scores: per conv, S = tanh((Q . M) * u^2)  (fp32, K=576)
    mmt<128, 128, 256, false, false, false, true, false>
        <<<dim3(1, 1, NBc), 256, SZ_128_128>>>(
        Qh, Ql, NDm, (long long)NL * NDm, emoh, emol, NDm, (long long)NL * NDm,
        S, nullptr, nullptr, NL, (long long)NL * NL,
        nullptr, 0, nullptr, umask, NDm);

    softmax_kernel<<<NND, NL>>>(S, umask, Sh, Sl);

    // att = alpha @ emo -> pairs  (B = emoT, K=128)
    mmt<128, 64, 128, false, false, false, false, true>
        <<<dim3(9, 1, NBc), 128, SZ_128_64>>>(
        Sh, Sl, NL, (long long)NL * NL, emoTh, emoTl, NL, (long long)NDm * NL,
        nullptr, atth, attl, NDm, (long long)NL * NDm,
        nullptr, 0, nullptr, nullptr, NL);

    // hidden = relu(att @ Wl + bl)  (fp32, K=576)
    mmt<64, 64, 128, false, true, true, false, false>
        <<<dim3(1, 128, 1), 128, SZ_64_64>>>(
        atth, attl, NDm, 0, WlTh, WlTl, NDm, 0,
        hid, nullptr, nullptr, 64, 0, nullptr, 0, bl, nullptr, NDm);

    head_kernel<<<NND / 128, 128>>>(hid, Ws, bs, out);

    (void)in_sizes; (void)n_in; (void)out_size;
}

// round 6
// speedup vs baseline: 2.4097x; 1.1510x over previous
#include <cuda_runtime.h>
#include <cuda_bf16.h>
#include <math.h>
#include <cstdint>

// ---- problem constants ----
#define NND 8192
#define NF  512
#define NH  64
#define NRel 16
#define NBase 30
#define NE  524288
#define NBc 64
#define NL  128
#define NDm 576
#define NC  7
#define KC  64          // K chunk (bf16) per pipeline stage; 128B rows

typedef __nv_bfloat16 bf16;
typedef unsigned int u32;

// ---- static device scratch ----
__device__ __align__(16) bf16 g_xh[(size_t)NND * NF];
__device__ __align__(16) bf16 g_xl[(size_t)NND * NF];
__device__ __align__(16) bf16 g_WtTh[1024 * 512];
__device__ __align__(16) bf16 g_WtTl[1024 * 512];
__device__ __align__(16) bf16 g_rootTh[64 * 512];
__device__ __align__(16) bf16 g_rootTl[64 * 512];
__device__ __align__(16) bf16 g_wnbrTh[64 * 64];
__device__ __align__(16) bf16 g_wnbrTl[64 * 64];
__device__ __align__(16) bf16 g_wrootTh[64 * 64];
__device__ __align__(16) bf16 g_wrootTl[64 * 64];
__device__ __align__(16) bf16 g_WmTh[576 * 576];
__device__ __align__(16) bf16 g_WmTl[576 * 576];
__device__ __align__(16) bf16 g_WlTh[64 * 576];
__device__ __align__(16) bf16 g_WlTl[64 * 576];
__device__ __align__(16) bf16 g_h1h[NND * NH];
__device__ __align__(16) bf16 g_h1l[NND * NH];
__device__ __align__(16) bf16 g_emoh[(size_t)NND * NDm];
__device__ __align__(16) bf16 g_emol[(size_t)NND * NDm];
__device__ __align__(16) bf16 g_emoTh[(size_t)NBc * NDm * NL];
__device__ __align__(16) bf16 g_emoTl[(size_t)NBc * NDm * NL];
__device__ __align__(16) bf16 g_Qh[(size_t)NND * NDm];
__device__ __align__(16) bf16 g_Ql[(size_t)NND * NDm];
__device__ __align__(16) bf16 g_Sh[NND * NL];
__device__ __align__(16) bf16 g_Sl[NND * NL];
__device__ __align__(16) bf16 g_atth[(size_t)NND * NDm];
__device__ __align__(16) bf16 g_attl[(size_t)NND * NDm];

__device__ __align__(16) float g_xw[(size_t)NND * NRel * NH];
__device__ __align__(16) float g_agg[NND * NH];
__device__ __align__(16) float g_y[NND * NH];
__device__ __align__(16) float g_nb[NND * NH];
__device__ __align__(16) float g_S[(size_t)NND * NL];
__device__ __align__(16) float g_hid[NND * NH];
// CSR
__device__ int g_cnt[NND];
__device__ int g_off[NND + 1];
__device__ int g_cur[NND];
__device__ int g_eidx[NE];

__device__ __forceinline__ void split_pair(float v, bf16& h, bf16& l) {
    h = __float2bfloat16(v);
    l = __float2bfloat16(v - __bfloat162float(h));
}

__device__ __forceinline__ u32 smem_u32(const void* p) {
    u32 a;
    asm("{ .reg .u64 t; cvta.to.shared.u64 t, %1; cvt.u32.u64 %0, t; }"
        : "=r"(a) : "l"(p));
    return a;
}

__device__ __forceinline__ void mma16816(float* d, const u32* a, const u32* b) {
    asm volatile(
        "mma.sync.aligned.m16n8k16.row.col.f32.bf16.bf16.f32 "
        "{%0,%1,%2,%3}, {%4,%5,%6,%7}, {%8,%9}, {%0,%1,%2,%3};"
        : "+f"(d[0]), "+f"(d[1]), "+f"(d[2]), "+f"(d[3])
        : "r"(a[0]), "r"(a[1]), "r"(a[2]), "r"(a[3]), "r"(b[0]), "r"(b[1]));
}

#define LDSM4(r, addr) \
    asm volatile("ldmatrix.sync.aligned.m8n8.x4.shared.b16 {%0,%1,%2,%3}, [%4];" \
        : "=r"((r)[0]), "=r"((r)[1]), "=r"((r)[2]), "=r"((r)[3]) : "r"(addr))

#define CPA(d, s) \
    asm volatile("cp.async.cg.shared.global [%0], [%1], 16;" :: "r"(d), "l"(s) : "memory")
#define CPC() asm volatile("cp.async.commit_group;" ::: "memory")
#define CPW1() asm volatile("cp.async.wait_group 1;" ::: "memory")

// ============================================================
// Pipelined warp-MMA 3xBF16 GEMM: C[M,N] = A @ B^T
// A:[m][k] hi/lo, B:[n][k] hi/lo. SW128-swizzled SMEM, 2-stage cp.async.
// Warp tile 16 x 64 (MI=1). WN = NT/64 warps over N, rest over M.
// ============================================================
template <int BM, int NT, int THREADS,
          bool ADD_D, bool BIAS, bool RELU, bool TANH_UM, bool OUT_PAIR>
__global__ void __launch_bounds__(THREADS, (THREADS == 128) ? 3 : 2)
mmt(const bf16* __restrict__ Ah, const bf16* __restrict__ Al, int lda, long long sA,
    const bf16* __restrict__ Bh, const bf16* __restrict__ Bl, int ldb, long long sB,
    float* __restrict__ C, bf16* __restrict__ Ch, bf16* __restrict__ Cl,
    int ldc, long long sC,
    const float* __restrict__ D, int ldd,
    const float* __restrict__ bias, const float* __restrict__ um,
    int K)
{
    constexpr int WARPS = THREADS / 32;
    constexpr int WN = NT / 64;
    constexpr int WMC = WARPS / WN;
    static_assert(BM / WMC == 16, "warp M tile must be 16");
    constexpr int STAGE_ROWS = 2 * (BM + NT);
    constexpr int STAGE_B = STAGE_ROWS * 128;
    constexpr int CHUNKS = STAGE_ROWS * 8 / THREADS;

    extern __shared__ char smem[];
    float* ums = (float*)smem;
    const u32 sb0 = smem_u32(smem) + 512;

    const int tid = threadIdx.x;
    const int wid = tid >> 5, lane = tid & 31;
    const int warpM = wid % WMC, warpN = wid / WMC;
    const int bz = blockIdx.z;
    const int m0 = blockIdx.y * BM;
    const int n0 = blockIdx.x * NT;

    const char* pAh = (const char*)(Ah + sA * bz + (size_t)m0 * lda);
    const char* pAl = (const char*)(Al + sA * bz + (size_t)m0 * lda);
    const char* pBh = (const char*)(Bh + sB * bz + (size_t)n0 * ldb);
    const char* pBl = (const char*)(Bl + sB * bz + (size_t)n0 * ldb);
    const size_t ldab = (size_t)lda * 2;
    const size_t ldbb = (size_t)ldb * 2;

    if (TANH_UM && tid < NT) ums[tid] = um[bz * NL + n0 + tid];

    float acc[8][4];
#pragma unroll
    for (int j = 0; j < 8; j++)
#pragma unroll
        for (int q = 0; q < 4; q++) acc[j][q] = 0.f;

    const int S = K / KC;

    auto load_stage = [&](int s) {
        const size_t kcb = (size_t)s * KC * 2;
        const u32 dst0 = sb0 + (u32)(s & 1) * STAGE_B;
#pragma unroll
        for (int f = 0; f < CHUNKS; f++) {
            int idx = tid + f * THREADS;
            int row = idx >> 3;
            u32 cb = (u32)(idx & 7) << 4;
            u32 sw = cb ^ (((u32)(row & 7)) << 4);
            const char* src;
            if (row < BM)               src = pAh + (size_t)row * ldab + kcb + cb;
            else if (row < 2 * BM)      src = pAl + (size_t)(row - BM) * ldab + kcb + cb;
            else if (row < 2 * BM + NT) src = pBh + (size_t)(row - 2 * BM) * ldbb + kcb + cb;
            else                        src = pBl + (size_t)(row - 2 * BM - NT) * ldbb + kcb + cb;
            CPA(dst0 + (u32)row * 128 + sw, src);
        }
    };

    load_stage(0);
    CPC();

    // per-lane fragment addressing (SW128)
    const u32 xorv = ((u32)(lane & 7)) << 4;
    const u32 aRow = (u32)(warpM * 16 + (lane & 15));
    const u32 aCol0 = ((u32)(lane >> 4) & 1) * 16;
    const u32 bRow = (u32)(warpN * 64 + ((lane & 7) | ((lane & 16) >> 1)));
    const u32 bCol0 = ((u32)(lane >> 3) & 1) * 16;

    for (int s = 0; s < S; s++) {
        if (s + 1 < S) load_stage(s + 1);
        CPC();
        CPW1();
        __syncthreads();

        const u32 base = sb0 + (u32)(s & 1) * STAGE_B;
        const u32 aH = base + aRow * 128;
        const u32 aL = aH + (u32)BM * 128;
        const u32 bH = base + (u32)(2 * BM) * 128 + bRow * 128;
        const u32 bL = bH + (u32)NT * 128;

#pragma unroll
        for (int ks = 0; ks < KC / 16; ks++) {
            const u32 kb = (u32)ks * 32;
            const u32 acol = (aCol0 + kb) ^ xorv;
            const u32 bcol = (bCol0 + kb) ^ xorv;
            u32 bh[4][4], bl[4][4];
#pragma unroll
            for (int nt = 0; nt < 4; nt++) {
                LDSM4(bh[nt], bH + (u32)nt * (16 * 128) + bcol);
                LDSM4(bl[nt], bL + (u32)nt * (16 * 128) + bcol);
            }
            u32 ah[4], al[4];
            LDSM4(ah, aH + acol);
            LDSM4(al, aL + acol);
#pragma unroll
            for (int nt = 0; nt < 4; nt++)
#pragma unroll
                for (int half = 0; half < 2; half++) {
                    float* a4 = acc[nt * 2 + half];
                    mma16816(a4, ah, &bh[nt][half * 2]);
                    mma16816(a4, ah, &bl[nt][half * 2]);
                    mma16816(a4, al, &bh[nt][half * 2]);
                }
        }
        __syncthreads();
    }

    // ---- epilogue ----
    const int rm = m0 + warpM * 16 + (lane >> 2);
#pragma unroll
    for (int ni = 0; ni < 8; ni++) {
        const int cl = warpN * 64 + ni * 8 + (lane & 3) * 2;
        const int n = n0 + cl;
#pragma unroll
        for (int half = 0; half < 2; half++) {
            const int m = rm + half * 8;
            float v0 = acc[ni][half * 2];
            float v1 = acc[ni][half * 2 + 1];
            if (BIAS) { v0 += bias[n]; v1 += bias[n + 1]; }
            if (ADD_D) {
                v0 += D[(size_t)m * ldd + n];
                v1 += D[(size_t)m * ldd + n + 1];
            }
            if (TANH_UM) {
                float u0 = ums[cl], u1 = ums[cl + 1];
                v0 = tanhf(v0 * u0 * u0);
                v1 = tanhf(v1 * u1 * u1);
            }
            if (RELU) { v0 = fmaxf(v0, 0.f); v1 = fmaxf(v1, 0.f); }
            const size_t base = (size_t)sC * bz + (size_t)m * ldc + n;
            if (OUT_PAIR) {
                bf16 h0, l0, h1, l1;
                split_pair(v0, h0, l0);
                split_pair(v1, h1, l1);
                *(__nv_bfloat162*)&Ch[base] = __nv_bfloat162(h0, h1);
                *(__nv_bfloat162*)&Cl[base] = __nv_bfloat162(l0, l1);
            } else {
                float2 f2; f2.x = v0; f2.y = v1;
                *(float2*)&C[base] = f2;
            }
        }
    }
}

// ============================================================
// conversion / transpose kernels
// ============================================================
__global__ void cvt_pair_kernel(const float* __restrict__ src,
                                bf16* __restrict__ hi, bf16* __restrict__ lo, int n)
{
    int i = blockIdx.x * 256 + threadIdx.x;
    if (i < n) { bf16 h, l; split_pair(src[i], h, l); hi[i] = h; lo[i] = l; }
}

__global__ void tcvt_kernel(const float* __restrict__ src,
                            bf16* __restrict__ hi, bf16* __restrict__ lo, int R, int C)
{
    int i = blockIdx.x * 256 + threadIdx.x;
    if (i >= R * C) return;
    int rr = i / C, cc = i % C;
    bf16 h, l; split_pair(src[i], h, l);
    hi[(size_t)cc * R + rr] = h;
    lo[(size_t)cc * R + rr] = l;
}

__global__ void wt_kernel(const float* __restrict__ comp,
                          const float* __restrict__ basis,
                          bf16* __restrict__ Wh, bf16* __restrict__ Wl)
{
    int idx = blockIdx.x * 256 + threadIdx.x;   // 524288
    int h = idx & 63, rr = (idx >> 6) & 15, k = idx >> 10;
    float acc = 0.f;
#pragma unroll
    for (int b = 0; b < NBase; b++)
        acc = fmaf(comp[rr * NBase + b], basis[((size_t)b * NF + k) * NH + h], acc);
    bf16 hh, ll; split_pair(acc, hh, ll);
    size_t o = (size_t)(rr * 64 + h) * 512 + k;
    Wh[o] = hh; Wl[o] = ll;
}

__global__ void copy_x_kernel(const bf16* __restrict__ xh, const bf16* __restrict__ xl,
                              bf16* __restrict__ eh, bf16* __restrict__ el)
{
    int id = blockIdx.x * 256 + threadIdx.x;    // 8192*64
    int row = id >> 6, c = id & 63;
    *(uint4*)&eh[(size_t)row * NDm + c * 8] = *(const uint4*)&xh[(size_t)row * NF + c * 8];
    *(uint4*)&el[(size_t)row * NDm + c * 8] = *(const uint4*)&xl[(size_t)row * NF + c * 8];
}

__global__ void emoT_kernel(const bf16* __restrict__ eh, const bf16* __restrict__ el,
                            bf16* __restrict__ th, bf16* __restrict__ tl)
{
    __shared__ unsigned short sh[32][33], sl[32][33];
    const int b = blockIdx.z;
    const int d0 = blockIdx.x * 32, t0 = blockIdx.y * 32;
    const int tx = threadIdx.x, ty = threadIdx.y;
#pragma unroll
    for (int q = 0; q < 4; q++) {
        int row = ty * 4 + q;
        size_t src = (size_t)(b * NL + t0 + row) * NDm + d0 + tx;
        sh[row][tx] = ((const unsigned short*)eh)[src];
        sl[row][tx] = ((const unsigned short*)el)[src];
    }
    __syncthreads();
#pragma unroll
    for (int q = 0; q < 4; q++) {
        int row = ty * 4 + q;
        size_t dst = (size_t)b * NDm * NL + (size_t)(d0 + row) * NL + t0 + tx;
        ((unsigned short*)th)[dst] = sh[tx][row];
        ((unsigned short*)tl)[dst] = sl[tx][row];
    }
}

// ---- CSR build ----
__global__ void zero_cnt_kernel(int* cnt)
{
    int i = blockIdx.x * 256 + threadIdx.x;
    if (i < NND) cnt[i] = 0;
}
__global__ void hist_kernel(const int* __restrict__ ei, int* __restrict__ cnt)
{
    int i = blockIdx.x * 256 + threadIdx.x;
    if (i < NE) atomicAdd(&cnt[ei[NE + i]], 1);
}
__global__ void __launch_bounds__(1024)
scan_kernel(const int* __restrict__ cnt, int* __restrict__ off, int* __restrict__ cur)
{
    __shared__ int s[NND];
    int t = threadIdx.x;
    for (int i = t; i < NND; i += 1024) s[i] = cnt[i];
    __syncthreads();
    for (int d = 1; d < NND; d <<= 1) {
        int v[8];
#pragma unroll
        for (int k = 0; k < 8; k++) {
            int i = t + k * 1024;
            v[k] = (i >= d) ? s[i - d] : 0;
        }
        __syncthreads();
#pragma unroll
        for (int k = 0; k < 8; k++) s[t + k * 1024] += v[k];
        __syncthreads();
    }
    for (int i = t; i < NND; i += 1024) {
        off[i + 1] = s[i];
        cur[i] = (i == 0) ? 0 : s[i - 1];
    }
    if (t == 0) off[0] = 0;
}
__global__ void fill_kernel(const int* __restrict__ ei, const int* __restrict__ et,
                            int* __restrict__ cur, int* __restrict__ eidx)
{
    int i = blockIdx.x * 256 + threadIdx.x;
    if (i >= NE) return;
    int dst = ei[NE + i];
    int pos = atomicAdd(&cur[dst], 1);
    eidx[pos] = ei[i] * 16 + et[i];
}

// ---- CSR gathers ----
__global__ void __launch_bounds__(64)
rgcn_gather(const int* __restrict__ off, const int* __restrict__ eidx,
            const float* __restrict__ xw, float* __restrict__ agg)
{
    const int n = blockIdx.x, h = threadIdx.x;
    const int beg = off[n], end = off[n + 1];
    float acc = 0.f;
    int e = beg;
    for (; e + 4 <= end; e += 4) {
        int p0 = eidx[e], p1 = eidx[e + 1], p2 = eidx[e + 2], p3 = eidx[e + 3];
        acc += xw[(size_t)(p0 >> 4) * 1024 + (p0 & 15) * 64 + h]
             + xw[(size_t)(p1 >> 4) * 1024 + (p1 & 15) * 64 + h]
             + xw[(size_t)(p2 >> 4) * 1024 + (p2 & 15) * 64 + h]
             + xw[(size_t)(p3 >> 4) * 1024 + (p3 & 15) * 64 + h];
    }
    for (; e < end; e++) {
        int p = eidx[e];
        acc += xw[(size_t)(p >> 4) * 1024 + (p & 15) * 64 + h];
    }
    agg[n * NH + h] = acc / fmaxf((float)(end - beg), 1.f);
}
__global__ void __launch_bounds__(64)
gc_gather(const int* __restrict__ off, const int* __restrict__ eidx,
          const float* __restrict__ y, float* __restrict__ nb)
{
    const int n = blockIdx.x, h = threadIdx.x;
    const int beg = off[n], end = off[n + 1];
    float acc = 0.f;
    int e = beg;
    for (; e + 4 <= end; e += 4) {
        int p0 = eidx[e], p1 = eidx[e + 1], p2 = eidx[e + 2], p3 = eidx[e + 3];
        acc += y[(p0 >> 4) * NH + h] + y[(p1 >> 4) * NH + h]
             + y[(p2 >> 4) * NH + h] + y[(p3 >> 4) * NH + h];
    }
    for (; e < end; e++) acc += y[(eidx[e] >> 4) * NH + h];
    nb[n * NH + h] = acc;
}

// softmax over k per (b,q): softmax(S)*u, renorm; emit bf16 pairs
__global__ void softmax_kernel(const float* __restrict__ S, const float* __restrict__ um,
                               bf16* __restrict__ Sh, bf16* __restrict__ Sl)
{
    __shared__ float red[NL];
    const int row = blockIdx.x;
    const int b = row >> 7;
    const int k = threadIdx.x;

    float s = S[(size_t)row * NL + k];
    red[k] = s; __syncthreads();
#pragma unroll
    for (int o = 64; o > 0; o >>= 1) { if (k < o) red[k] = fmaxf(red[k], red[k + o]); __syncthreads(); }
    float mx = red[0]; __syncthreads();

    float e = expf(s - mx);
    red[k] = e; __syncthreads();
#pragma unroll
    for (int o = 64; o > 0; o >>= 1) { if (k < o) red[k] += red[k + o]; __syncthreads(); }
    float sum1 = red[0]; __syncthreads();

    float a = (e / sum1) * um[b * NL + k];
    red[k] = a; __syncthreads();
#pragma unroll
    for (int o = 64; o > 0; o >>= 1) { if (k < o) red[k] += red[k + o]; __syncthreads(); }
    float sum2 = red[0];

    bf16 h, l; split_pair(a / sum2, h, l);
    Sh[(size_t)row * NL + k] = h;
    Sl[(size_t)row * NL + k] = l;
}

// head: logits = hid @ Ws + bs ; log_softmax
__global__ void head_kernel(const float* __restrict__ hid, const float* __restrict__ Ws,
                            const float* __restrict__ bsv, float* __restrict__ out)
{
    int n = blockIdx.x * blockDim.x + threadIdx.x;
    if (n >= NND) return;
    float lg[NC];
#pragma unroll
    for (int c = 0; c < NC; c++) lg[c] = bsv[c];
    const float* h = hid + (size_t)n * NH;
#pragma unroll 8
    for (int k = 0; k < NH; k++) {
        float hv = h[k];
#pragma unroll
        for (int c = 0; c < NC; c++) lg[c] = fmaf(hv, Ws[k * NC + c], lg[c]);
    }
    float mx = lg[0];
#pragma unroll
    for (int c = 1; c < NC; c++) mx = fmaxf(mx, lg[c]);
    float ssum = 0.f;
#pragma unroll
    for (int c = 0; c < NC; c++) ssum += expf(lg[c] - mx);
    float lse = mx + logf(ssum);
#pragma unroll
    for (int c = 0; c < NC; c++) out[(size_t)n * NC + c] = lg[c] - lse;
}

// ============================================================
extern "C" void kernel_launch(void* const* d_in, const int* in_sizes, int n_in,
                              void* d_out, int out_size)
{
    const float* x      = (const float*)d_in[0];
    const int*   ei     = (const int*)d_in[1];
    const int*   et     = (const int*)d_in[3];
    const float* umask  = (const float*)d_in[5];
    const float* basis  = (const float*)d_in[8];
    const float* comp   = (const float*)d_in[9];
    const float* root   = (const float*)d_in[10];
    const float* bias1  = (const float*)d_in[11];
    const float* w_nbr  = (const float*)d_in[12];
    const float* w_root = (const float*)d_in[13];
    const float* bias2  = (const float*)d_in[14];
    const float* Wm     = (const float*)d_in[15];
    const float* bm     = (const float*)d_in[16];
    const float* Wl     = (const float*)d_in[17];
    const float* bl     = (const float*)d_in[18];
    const float* Ws     = (const float*)d_in[19];
    const float* bs     = (const float*)d_in[20];
    float* out = (float*)d_out;

#define SYM(T, v, s) T* v; cudaGetSymbolAddress((void**)&v, s)
    SYM(bf16, xh, g_xh); SYM(bf16, xl, g_xl);
    SYM(bf16, WtTh, g_WtTh); SYM(bf16, WtTl, g_WtTl);
    SYM(bf16, rootTh, g_rootTh); SYM(bf16, rootTl, g_rootTl);
    SYM(bf16, wnbrTh, g_wnbrTh); SYM(bf16, wnbrTl, g_wnbrTl);
    SYM(bf16, wrootTh, g_wrootTh); SYM(bf16, wrootTl, g_wrootTl);
    SYM(bf16, WmTh, g_WmTh); SYM(bf16, WmTl, g_WmTl);
    SYM(bf16, WlTh, g_WlTh); SYM(bf16, WlTl, g_WlTl);
    SYM(bf16, h1h, g_h1h); SYM(bf16, h1l, g_h1l);
    SYM(bf16, emoh, g_emoh); SYM(bf16, emol, g_emol);
    SYM(bf16, emoTh, g_emoTh); SYM(bf16, emoTl, g_emoTl);
    SYM(bf16, Qh, g_Qh); SYM(bf16, Ql, g_Ql);
    SYM(bf16, Sh, g_Sh); SYM(bf16, Sl, g_Sl);
    SYM(bf16, atth, g_atth); SYM(bf16, attl, g_attl);
    SYM(float, xw, g_xw); SYM(float, agg, g_agg); SYM(float, y, g_y);
    SYM(float, nb, g_nb); SYM(float, S, g_S); SYM(float, hid, g_hid);
    SYM(int, cnt, g_cnt); SYM(int, off, g_off); SYM(int, cur, g_cur);
    SYM(int, eidx, g_eidx);
#undef SYM

    // dynamic smem: 512 + 2 stages * 2*(BM+NT) rows * 128B
    const int SZ_128_64 = 512 + 2 * 2 * (128 + 64) * 128;   // 98816
    const int SZ_64_128 = 512 + 2 * 2 * (64 + 128) * 128;   // 98816
    const int SZ_64_64  = 512 + 2 * 2 * (64 + 64) * 128;    // 66048

#define SETSM(KERN, SZ) cudaFuncSetAttribute((const void*)(KERN), \
    cudaFuncAttributeMaxDynamicSharedMemorySize, SZ)
    SETSM((mmt<128, 64, 256, false, false, false, false, false>), SZ_128_64);
    SETSM((mmt<128, 64, 256, false, true,  false, false, true>),  SZ_128_64);
    SETSM((mmt<128, 64, 256, false, false, false, false, true>),  SZ_128_64);
    SETSM((mmt<64, 128, 256, false, false, false, true,  false>), SZ_64_128);
    SETSM((mmt<64, 64, 128, true,  true,  false, false, true>),   SZ_64_64);
    SETSM((mmt<64, 64, 128, false, false, false, false, false>),  SZ_64_64);
    SETSM((mmt<64, 64, 128, false, true,  true,  false, false>),  SZ_64_64);
#undef SETSM

    // ---- operand prep (xw GEMM stays the 4th launch for ncu) ----
    cvt_pair_kernel<<<(NND * NF) / 256, 256>>>(x, xh, xl, NND * NF);
    wt_kernel<<<(NF * NRel * NH) / 256, 256>>>(comp, basis, WtTh, WtTl);
    tcvt_kernel<<<(512 * 64 + 255) / 256, 256>>>(root, rootTh, rootTl, 512, 64);

    // xw = x @ Wt  [8192,1024], K=512
    mmt<128, 64, 256, false, false, false, false, false>
        <<<dim3(16, 64, 1), 256, SZ_128_64>>>(
        xh, xl, 512, 0, WtTh, WtTl, 512, 0,
        xw, nullptr, nullptr, 1024, 0, nullptr, 0, nullptr, nullptr, 512);

    // ---- CSR build ----
    zero_cnt_kernel<<<NND / 256, 256>>>(cnt);
    hist_kernel<<<NE / 256, 256>>>(ei, cnt);
    scan_kernel<<<1, 1024>>>(cnt, off, cur);
    fill_kernel<<<NE / 256, 256>>>(ei, et, cur, eidx);

    tcvt_kernel<<<(64 * 64 + 255) / 256, 256>>>(w_nbr, wnbrTh, wnbrTl, 64, 64);
    tcvt_kernel<<<(64 * 64 + 255) / 256, 256>>>(w_root, wrootTh, wrootTl, 64, 64);
    tcvt_kernel<<<(576 * 576 + 255) / 256, 256>>>(Wm, WmTh, WmTl, 576, 576);
    tcvt_kernel<<<(576 * 64 + 255) / 256, 256>>>(Wl, WlTh, WlTl, 576, 64);
    copy_x_kernel<<<(NND * 64) / 256, 256>>>(xh, xl, emoh, emol);

    rgcn_gather<<<NND, 64>>>(off, eidx, xw, agg);

    // h1 = agg + x@root + bias1 -> pairs  (K=512)
    mmt<64, 64, 128, true, true, false, false, true>
        <<<dim3(1, 128, 1), 128, SZ_64_64>>>(
        xh, xl, 512, 0, rootTh, rootTl, 512, 0,
        nullptr, h1h, h1l, 64, 0, agg, 64, bias1, nullptr, 512);

    // y = h1 @ w_nbr  (fp32, K=64)
    mmt<64, 64, 128, false, false, false, false, false>
        <<<dim3(1, 128, 1), 128, SZ_64_64>>>(
        h1h, h1l, 64, 0, wnbrTh, wnbrTl, 64, 0,
        y, nullptr, nullptr, 64, 0, nullptr, 0, nullptr, nullptr, 64);

    gc_gather<<<NND, 64>>>(off, eidx, y, nb);

    // h2 = nb + h1@w_root + bias2 -> emo pairs cols [512,576)  (K=64)
    mmt<64, 64, 128, true, true, false, false, true>
        <<<dim3(1, 128, 1), 128, SZ_64_64>>>(
        h1h, h1l, 64, 0, wrootTh, wrootTl, 64, 0,
        nullptr, emoh + NF, emol + NF, NDm, 0, nb, 64, bias2, nullptr, 64);

    emoT_kernel<<<dim3(NDm / 32, NL / 32, NBc), dim3(32, 8)>>>(emoh, emol, emoTh, emoTl);

    // Q = emo @ Wm + bm -> pairs  (K=576)
    mmt<128, 64, 256, false, true, false, false, true>
        <<<dim3(9, 64, 1), 256, SZ_128_64>>>(
        emoh, emol, NDm, 0, WmTh, WmTl, NDm, 0,
        nullptr, Qh, Ql, NDm, 0, nullptr, 0, bm, nullptr, NDm);

    // scores: per conv, S = tanh((Q . M) * u^2)  (fp32, K=576)
    mmt<64, 128, 256, false, false, false, true, false>
        <<<dim3(1, 2, NBc), 256, SZ_64_128>>>(
        Qh, Ql, NDm, (long long)NL * NDm, emoh, emol, NDm, (long long)NL * NDm,
        S, nullptr, nullptr, NL, (long long)NL * NL,
        nullptr, 0, nullptr, umask, NDm);

    softmax_kernel<<<NND, NL>>>(S, umask, Sh, Sl);

    // att = alpha @ emo -> pairs  (B = emoT, K=128)
    mmt<128, 64, 256, false, false, false, false, true>
        <<<dim3(9, 1, NBc), 256, SZ_128_64>>>(
        Sh, Sl, NL, (long long)NL * NL, emoTh, emoTl, NL, (long long)NDm * NL,
        nullptr, atth, attl, NDm, (long long)NL * NDm,
        nullptr, 0, nullptr, nullptr, NL);

    // hidden = relu(att @ Wl + bl)  (fp32, K=576)
    mmt<64, 64, 128, false, true, true, false, false>
        <<<dim3(1, 128, 1), 128, SZ_64_64>>>(
        atth, attl, NDm, 0, WlTh, WlTl, NDm, 0,
        hid, nullptr, nullptr, 64, 0, nullptr, 0, bl, nullptr, NDm);

    head_kernel<<<NND / 128, 128>>>(hid, Ws, bs, out);

    (void)in_sizes; (void)n_in; (void)out_size;
}

// round 7
// speedup vs baseline: 2.4793x; 1.0289x over previous
#include <cuda_runtime.h>
#include <cuda_bf16.h>
#include <math.h>
#include <cstdint>

// ---- problem constants ----
#define NND 8192
#define NF  512
#define NH  64
#define NRel 16
#define NBase 30
#define NE  524288
#define NBc 64
#define NL  128
#define NDm 576
#define NC  7
#define KC  64          // K chunk (bf16) per pipeline stage; 128B rows

typedef __nv_bfloat16 bf16;
typedef unsigned int u32;

// ---- static device scratch ----
__device__ __align__(16) bf16 g_xh[(size_t)NND * NF];
__device__ __align__(16) bf16 g_xl[(size_t)NND * NF];
__device__ __align__(16) bf16 g_WtTh[1024 * 512];
__device__ __align__(16) bf16 g_WtTl[1024 * 512];
__device__ __align__(16) bf16 g_rootTh[64 * 512];
__device__ __align__(16) bf16 g_rootTl[64 * 512];
__device__ __align__(16) bf16 g_wnbrTh[64 * 64];
__device__ __align__(16) bf16 g_wnbrTl[64 * 64];
__device__ __align__(16) bf16 g_wrootTh[64 * 64];
__device__ __align__(16) bf16 g_wrootTl[64 * 64];
__device__ __align__(16) bf16 g_WmTh[576 * 576];
__device__ __align__(16) bf16 g_WmTl[576 * 576];
__device__ __align__(16) bf16 g_WlTh[64 * 576];
__device__ __align__(16) bf16 g_WlTl[64 * 576];
__device__ __align__(16) bf16 g_h1h[NND * NH];
__device__ __align__(16) bf16 g_h1l[NND * NH];
__device__ __align__(16) bf16 g_emoh[(size_t)NND * NDm];
__device__ __align__(16) bf16 g_emol[(size_t)NND * NDm];
__device__ __align__(16) bf16 g_emoTh[(size_t)NBc * NDm * NL];
__device__ __align__(16) bf16 g_emoTl[(size_t)NBc * NDm * NL];
__device__ __align__(16) bf16 g_Qh[(size_t)NND * NDm];
__device__ __align__(16) bf16 g_Ql[(size_t)NND * NDm];
__device__ __align__(16) bf16 g_Sh[NND * NL];
__device__ __align__(16) bf16 g_Sl[NND * NL];
__device__ __align__(16) bf16 g_atth[(size_t)NND * NDm];
__device__ __align__(16) bf16 g_attl[(size_t)NND * NDm];

__device__ __align__(16) float g_xw[(size_t)NND * NRel * NH];
__device__ __align__(16) float g_agg[NND * NH];
__device__ __align__(16) float g_y[NND * NH];
__device__ __align__(16) float g_nb[NND * NH];
__device__ __align__(16) float g_S[(size_t)NND * NL];
__device__ __align__(16) float g_hid[NND * NH];
// CSR
__device__ int g_cnt[NND];
__device__ int g_off[NND + 1];
__device__ int g_cur[NND];
__device__ int g_eidx[NE];

__device__ __forceinline__ void split_pair(float v, bf16& h, bf16& l) {
    h = __float2bfloat16(v);
    l = __float2bfloat16(v - __bfloat162float(h));
}

__device__ __forceinline__ u32 smem_u32(const void* p) {
    u32 a;
    asm("{ .reg .u64 t; cvta.to.shared.u64 t, %1; cvt.u32.u64 %0, t; }"
        : "=r"(a) : "l"(p));
    return a;
}

__device__ __forceinline__ void mma16816(float* d, const u32* a, const u32* b) {
    asm volatile(
        "mma.sync.aligned.m16n8k16.row.col.f32.bf16.bf16.f32 "
        "{%0,%1,%2,%3}, {%4,%5,%6,%7}, {%8,%9}, {%0,%1,%2,%3};"
        : "+f"(d[0]), "+f"(d[1]), "+f"(d[2]), "+f"(d[3])
        : "r"(a[0]), "r"(a[1]), "r"(a[2]), "r"(a[3]), "r"(b[0]), "r"(b[1]));
}

#define LDSM4(r, addr) \
    asm volatile("ldmatrix.sync.aligned.m8n8.x4.shared.b16 {%0,%1,%2,%3}, [%4];" \
        : "=r"((r)[0]), "=r"((r)[1]), "=r"((r)[2]), "=r"((r)[3]) : "r"(addr))

#define CPA(d, s) \
    asm volatile("cp.async.cg.shared.global [%0], [%1], 16;" :: "r"(d), "l"(s) : "memory")
#define CPC() asm volatile("cp.async.commit_group;" ::: "memory")
#define CPW1() asm volatile("cp.async.wait_group 1;" ::: "memory")

// ============================================================
// Pipelined warp-MMA 3xBF16 GEMM: C[M,N] = A @ B^T
// A:[m][k] hi/lo, B:[n][k] hi/lo. SW128-swizzled SMEM, 2-stage cp.async.
// WN = NT/64 warps over N, WMC = WARPS/WN over M; warp tile (BM/WMC) x 64.
// ============================================================
template <int BM, int NT, int THREADS,
          bool ADD_D, bool BIAS, bool RELU, bool TANH_UM, bool OUT_PAIR>
__global__ void __launch_bounds__(THREADS, (THREADS == 128) ? 2 : 2)
mmt(const bf16* __restrict__ Ah, const bf16* __restrict__ Al, int lda, long long sA,
    const bf16* __restrict__ Bh, const bf16* __restrict__ Bl, int ldb, long long sB,
    float* __restrict__ C, bf16* __restrict__ Ch, bf16* __restrict__ Cl,
    int ldc, long long sC,
    const float* __restrict__ D, int ldd,
    const float* __restrict__ bias, const float* __restrict__ um,
    int K)
{
    constexpr int WARPS = THREADS / 32;
    constexpr int WN = NT / 64;
    constexpr int WMC = WARPS / WN;
    constexpr int WM = BM / WMC;
    constexpr int MI = WM / 16;
    constexpr int STAGE_ROWS = 2 * (BM + NT);
    constexpr int STAGE_B = STAGE_ROWS * 128;
    constexpr int CHUNKS = STAGE_ROWS * 8 / THREADS;

    extern __shared__ char smem[];
    float* ums = (float*)smem;
    const u32 sb0 = smem_u32(smem) + 512;

    const int tid = threadIdx.x;
    const int wid = tid >> 5, lane = tid & 31;
    const int warpM = wid % WMC, warpN = wid / WMC;
    const int bz = blockIdx.z;
    const int m0 = blockIdx.y * BM;
    const int n0 = blockIdx.x * NT;

    const char* pAh = (const char*)(Ah + sA * bz + (size_t)m0 * lda);
    const char* pAl = (const char*)(Al + sA * bz + (size_t)m0 * lda);
    const char* pBh = (const char*)(Bh + sB * bz + (size_t)n0 * ldb);
    const char* pBl = (const char*)(Bl + sB * bz + (size_t)n0 * ldb);
    const size_t ldab = (size_t)lda * 2;
    const size_t ldbb = (size_t)ldb * 2;

    if (TANH_UM && tid < NT) ums[tid] = um[bz * NL + n0 + tid];

    float acc[MI][8][4];
#pragma unroll
    for (int i = 0; i < MI; i++)
#pragma unroll
        for (int j = 0; j < 8; j++)
#pragma unroll
            for (int q = 0; q < 4; q++) acc[i][j][q] = 0.f;

    const int S = K / KC;

    auto load_stage = [&](int s) {
        const size_t kcb = (size_t)s * KC * 2;
        const u32 dst0 = sb0 + (u32)(s & 1) * STAGE_B;
#pragma unroll
        for (int f = 0; f < CHUNKS; f++) {
            int idx = tid + f * THREADS;
            int row = idx >> 3;
            u32 cb = (u32)(idx & 7) << 4;
            u32 sw = cb ^ (((u32)(row & 7)) << 4);
            const char* src;
            if (row < BM)               src = pAh + (size_t)row * ldab + kcb + cb;
            else if (row < 2 * BM)      src = pAl + (size_t)(row - BM) * ldab + kcb + cb;
            else if (row < 2 * BM + NT) src = pBh + (size_t)(row - 2 * BM) * ldbb + kcb + cb;
            else                        src = pBl + (size_t)(row - 2 * BM - NT) * ldbb + kcb + cb;
            CPA(dst0 + (u32)row * 128 + sw, src);
        }
    };

    load_stage(0);
    CPC();

    // per-lane fragment addressing (SW128); row&7 == lane&7 for all tiles used
    const u32 xorv = ((u32)(lane & 7)) << 4;
    const u32 aRow = (u32)(warpM * WM + (lane & 15));
    const u32 aCol0 = ((u32)(lane >> 4) & 1) * 16;
    const u32 bRow = (u32)(warpN * 64 + ((lane & 7) | ((lane & 16) >> 1)));
    const u32 bCol0 = ((u32)(lane >> 3) & 1) * 16;

    for (int s = 0; s < S; s++) {
        if (s + 1 < S) load_stage(s + 1);
        CPC();
        CPW1();
        __syncthreads();

        const u32 base = sb0 + (u32)(s & 1) * STAGE_B;
        const u32 aH = base + aRow * 128;
        const u32 aL = aH + (u32)BM * 128;
        const u32 bH = base + (u32)(2 * BM) * 128 + bRow * 128;
        const u32 bL = bH + (u32)NT * 128;

#pragma unroll
        for (int ks = 0; ks < KC / 16; ks++) {
            const u32 kb = (u32)ks * 32;
            const u32 acol = (aCol0 + kb) ^ xorv;
            const u32 bcol = (bCol0 + kb) ^ xorv;
            u32 bh[4][4], bl[4][4];
#pragma unroll
            for (int nt = 0; nt < 4; nt++) {
                LDSM4(bh[nt], bH + (u32)nt * (16 * 128) + bcol);
                LDSM4(bl[nt], bL + (u32)nt * (16 * 128) + bcol);
            }
#pragma unroll
            for (int mi = 0; mi < MI; mi++) {
                u32 ah[4], al[4];
                LDSM4(ah, aH + (u32)mi * (16 * 128) + acol);
                LDSM4(al, aL + (u32)mi * (16 * 128) + acol);
#pragma unroll
                for (int nt = 0; nt < 4; nt++)
#pragma unroll
                    for (int half = 0; half < 2; half++) {
                        float* a4 = acc[mi][nt * 2 + half];
                        mma16816(a4, ah, &bh[nt][half * 2]);
                        mma16816(a4, ah, &bl[nt][half * 2]);
                        mma16816(a4, al, &bh[nt][half * 2]);
                    }
            }
        }
        __syncthreads();
    }

    // ---- epilogue ----
#pragma unroll
    for (int mi = 0; mi < MI; mi++) {
        const int rm = m0 + warpM * WM + mi * 16 + (lane >> 2);
#pragma unroll
        for (int ni = 0; ni < 8; ni++) {
            const int cl = warpN * 64 + ni * 8 + (lane & 3) * 2;
            const int n = n0 + cl;
#pragma unroll
            for (int half = 0; half < 2; half++) {
                const int m = rm + half * 8;
                float v0 = acc[mi][ni][half * 2];
                float v1 = acc[mi][ni][half * 2 + 1];
                if (BIAS) { v0 += bias[n]; v1 += bias[n + 1]; }
                if (ADD_D) {
                    v0 += D[(size_t)m * ldd + n];
                    v1 += D[(size_t)m * ldd + n + 1];
                }
                if (TANH_UM) {
                    float u0 = ums[cl], u1 = ums[cl + 1];
                    v0 = tanhf(v0 * u0 * u0);
                    v1 = tanhf(v1 * u1 * u1);
                }
                if (RELU) { v0 = fmaxf(v0, 0.f); v1 = fmaxf(v1, 0.f); }
                const size_t base = (size_t)sC * bz + (size_t)m * ldc + n;
                if (OUT_PAIR) {
                    bf16 h0, l0, h1, l1;
                    split_pair(v0, h0, l0);
                    split_pair(v1, h1, l1);
                    *(__nv_bfloat162*)&Ch[base] = __nv_bfloat162(h0, h1);
                    *(__nv_bfloat162*)&Cl[base] = __nv_bfloat162(l0, l1);
                } else {
                    float2 f2; f2.x = v0; f2.y = v1;
                    *(float2*)&C[base] = f2;
                }
            }
        }
    }
}

// ============================================================
// conversion / transpose kernels
// ============================================================
__global__ void cvt_pair_kernel(const float* __restrict__ src,
                                bf16* __restrict__ hi, bf16* __restrict__ lo, int n)
{
    int i = blockIdx.x * 256 + threadIdx.x;
    if (i < n) { bf16 h, l; split_pair(src[i], h, l); hi[i] = h; lo[i] = l; }
}

__global__ void tcvt_kernel(const float* __restrict__ src,
                            bf16* __restrict__ hi, bf16* __restrict__ lo, int R, int C)
{
    int i = blockIdx.x * 256 + threadIdx.x;
    if (i >= R * C) return;
    int rr = i / C, cc = i % C;
    bf16 h, l; split_pair(src[i], h, l);
    hi[(size_t)cc * R + rr] = h;
    lo[(size_t)cc * R + rr] = l;
}

__global__ void wt_kernel(const float* __restrict__ comp,
                          const float* __restrict__ basis,
                          bf16* __restrict__ Wh, bf16* __restrict__ Wl)
{
    int idx = blockIdx.x * 256 + threadIdx.x;   // 524288
    int h = idx & 63, rr = (idx >> 6) & 15, k = idx >> 10;
    float acc = 0.f;
#pragma unroll
    for (int b = 0; b < NBase; b++)
        acc = fmaf(comp[rr * NBase + b], basis[((size_t)b * NF + k) * NH + h], acc);
    bf16 hh, ll; split_pair(acc, hh, ll);
    size_t o = (size_t)(rr * 64 + h) * 512 + k;
    Wh[o] = hh; Wl[o] = ll;
}

__global__ void copy_x_kernel(const bf16* __restrict__ xh, const bf16* __restrict__ xl,
                              bf16* __restrict__ eh, bf16* __restrict__ el)
{
    int id = blockIdx.x * 256 + threadIdx.x;    // 8192*64
    int row = id >> 6, c = id & 63;
    *(uint4*)&eh[(size_t)row * NDm + c * 8] = *(const uint4*)&xh[(size_t)row * NF + c * 8];
    *(uint4*)&el[(size_t)row * NDm + c * 8] = *(const uint4*)&xl[(size_t)row * NF + c * 8];
}

__global__ void emoT_kernel(const bf16* __restrict__ eh, const bf16* __restrict__ el,
                            bf16* __restrict__ th, bf16* __restrict__ tl)
{
    __shared__ unsigned short sh[32][33], sl[32][33];
    const int b = blockIdx.z;
    const int d0 = blockIdx.x * 32, t0 = blockIdx.y * 32;
    const int tx = threadIdx.x, ty = threadIdx.y;
#pragma unroll
    for (int q = 0; q < 4; q++) {
        int row = ty * 4 + q;
        size_t src = (size_t)(b * NL + t0 + row) * NDm + d0 + tx;
        sh[row][tx] = ((const unsigned short*)eh)[src];
        sl[row][tx] = ((const unsigned short*)el)[src];
    }
    __syncthreads();
#pragma unroll
    for (int q = 0; q < 4; q++) {
        int row = ty * 4 + q;
        size_t dst = (size_t)b * NDm * NL + (size_t)(d0 + row) * NL + t0 + tx;
        ((unsigned short*)th)[dst] = sh[tx][row];
        ((unsigned short*)tl)[dst] = sl[tx][row];
    }
}

// ---- CSR build ----
__global__ void zero_cnt_kernel(int* cnt)
{
    int i = blockIdx.x * 256 + threadIdx.x;
    if (i < NND) cnt[i] = 0;
}
__global__ void hist_kernel(const int* __restrict__ ei, int* __restrict__ cnt)
{
    int i = blockIdx.x * 256 + threadIdx.x;
    if (i < NE) atomicAdd(&cnt[ei[NE + i]], 1);
}
__global__ void __launch_bounds__(1024)
scan_kernel(const int* __restrict__ cnt, int* __restrict__ off, int* __restrict__ cur)
{
    __shared__ int s[NND];
    int t = threadIdx.x;
    for (int i = t; i < NND; i += 1024) s[i] = cnt[i];
    __syncthreads();
    for (int d = 1; d < NND; d <<= 1) {
        int v[8];
#pragma unroll
        for (int k = 0; k < 8; k++) {
            int i = t + k * 1024;
            v[k] = (i >= d) ? s[i - d] : 0;
        }
        __syncthreads();
#pragma unroll
        for (int k = 0; k < 8; k++) s[t + k * 1024] += v[k];
        __syncthreads();
    }
    for (int i = t; i < NND; i += 1024) {
        off[i + 1] = s[i];
        cur[i] = (i == 0) ? 0 : s[i - 1];
    }
    if (t == 0) off[0] = 0;
}
__global__ void fill_kernel(const int* __restrict__ ei, const int* __restrict__ et,
                            int* __restrict__ cur, int* __restrict__ eidx)
{
    int i = blockIdx.x * 256 + threadIdx.x;
    if (i >= NE) return;
    int dst = ei[NE + i];
    int pos = atomicAdd(&cur[dst], 1);
    eidx[pos] = ei[i] * 16 + et[i];
}

// ---- CSR gathers ----
__global__ void __launch_bounds__(64)
rgcn_gather(const int* __restrict__ off, const int* __restrict__ eidx,
            const float* __restrict__ xw, float* __restrict__ agg)
{
    const int n = blockIdx.x, h = threadIdx.x;
    const int beg = off[n], end = off[n + 1];
    float acc = 0.f;
    int e = beg;
    for (; e + 4 <= end; e += 4) {
        int p0 = eidx[e], p1 = eidx[e + 1], p2 = eidx[e + 2], p3 = eidx[e + 3];
        acc += xw[(size_t)(p0 >> 4) * 1024 + (p0 & 15) * 64 + h]
             + xw[(size_t)(p1 >> 4) * 1024 + (p1 & 15) * 64 + h]
             + xw[(size_t)(p2 >> 4) * 1024 + (p2 & 15) * 64 + h]
             + xw[(size_t)(p3 >> 4) * 1024 + (p3 & 15) * 64 + h];
    }
    for (; e < end; e++) {
        int p = eidx[e];
        acc += xw[(size_t)(p >> 4) * 1024 + (p & 15) * 64 + h];
    }
    agg[n * NH + h] = acc / fmaxf((float)(end - beg), 1.f);
}
__global__ void __launch_bounds__(64)
gc_gather(const int* __restrict__ off, const int* __restrict__ eidx,
          const float* __restrict__ y, float* __restrict__ nb)
{
    const int n = blockIdx.x, h = threadIdx.x;
    const int beg = off[n], end = off[n + 1];
    float acc = 0.f;
    int e = beg;
    for (; e + 4 <= end; e += 4) {
        int p0 = eidx[e], p1 = eidx[e + 1], p2 = eidx[e + 2], p3 = eidx[e + 3];
        acc += y[(p0 >> 4) * NH + h] + y[(p1 >> 4) * NH + h]
             + y[(p2 >> 4) * NH + h] + y[(p3 >> 4) * NH + h];
    }
    for (; e < end; e++) acc += y[(eidx[e] >> 4) * NH + h];
    nb[n * NH + h] = acc;
}

// softmax over k per (b,q): softmax(S)*u, renorm; emit bf16 pairs
__global__ void softmax_kernel(const float* __restrict__ S, const float* __restrict__ um,
                               bf16* __restrict__ Sh, bf16* __restrict__ Sl)
{
    __shared__ float red[NL];
    const int row = blockIdx.x;
    const int b = row >> 7;
    const int k = threadIdx.x;

    float s = S[(size_t)row * NL + k];
    red[k] = s; __syncthreads();
#pragma unroll
    for (int o = 64; o > 0; o >>= 1) { if (k < o) red[k] = fmaxf(red[k], red[k + o]); __syncthreads(); }
    float mx = red[0]; __syncthreads();

    float e = expf(s - mx);
    red[k] = e; __syncthreads();
#pragma unroll
    for (int o = 64; o > 0; o >>= 1) { if (k < o) red[k] += red[k + o]; __syncthreads(); }
    float sum1 = red[0]; __syncthreads();

    float a = (e / sum1) * um[b * NL + k];
    red[k] = a; __syncthreads();
#pragma unroll
    for (int o = 64; o > 0; o >>= 1) { if (k < o) red[k] += red[k + o]; __syncthreads(); }
    float sum2 = red[0];

    bf16 h, l; split_pair(a / sum2, h, l);
    Sh[(size_t)row * NL + k] = h;
    Sl[(size_t)row * NL + k] = l;
}

// head: logits = hid @ Ws + bs ; log_softmax
__global__ void head_kernel(const float* __restrict__ hid, const float* __restrict__ Ws,
                            const float* __restrict__ bsv, float* __restrict__ out)
{
    int n = blockIdx.x * blockDim.x + threadIdx.x;
    if (n >= NND) return;
    float lg[NC];
#pragma unroll
    for (int c = 0; c < NC; c++) lg[c] = bsv[c];
    const float* h = hid + (size_t)n * NH;
#pragma unroll 8
    for (int k = 0; k < NH; k++) {
        float hv = h[k];
#pragma unroll
        for (int c = 0; c < NC; c++) lg[c] = fmaf(hv, Ws[k * NC + c], lg[c]);
    }
    float mx = lg[0];
#pragma unroll
    for (int c = 1; c < NC; c++) mx = fmaxf(mx, lg[c]);
    float ssum = 0.f;
#pragma unroll
    for (int c = 0; c < NC; c++) ssum += expf(lg[c] - mx);
    float lse = mx + logf(ssum);
#pragma unroll
    for (int c = 0; c < NC; c++) out[(size_t)n * NC + c] = lg[c] - lse;
}

// ============================================================
extern "C" void kernel_launch(void* const* d_in, const int* in_sizes, int n_in,
                              void* d_out, int out_size)
{
    const float* x      = (const float*)d_in[0];
    const int*   ei     = (const int*)d_in[1];
    const int*   et     = (const int*)d_in[3];
    const float* umask  = (const float*)d_in[5];
    const float* basis  = (const float*)d_in[8];
    const float* comp   = (const float*)d_in[9];
    const float* root   = (const float*)d_in[10];
    const float* bias1  = (const float*)d_in[11];
    const float* w_nbr  = (const float*)d_in[12];
    const float* w_root = (const float*)d_in[13];
    const float* bias2  = (const float*)d_in[14];
    const float* Wm     = (const float*)d_in[15];
    const float* bm     = (const float*)d_in[16];
    const float* Wl     = (const float*)d_in[17];
    const float* bl     = (const float*)d_in[18];
    const float* Ws     = (const float*)d_in[19];
    const float* bs     = (const float*)d_in[20];
    float* out = (float*)d_out;

#define SYM(T, v, s) T* v; cudaGetSymbolAddress((void**)&v, s)
    SYM(bf16, xh, g_xh); SYM(bf16, xl, g_xl);
    SYM(bf16, WtTh, g_WtTh); SYM(bf16, WtTl, g_WtTl);
    SYM(bf16, rootTh, g_rootTh); SYM(bf16, rootTl, g_rootTl);
    SYM(bf16, wnbrTh, g_wnbrTh); SYM(bf16, wnbrTl, g_wnbrTl);
    SYM(bf16, wrootTh, g_wrootTh); SYM(bf16, wrootTl, g_wrootTl);
    SYM(bf16, WmTh, g_WmTh); SYM(bf16, WmTl, g_WmTl);
    SYM(bf16, WlTh, g_WlTh); SYM(bf16, WlTl, g_WlTl);
    SYM(bf16, h1h, g_h1h); SYM(bf16, h1l, g_h1l);
    SYM(bf16, emoh, g_emoh); SYM(bf16, emol, g_emol);
    SYM(bf16, emoTh, g_emoTh); SYM(bf16, emoTl, g_emoTl);
    SYM(bf16, Qh, g_Qh); SYM(bf16, Ql, g_Ql);
    SYM(bf16, Sh, g_Sh); SYM(bf16, Sl, g_Sl);
    SYM(bf16, atth, g_atth); SYM(bf16, attl, g_attl);
    SYM(float, xw, g_xw); SYM(float, agg, g_agg); SYM(float, y, g_y);
    SYM(float, nb, g_nb); SYM(float, S, g_S); SYM(float, hid, g_hid);
    SYM(int, cnt, g_cnt); SYM(int, off, g_off); SYM(int, cur, g_cur);
    SYM(int, eidx, g_eidx);
#undef SYM

    // dynamic smem: 512 + 2 stages * 2*(BM+NT) rows * 128B
    const int SZ_128_64 = 512 + 2 * 2 * (128 + 64) * 128;   // 98816
    const int SZ_64_128 = 512 + 2 * 2 * (64 + 128) * 128;   // 98816
    const int SZ_64_64  = 512 + 2 * 2 * (64 + 64) * 128;    // 66048

#define SETSM(KERN, SZ) cudaFuncSetAttribute((const void*)(KERN), \
    cudaFuncAttributeMaxDynamicSharedMemorySize, SZ)
    SETSM((mmt<128, 64, 128, false, false, false, false, false>), SZ_128_64);
    SETSM((mmt<128, 64, 128, false, true,  false, false, true>),  SZ_128_64);
    SETSM((mmt<128, 64, 128, false, false, false, false, true>),  SZ_128_64);
    SETSM((mmt<64, 128, 128, false, false, false, true,  false>), SZ_64_128);
    SETSM((mmt<64, 64, 128, true,  true,  false, false, true>),   SZ_64_64);
    SETSM((mmt<64, 64, 128, false, false, false, false, false>),  SZ_64_64);
    SETSM((mmt<64, 64, 128, false, true,  true,  false, false>),  SZ_64_64);
#undef SETSM

    // ---- operand prep (xw GEMM stays the 4th launch for ncu) ----
    cvt_pair_kernel<<<(NND * NF) / 256, 256>>>(x, xh, xl, NND * NF);
    wt_kernel<<<(NF * NRel * NH) / 256, 256>>>(comp, basis, WtTh, WtTl);
    tcvt_kernel<<<(512 * 64 + 255) / 256, 256>>>(root, rootTh, rootTl, 512, 64);

    // xw = x @ Wt  [8192,1024], K=512  (MI=2: warp tile 32x64)
    mmt<128, 64, 128, false, false, false, false, false>
        <<<dim3(16, 64, 1), 128, SZ_128_64>>>(
        xh, xl, 512, 0, WtTh, WtTl, 512, 0,
        xw, nullptr, nullptr, 1024, 0, nullptr, 0, nullptr, nullptr, 512);

    // ---- CSR build ----
    zero_cnt_kernel<<<NND / 256, 256>>>(cnt);
    hist_kernel<<<NE / 256, 256>>>(ei, cnt);
    scan_kernel<<<1, 1024>>>(cnt, off, cur);
    fill_kernel<<<NE / 256, 256>>>(ei, et, cur, eidx);

    tcvt_kernel<<<(64 * 64 + 255) / 256, 256>>>(w_nbr, wnbrTh, wnbrTl, 64, 64);
    tcvt_kernel<<<(64 * 64 + 255) / 256, 256>>>(w_root, wrootTh, wrootTl, 64, 64);
    tcvt_kernel<<<(576 * 576 + 255) / 256, 256>>>(Wm, WmTh, WmTl, 576, 576);
    tcvt_kernel<<<(576 * 64 + 255) / 256, 256>>>(Wl, WlTh, WlTl, 576, 64);
    copy_x_kernel<<<(NND * 64) / 256, 256>>>(xh, xl, emoh, emol);

    rgcn_gather<<<NND, 64>>>(off, eidx, xw, agg);

    // h1 = agg + x@root + bias1 -> pairs  (K=512)
    mmt<64, 64, 128, true, true, false, false, true>
        <<<dim3(1, 128, 1), 128, SZ_64_64>>>(
        xh, xl, 512, 0, rootTh, rootTl, 512, 0,
        nullptr, h1h, h1l, 64, 0, agg, 64, bias1, nullptr, 512);

    // y = h1 @ w_nbr  (fp32, K=64)
    mmt<64, 64, 128, false, false, false, false, false>
        <<<dim3(1, 128, 1), 128, SZ_64_64>>>(
        h1h, h1l, 64, 0, wnbrTh, wnbrTl, 64, 0,
        y, nullptr, nullptr, 64, 0, nullptr, 0, nullptr, nullptr, 64);

    gc_gather<<<NND, 64>>>(off, eidx, y, nb);

    // h2 = nb + h1@w_root + bias2 -> emo pairs cols [512,576)  (K=64)
    mmt<64, 64, 128, true, true, false, false, true>
        <<<dim3(1, 128, 1), 128, SZ_64_64>>>(
        h1h, h1l, 64, 0, wrootTh, wrootTl, 64, 0,
        nullptr, emoh + NF, emol + NF, NDm, 0, nb, 64, bias2, nullptr, 64);

    emoT_kernel<<<dim3(NDm / 32, NL / 32, NBc), dim3(32, 8)>>>(emoh, emol, emoTh, emoTl);

    // Q = emo @ Wm + bm -> pairs  (K=576, MI=2)
    mmt<128, 64, 128, false, true, false, false, true>
        <<<dim3(9, 64, 1), 128, SZ_128_64>>>(
        emoh, emol, NDm, 0, WmTh, WmTl, NDm, 0,
        nullptr, Qh, Ql, NDm, 0, nullptr, 0, bm, nullptr, NDm);

    // scores: per conv, S = tanh((Q . M) * u^2)  (fp32, K=576, MI=2)
    mmt<64, 128, 128, false, false, false, true, false>
        <<<dim3(1, 2, NBc), 128, SZ_64_128>>>(
        Qh, Ql, NDm, (long long)NL * NDm, emoh, emol, NDm, (long long)NL * NDm,
        S, nullptr, nullptr, NL, (long long)NL * NL,
        nullptr, 0, nullptr, umask, NDm);

    softmax_kernel<<<NND, NL>>>(S, umask, Sh, Sl);

    // att = alpha @ emo -> pairs  (B = emoT, K=128, MI=2)
    mmt<128, 64, 128, false, false, false, false, true>
        <<<dim3(9, 1, NBc), 128, SZ_128_64>>>(
        Sh, Sl, NL, (long long)NL * NL, emoTh, emoTl, NL, (long long)NDm * NL,
        nullptr, atth, attl, NDm, (long long)NL * NDm,
        nullptr, 0, nullptr, nullptr, NL);

    // hidden = relu(att @ Wl + bl)  (fp32, K=576)
    mmt<64, 64, 128, false, true, true, false, false>
        <<<dim3(1, 128, 1), 128, SZ_64_64>>>(
        atth, attl, NDm, 0, WlTh, WlTl, NDm, 0,
        hid, nullptr, nullptr, 64, 0, nullptr, 0, bl, nullptr, NDm);

    head_kernel<<<NND / 128, 128>>>(hid, Ws, bs, out);

    (void)in_sizes; (void)n_in; (void)out_size;
}

// round 8
// speedup vs baseline: 2.6033x; 1.0500x over previous
#include <cuda_runtime.h>
#include <cuda_bf16.h>
#include <math.h>
#include <cstdint>

// ---- problem constants ----
#define NND 8192
#define NF  512
#define NH  64
#define NRel 16
#define NBase 30
#define NE  524288
#define NBc 64
#define NL  128
#define NDm 576
#define NC  7
#define KC  64          // K chunk (bf16) per pipeline stage; 128B rows

typedef __nv_bfloat16 bf16;
typedef unsigned int u32;

// ---- static device scratch ----
__device__ __align__(16) bf16 g_xh[(size_t)NND * NF];
__device__ __align__(16) bf16 g_xl[(size_t)NND * NF];
__device__ __align__(16) bf16 g_WtTh[1024 * 512];
__device__ __align__(16) bf16 g_WtTl[1024 * 512];
__device__ __align__(16) bf16 g_rootTh[64 * 512];
__device__ __align__(16) bf16 g_rootTl[64 * 512];
__device__ __align__(16) bf16 g_wnbrTh[64 * 64];
__device__ __align__(16) bf16 g_wnbrTl[64 * 64];
__device__ __align__(16) bf16 g_wrootTh[64 * 64];
__device__ __align__(16) bf16 g_wrootTl[64 * 64];
__device__ __align__(16) bf16 g_WmTh[576 * 576];
__device__ __align__(16) bf16 g_WmTl[576 * 576];
__device__ __align__(16) bf16 g_WlTh[64 * 576];
__device__ __align__(16) bf16 g_WlTl[64 * 576];
__device__ __align__(16) bf16 g_h1h[NND * NH];
__device__ __align__(16) bf16 g_h1l[NND * NH];
__device__ __align__(16) bf16 g_emoh[(size_t)NND * NDm];
__device__ __align__(16) bf16 g_emol[(size_t)NND * NDm];
__device__ __align__(16) bf16 g_emoTh[(size_t)NBc * NDm * NL];
__device__ __align__(16) bf16 g_emoTl[(size_t)NBc * NDm * NL];
__device__ __align__(16) bf16 g_Qh[(size_t)NND * NDm];
__device__ __align__(16) bf16 g_Ql[(size_t)NND * NDm];
__device__ __align__(16) bf16 g_Sh[NND * NL];
__device__ __align__(16) bf16 g_Sl[NND * NL];
__device__ __align__(16) bf16 g_atth[(size_t)NND * NDm];
__device__ __align__(16) bf16 g_attl[(size_t)NND * NDm];

__device__ __align__(16) float g_xw[(size_t)NND * NRel * NH];
__device__ __align__(16) float g_agg[NND * NH];
__device__ __align__(16) float g_y[NND * NH];
__device__ __align__(16) float g_nb[NND * NH];
__device__ __align__(16) float g_hid[NND * NH];
// CSR
__device__ int g_cnt[NND];
__device__ int g_off[NND + 1];
__device__ int g_cur[NND];
__device__ int g_eidx[NE];

__device__ __forceinline__ void split_pair(float v, bf16& h, bf16& l) {
    h = __float2bfloat16(v);
    l = __float2bfloat16(v - __bfloat162float(h));
}

__device__ __forceinline__ u32 smem_u32(const void* p) {
    u32 a;
    asm("{ .reg .u64 t; cvta.to.shared.u64 t, %1; cvt.u32.u64 %0, t; }"
        : "=r"(a) : "l"(p));
    return a;
}

__device__ __forceinline__ void mma16816(float* d, const u32* a, const u32* b) {
    asm volatile(
        "mma.sync.aligned.m16n8k16.row.col.f32.bf16.bf16.f32 "
        "{%0,%1,%2,%3}, {%4,%5,%6,%7}, {%8,%9}, {%0,%1,%2,%3};"
        : "+f"(d[0]), "+f"(d[1]), "+f"(d[2]), "+f"(d[3])
        : "r"(a[0]), "r"(a[1]), "r"(a[2]), "r"(a[3]), "r"(b[0]), "r"(b[1]));
}

#define LDSM4(r, addr) \
    asm volatile("ldmatrix.sync.aligned.m8n8.x4.shared.b16 {%0,%1,%2,%3}, [%4];" \
        : "=r"((r)[0]), "=r"((r)[1]), "=r"((r)[2]), "=r"((r)[3]) : "r"(addr))

#define CPA(d, s) \
    asm volatile("cp.async.cg.shared.global [%0], [%1], 16;" :: "r"(d), "l"(s) : "memory")
#define CPC() asm volatile("cp.async.commit_group;" ::: "memory")
#define CPW1() asm volatile("cp.async.wait_group 1;" ::: "memory")

// ============================================================
// Pipelined warp-MMA 3xBF16 GEMM: C[M,N] = A @ B^T
// A:[m][k] hi/lo, B:[n][k] hi/lo. SW128-swizzled SMEM, 2-stage cp.async.
// ============================================================
template <int BM, int NT, int THREADS,
          bool ADD_D, bool BIAS, bool RELU, bool OUT_PAIR>
__global__ void __launch_bounds__(THREADS, 2)
mmt(const bf16* __restrict__ Ah, const bf16* __restrict__ Al, int lda, long long sA,
    const bf16* __restrict__ Bh, const bf16* __restrict__ Bl, int ldb, long long sB,
    float* __restrict__ C, bf16* __restrict__ Ch, bf16* __restrict__ Cl,
    int ldc, long long sC,
    const float* __restrict__ D, int ldd,
    const float* __restrict__ bias,
    int K)
{
    constexpr int WARPS = THREADS / 32;
    constexpr int WN = NT / 64;
    constexpr int WMC = WARPS / WN;
    constexpr int WM = BM / WMC;
    constexpr int MI = WM / 16;
    constexpr int STAGE_ROWS = 2 * (BM + NT);
    constexpr int STAGE_B = STAGE_ROWS * 128;
    constexpr int CHUNKS = STAGE_ROWS * 8 / THREADS;

    extern __shared__ char smem[];
    const u32 sb0 = smem_u32(smem) + 512;

    const int tid = threadIdx.x;
    const int wid = tid >> 5, lane = tid & 31;
    const int warpM = wid % WMC, warpN = wid / WMC;
    const int bz = blockIdx.z;
    const int m0 = blockIdx.y * BM;
    const int n0 = blockIdx.x * NT;

    const char* pAh = (const char*)(Ah + sA * bz + (size_t)m0 * lda);
    const char* pAl = (const char*)(Al + sA * bz + (size_t)m0 * lda);
    const char* pBh = (const char*)(Bh + sB * bz + (size_t)n0 * ldb);
    const char* pBl = (const char*)(Bl + sB * bz + (size_t)n0 * ldb);
    const size_t ldab = (size_t)lda * 2;
    const size_t ldbb = (size_t)ldb * 2;

    float acc[MI][8][4];
#pragma unroll
    for (int i = 0; i < MI; i++)
#pragma unroll
        for (int j = 0; j < 8; j++)
#pragma unroll
            for (int q = 0; q < 4; q++) acc[i][j][q] = 0.f;

    const int S = K / KC;

    auto load_stage = [&](int s) {
        const size_t kcb = (size_t)s * KC * 2;
        const u32 dst0 = sb0 + (u32)(s & 1) * STAGE_B;
#pragma unroll
        for (int f = 0; f < CHUNKS; f++) {
            int idx = tid + f * THREADS;
            int row = idx >> 3;
            u32 cb = (u32)(idx & 7) << 4;
            u32 sw = cb ^ (((u32)(row & 7)) << 4);
            const char* src;
            if (row < BM)               src = pAh + (size_t)row * ldab + kcb + cb;
            else if (row < 2 * BM)      src = pAl + (size_t)(row - BM) * ldab + kcb + cb;
            else if (row < 2 * BM + NT) src = pBh + (size_t)(row - 2 * BM) * ldbb + kcb + cb;
            else                        src = pBl + (size_t)(row - 2 * BM - NT) * ldbb + kcb + cb;
            CPA(dst0 + (u32)row * 128 + sw, src);
        }
    };

    load_stage(0);
    CPC();

    const u32 xorv = ((u32)(lane & 7)) << 4;
    const u32 aRow = (u32)(warpM * WM + (lane & 15));
    const u32 aCol0 = ((u32)(lane >> 4) & 1) * 16;
    const u32 bRow = (u32)(warpN * 64 + ((lane & 7) | ((lane & 16) >> 1)));
    const u32 bCol0 = ((u32)(lane >> 3) & 1) * 16;

    for (int s = 0; s < S; s++) {
        if (s + 1 < S) load_stage(s + 1);
        CPC();
        CPW1();
        __syncthreads();

        const u32 base = sb0 + (u32)(s & 1) * STAGE_B;
        const u32 aH = base + aRow * 128;
        const u32 aL = aH + (u32)BM * 128;
        const u32 bH = base + (u32)(2 * BM) * 128 + bRow * 128;
        const u32 bL = bH + (u32)NT * 128;

#pragma unroll
        for (int ks = 0; ks < KC / 16; ks++) {
            const u32 kb = (u32)ks * 32;
            const u32 acol = (aCol0 + kb) ^ xorv;
            const u32 bcol = (bCol0 + kb) ^ xorv;
            u32 ah[MI][4], al[MI][4];
#pragma unroll
            for (int mi = 0; mi < MI; mi++) {
                LDSM4(ah[mi], aH + (u32)mi * (16 * 128) + acol);
                LDSM4(al[mi], aL + (u32)mi * (16 * 128) + acol);
            }
#pragma unroll
            for (int nt = 0; nt < 4; nt++) {
                u32 bh[4], bl[4];
                LDSM4(bh, bH + (u32)nt * (16 * 128) + bcol);
                LDSM4(bl, bL + (u32)nt * (16 * 128) + bcol);
#pragma unroll
                for (int mi = 0; mi < MI; mi++)
#pragma unroll
                    for (int half = 0; half < 2; half++) {
                        float* a4 = acc[mi][nt * 2 + half];
                        mma16816(a4, ah[mi], &bh[half * 2]);
                        mma16816(a4, ah[mi], &bl[half * 2]);
                        mma16816(a4, al[mi], &bh[half * 2]);
                    }
            }
        }
        __syncthreads();
    }

    // ---- epilogue ----
#pragma unroll
    for (int mi = 0; mi < MI; mi++) {
        const int rm = m0 + warpM * WM + mi * 16 + (lane >> 2);
#pragma unroll
        for (int ni = 0; ni < 8; ni++) {
            const int n = n0 + warpN * 64 + ni * 8 + (lane & 3) * 2;
#pragma unroll
            for (int half = 0; half < 2; half++) {
                const int m = rm + half * 8;
                float v0 = acc[mi][ni][half * 2];
                float v1 = acc[mi][ni][half * 2 + 1];
                if (BIAS) { v0 += bias[n]; v1 += bias[n + 1]; }
                if (ADD_D) {
                    v0 += D[(size_t)m * ldd + n];
                    v1 += D[(size_t)m * ldd + n + 1];
                }
                if (RELU) { v0 = fmaxf(v0, 0.f); v1 = fmaxf(v1, 0.f); }
                const size_t base = (size_t)sC * bz + (size_t)m * ldc + n;
                if (OUT_PAIR) {
                    bf16 h0, l0, h1, l1;
                    split_pair(v0, h0, l0);
                    split_pair(v1, h1, l1);
                    *(__nv_bfloat162*)&Ch[base] = __nv_bfloat162(h0, h1);
                    *(__nv_bfloat162*)&Cl[base] = __nv_bfloat162(l0, l1);
                } else {
                    float2 f2; f2.x = v0; f2.y = v1;
                    *(float2*)&C[base] = f2;
                }
            }
        }
    }
}

// ============================================================
// Fused scores kernel: S = tanh((Q.M)*u^2) -> softmax -> *u -> renorm
// -> bf16 pairs. BM=64 q-rows per block, NT=128 (full k), 128 threads.
// ============================================================
__global__ void __launch_bounds__(128, 2)
scores_softmax(const bf16* __restrict__ Qh, const bf16* __restrict__ Ql,
               const bf16* __restrict__ Mh, const bf16* __restrict__ Ml,
               const float* __restrict__ um,
               bf16* __restrict__ Sh, bf16* __restrict__ Sl)
{
    constexpr int BM = 64, NT = 128, THREADS = 128;
    constexpr int STAGE_ROWS = 2 * (BM + NT);       // 384
    constexpr int STAGE_B = STAGE_ROWS * 128;
    constexpr int CHUNKS = STAGE_ROWS * 8 / THREADS;  // 24

    extern __shared__ char smem[];
    float* ums = (float*)smem;
    float* sbuf = (float*)(smem + 512);              // aliases stage area post-GEMM
    const u32 sb0 = smem_u32(smem) + 512;

    const int tid = threadIdx.x;
    const int wid = tid >> 5, lane = tid & 31;
    const int warpM = wid & 1, warpN = wid >> 1;     // WMC=2, WN=2
    const int bz = blockIdx.z;
    const int m0 = blockIdx.y * BM;

    const char* pAh = (const char*)(Qh + (size_t)bz * NL * NDm + (size_t)m0 * NDm);
    const char* pAl = (const char*)(Ql + (size_t)bz * NL * NDm + (size_t)m0 * NDm);
    const char* pBh = (const char*)(Mh + (size_t)bz * NL * NDm);
    const char* pBl = (const char*)(Ml + (size_t)bz * NL * NDm);
    const size_t ldab = (size_t)NDm * 2;

    if (tid < NT) ums[tid] = um[bz * NL + tid];

    float acc[2][8][4];
#pragma unroll
    for (int i = 0; i < 2; i++)
#pragma unroll
        for (int j = 0; j < 8; j++)
#pragma unroll
            for (int q = 0; q < 4; q++) acc[i][j][q] = 0.f;

    const int S = NDm / KC;   // 9

    auto load_stage = [&](int s) {
        const size_t kcb = (size_t)s * KC * 2;
        const u32 dst0 = sb0 + (u32)(s & 1) * STAGE_B;
#pragma unroll
        for (int f = 0; f < CHUNKS; f++) {
            int idx = tid + f * THREADS;
            int row = idx >> 3;
            u32 cb = (u32)(idx & 7) << 4;
            u32 sw = cb ^ (((u32)(row & 7)) << 4);
            const char* src;
            if (row < BM)               src = pAh + (size_t)row * ldab + kcb + cb;
            else if (row < 2 * BM)      src = pAl + (size_t)(row - BM) * ldab + kcb + cb;
            else if (row < 2 * BM + NT) src = pBh + (size_t)(row - 2 * BM) * ldab + kcb + cb;
            else                        src = pBl + (size_t)(row - 2 * BM - NT) * ldab + kcb + cb;
            CPA(dst0 + (u32)row * 128 + sw, src);
        }
    };

    load_stage(0);
    CPC();

    const u32 xorv = ((u32)(lane & 7)) << 4;
    const u32 aRow = (u32)(warpM * 32 + (lane & 15));
    const u32 aCol0 = ((u32)(lane >> 4) & 1) * 16;
    const u32 bRow = (u32)(warpN * 64 + ((lane & 7) | ((lane & 16) >> 1)));
    const u32 bCol0 = ((u32)(lane >> 3) & 1) * 16;

    for (int s = 0; s < S; s++) {
        if (s + 1 < S) load_stage(s + 1);
        CPC();
        CPW1();
        __syncthreads();

        const u32 base = sb0 + (u32)(s & 1) * STAGE_B;
        const u32 aH = base + aRow * 128;
        const u32 aL = aH + (u32)BM * 128;
        const u32 bH = base + (u32)(2 * BM) * 128 + bRow * 128;
        const u32 bL = bH + (u32)NT * 128;

#pragma unroll
        for (int ks = 0; ks < KC / 16; ks++) {
            const u32 kb = (u32)ks * 32;
            const u32 acol = (aCol0 + kb) ^ xorv;
            const u32 bcol = (bCol0 + kb) ^ xorv;
            u32 ah[2][4], al[2][4];
#pragma unroll
            for (int mi = 0; mi < 2; mi++) {
                LDSM4(ah[mi], aH + (u32)mi * (16 * 128) + acol);
                LDSM4(al[mi], aL + (u32)mi * (16 * 128) + acol);
            }
#pragma unroll
            for (int nt = 0; nt < 4; nt++) {
                u32 bh[4], bl[4];
                LDSM4(bh, bH + (u32)nt * (16 * 128) + bcol);
                LDSM4(bl, bL + (u32)nt * (16 * 128) + bcol);
#pragma unroll
                for (int mi = 0; mi < 2; mi++)
#pragma unroll
                    for (int half = 0; half < 2; half++) {
                        float* a4 = acc[mi][nt * 2 + half];
                        mma16816(a4, ah[mi], &bh[half * 2]);
                        mma16816(a4, ah[mi], &bl[half * 2]);
                        mma16816(a4, al[mi], &bh[half * 2]);
                    }
            }
        }
        __syncthreads();
    }

    // ---- tanh(score*u^2) into smem buffer (stride 132) ----
#pragma unroll
    for (int mi = 0; mi < 2; mi++) {
#pragma unroll
        for (int ni = 0; ni < 8; ni++) {
            const int col = warpN * 64 + ni * 8 + (lane & 3) * 2;
            const float u0 = ums[col], u1 = ums[col + 1];
#pragma unroll
            for (int half = 0; half < 2; half++) {
                const int row = warpM * 32 + mi * 16 + (lane >> 2) + half * 8;
                float v0 = tanhf(acc[mi][ni][half * 2] * u0 * u0);
                float v1 = tanhf(acc[mi][ni][half * 2 + 1] * u1 * u1);
                float2 f2; f2.x = v0; f2.y = v1;
                *(float2*)&sbuf[row * 132 + col] = f2;
            }
        }
    }
    __syncthreads();

    // ---- per-row softmax: warp w owns rows [w*16, w*16+16) ----
    for (int r8 = 0; r8 < 16; r8++) {
        const int row = wid * 16 + r8;
        float4 v = *(const float4*)&sbuf[row * 132 + lane * 4];
        float mx = fmaxf(fmaxf(v.x, v.y), fmaxf(v.z, v.w));
#pragma unroll
        for (int o = 16; o > 0; o >>= 1)
            mx = fmaxf(mx, __shfl_xor_sync(0xffffffffu, mx, o));
        float e0 = expf(v.x - mx), e1 = expf(v.y - mx);
        float e2 = expf(v.z - mx), e3 = expf(v.w - mx);
        float sum1 = e0 + e1 + e2 + e3;
#pragma unroll
        for (int o = 16; o > 0; o >>= 1)
            sum1 += __shfl_xor_sync(0xffffffffu, sum1, o);
        const int col = lane * 4;
        float a0 = (e0 / sum1) * ums[col];
        float a1 = (e1 / sum1) * ums[col + 1];
        float a2 = (e2 / sum1) * ums[col + 2];
        float a3 = (e3 / sum1) * ums[col + 3];
        float sum2 = a0 + a1 + a2 + a3;
#pragma unroll
        for (int o = 16; o > 0; o >>= 1)
            sum2 += __shfl_xor_sync(0xffffffffu, sum2, o);
        float inv = 1.f / sum2;
        bf16 h0, l0, h1, l1, h2, l2, h3, l3;
        split_pair(a0 * inv, h0, l0);
        split_pair(a1 * inv, h1, l1);
        split_pair(a2 * inv, h2, l2);
        split_pair(a3 * inv, h3, l3);
        const size_t o0 = (size_t)(bz * NL + m0 + row) * NL + col;
        *(__nv_bfloat162*)&Sh[o0]     = __nv_bfloat162(h0, h1);
        *(__nv_bfloat162*)&Sh[o0 + 2] = __nv_bfloat162(h2, h3);
        *(__nv_bfloat162*)&Sl[o0]     = __nv_bfloat162(l0, l1);
        *(__nv_bfloat162*)&Sl[o0 + 2] = __nv_bfloat162(l2, l3);
    }
}

// ============================================================
// conversion / transpose kernels
// ============================================================
// x -> xh/xl pairs AND emo cols [0,512)
__global__ void cvtx_kernel(const float* __restrict__ x,
                            bf16* __restrict__ xh, bf16* __restrict__ xl,
                            bf16* __restrict__ eh, bf16* __restrict__ el)
{
    int i = blockIdx.x * 256 + threadIdx.x;     // 8192*512
    bf16 h, l; split_pair(x[i], h, l);
    xh[i] = h; xl[i] = l;
    int row = i >> 9, c = i & 511;
    size_t eo = (size_t)row * NDm + c;
    eh[eo] = h; el[eo] = l;
}

// batched transpose+split of the five weight matrices
__global__ void tcvt_all_kernel(
    const float* __restrict__ root, bf16* __restrict__ rTh, bf16* __restrict__ rTl,
    const float* __restrict__ wn, bf16* __restrict__ wnTh, bf16* __restrict__ wnTl,
    const float* __restrict__ wr, bf16* __restrict__ wrTh, bf16* __restrict__ wrTl,
    const float* __restrict__ Wm, bf16* __restrict__ WmTh, bf16* __restrict__ WmTl,
    const float* __restrict__ Wl, bf16* __restrict__ WlTh, bf16* __restrict__ WlTl)
{
    int i = blockIdx.x * 256 + threadIdx.x;
    const float* src; bf16 *dh, *dl; int R, C, base;
    if (i < 32768)       { src = root; dh = rTh;  dl = rTl;  R = 512; C = 64;  base = 0; }
    else if (i < 36864)  { src = wn;   dh = wnTh; dl = wnTl; R = 64;  C = 64;  base = 32768; }
    else if (i < 40960)  { src = wr;   dh = wrTh; dl = wrTl; R = 64;  C = 64;  base = 36864; }
    else if (i < 372736) { src = Wm;   dh = WmTh; dl = WmTl; R = 576; C = 576; base = 40960; }
    else if (i < 409600) { src = Wl;   dh = WlTh; dl = WlTl; R = 576; C = 64;  base = 372736; }
    else return;
    int j = i - base;
    int rr = j / C, cc = j % C;
    bf16 h, l; split_pair(src[j], h, l);
    dh[(size_t)cc * R + rr] = h;
    dl[(size_t)cc * R + rr] = l;
}

__global__ void wt_kernel(const float* __restrict__ comp,
                          const float* __restrict__ basis,
                          bf16* __restrict__ Wh, bf16* __restrict__ Wl)
{
    int idx = blockIdx.x * 256 + threadIdx.x;   // 524288
    int h = idx & 63, rr = (idx >> 6) & 15, k = idx >> 10;
    float acc = 0.f;
#pragma unroll
    for (int b = 0; b < NBase; b++)
        acc = fmaf(comp[rr * NBase + b], basis[((size_t)b * NF + k) * NH + h], acc);
    bf16 hh, ll; split_pair(acc, hh, ll);
    size_t o = (size_t)(rr * 64 + h) * 512 + k;
    Wh[o] = hh; Wl[o] = ll;
}

__global__ void emoT_kernel(const bf16* __restrict__ eh, const bf16* __restrict__ el,
                            bf16* __restrict__ th, bf16* __restrict__ tl)
{
    __shared__ unsigned short sh[32][33], sl[32][33];
    const int b = blockIdx.z;
    const int d0 = blockIdx.x * 32, t0 = blockIdx.y * 32;
    const int tx = threadIdx.x, ty = threadIdx.y;
#pragma unroll
    for (int q = 0; q < 4; q++) {
        int row = ty * 4 + q;
        size_t src = (size_t)(b * NL + t0 + row) * NDm + d0 + tx;
        sh[row][tx] = ((const unsigned short*)eh)[src];
        sl[row][tx] = ((const unsigned short*)el)[src];
    }
    __syncthreads();
#pragma unroll
    for (int q = 0; q < 4; q++) {
        int row = ty * 4 + q;
        size_t dst = (size_t)b * NDm * NL + (size_t)(d0 + row) * NL + t0 + tx;
        ((unsigned short*)th)[dst] = sh[tx][row];
        ((unsigned short*)tl)[dst] = sl[tx][row];
    }
}

// ---- CSR build ----
__global__ void zero_cnt_kernel(int* cnt)
{
    int i = blockIdx.x * 256 + threadIdx.x;
    if (i < NND) cnt[i] = 0;
}
__global__ void hist_kernel(const int* __restrict__ ei, int* __restrict__ cnt)
{
    int i = blockIdx.x * 256 + threadIdx.x;
    if (i < NE) atomicAdd(&cnt[ei[NE + i]], 1);
}
__global__ void __launch_bounds__(1024)
scan_kernel(const int* __restrict__ cnt, int* __restrict__ off, int* __restrict__ cur)
{
    __shared__ int s[NND];
    int t = threadIdx.x;
    for (int i = t; i < NND; i += 1024) s[i] = cnt[i];
    __syncthreads();
    for (int d = 1; d < NND; d <<= 1) {
        int v[8];
#pragma unroll
        for (int k = 0; k < 8; k++) {
            int i = t + k * 1024;
            v[k] = (i >= d) ? s[i - d] : 0;
        }
        __syncthreads();
#pragma unroll
        for (int k = 0; k < 8; k++) s[t + k * 1024] += v[k];
        __syncthreads();
    }
    for (int i = t; i < NND; i += 1024) {
        off[i + 1] = s[i];
        cur[i] = (i == 0) ? 0 : s[i - 1];
    }
    if (t == 0) off[0] = 0;
}
__global__ void fill_kernel(const int* __restrict__ ei, const int* __restrict__ et,
                            int* __restrict__ cur, int* __restrict__ eidx)
{
    int i = blockIdx.x * 256 + threadIdx.x;
    if (i >= NE) return;
    int dst = ei[NE + i];
    int pos = atomicAdd(&cur[dst], 1);
    eidx[pos] = ei[i] * 16 + et[i];
}

// ---- CSR gathers ----
__global__ void __launch_bounds__(64)
rgcn_gather(const int* __restrict__ off, const int* __restrict__ eidx,
            const float* __restrict__ xw, float* __restrict__ agg)
{
    const int n = blockIdx.x, h = threadIdx.x;
    const int beg = off[n], end = off[n + 1];
    float acc = 0.f;
    int e = beg;
    for (; e + 4 <= end; e += 4) {
        int p0 = eidx[e], p1 = eidx[e + 1], p2 = eidx[e + 2], p3 = eidx[e + 3];
        acc += xw[(size_t)(p0 >> 4) * 1024 + (p0 & 15) * 64 + h]
             + xw[(size_t)(p1 >> 4) * 1024 + (p1 & 15) * 64 + h]
             + xw[(size_t)(p2 >> 4) * 1024 + (p2 & 15) * 64 + h]
             + xw[(size_t)(p3 >> 4) * 1024 + (p3 & 15) * 64 + h];
    }
    for (; e < end; e++) {
        int p = eidx[e];
        acc += xw[(size_t)(p >> 4) * 1024 + (p & 15) * 64 + h];
    }
    agg[n * NH + h] = acc / fmaxf((float)(end - beg), 1.f);
}
__global__ void __launch_bounds__(64)
gc_gather(const int* __restrict__ off, const int* __restrict__ eidx,
          const float* __restrict__ y, float* __restrict__ nb)
{
    const int n = blockIdx.x, h = threadIdx.x;
    const int beg = off[n], end = off[n + 1];
    float acc = 0.f;
    int e = beg;
    for (; e + 4 <= end; e += 4) {
        int p0 = eidx[e], p1 = eidx[e + 1], p2 = eidx[e + 2], p3 = eidx[e + 3];
        acc += y[(p0 >> 4) * NH + h] + y[(p1 >> 4) * NH + h]
             + y[(p2 >> 4) * NH + h] + y[(p3 >> 4) * NH + h];
    }
    for (; e < end; e++) acc += y[(eidx[e] >> 4) * NH + h];
    nb[n * NH + h] = acc;
}

// head: logits = hid @ Ws + bs ; log_softmax
__global__ void head_kernel(const float* __restrict__ hid, const float* __restrict__ Ws,
                            const float* __restrict__ bsv, float* __restrict__ out)
{
    int n = blockIdx.x * blockDim.x + threadIdx.x;
    if (n >= NND) return;
    float lg[NC];
#pragma unroll
    for (int c = 0; c < NC; c++) lg[c] = bsv[c];
    const float* h = hid + (size_t)n * NH;
#pragma unroll 8
    for (int k = 0; k < NH; k++) {
        float hv = h[k];
#pragma unroll
        for (int c = 0; c < NC; c++) lg[c] = fmaf(hv, Ws[k * NC + c], lg[c]);
    }
    float mx = lg[0];
#pragma unroll
    for (int c = 1; c < NC; c++) mx = fmaxf(mx, lg[c]);
    float ssum = 0.f;
#pragma unroll
    for (int c = 0; c < NC; c++) ssum += expf(lg[c] - mx);
    float lse = mx + logf(ssum);
#pragma unroll
    for (int c = 0; c < NC; c++) out[(size_t)n * NC + c] = lg[c] - lse;
}

// ============================================================
extern "C" void kernel_launch(void* const* d_in, const int* in_sizes, int n_in,
                              void* d_out, int out_size)
{
    const float* x      = (const float*)d_in[0];
    const int*   ei     = (const int*)d_in[1];
    const int*   et     = (const int*)d_in[3];
    const float* umask  = (const float*)d_in[5];
    const float* basis  = (const float*)d_in[8];
    const float* comp   = (const float*)d_in[9];
    const float* root   = (const float*)d_in[10];
    const float* bias1  = (const float*)d_in[11];
    const float* w_nbr  = (const float*)d_in[12];
    const float* w_root = (const float*)d_in[13];
    const float* bias2  = (const float*)d_in[14];
    const float* Wm     = (const float*)d_in[15];
    const float* bm     = (const float*)d_in[16];
    const float* Wl     = (const float*)d_in[17];
    const float* bl     = (const float*)d_in[18];
    const float* Ws     = (const float*)d_in[19];
    const float* bs     = (const float*)d_in[20];
    float* out = (float*)d_out;

#define SYM(T, v, s) T* v; cudaGetSymbolAddress((void**)&v, s)
    SYM(bf16, xh, g_xh); SYM(bf16, xl, g_xl);
    SYM(bf16, WtTh, g_WtTh); SYM(bf16, WtTl, g_WtTl);
    SYM(bf16, rootTh, g_rootTh); SYM(bf16, rootTl, g_rootTl);
    SYM(bf16, wnbrTh, g_wnbrTh); SYM(bf16, wnbrTl, g_wnbrTl);
    SYM(bf16, wrootTh, g_wrootTh); SYM(bf16, wrootTl, g_wrootTl);
    SYM(bf16, WmTh, g_WmTh); SYM(bf16, WmTl, g_WmTl);
    SYM(bf16, WlTh, g_WlTh); SYM(bf16, WlTl, g_WlTl);
    SYM(bf16, h1h, g_h1h); SYM(bf16, h1l, g_h1l);
    SYM(bf16, emoh, g_emoh); SYM(bf16, emol, g_emol);
    SYM(bf16, emoTh, g_emoTh); SYM(bf16, emoTl, g_emoTl);
    SYM(bf16, Qh, g_Qh); SYM(bf16, Ql, g_Ql);
    SYM(bf16, Sh, g_Sh); SYM(bf16, Sl, g_Sl);
    SYM(bf16, atth, g_atth); SYM(bf16, attl, g_attl);
    SYM(float, xw, g_xw); SYM(float, agg, g_agg); SYM(float, y, g_y);
    SYM(float, nb, g_nb); SYM(float, hid, g_hid);
    SYM(int, cnt, g_cnt); SYM(int, off, g_off); SYM(int, cur, g_cur);
    SYM(int, eidx, g_eidx);
#undef SYM

    const int SZ_128_64 = 512 + 2 * 2 * (128 + 64) * 128;   // 98816
    const int SZ_64_128 = 512 + 2 * 2 * (64 + 128) * 128;   // 98816
    const int SZ_64_64  = 512 + 2 * 2 * (64 + 64) * 128;    // 66048

#define SETSM(KERN, SZ) cudaFuncSetAttribute((const void*)(KERN), \
    cudaFuncAttributeMaxDynamicSharedMemorySize, SZ)
    SETSM((mmt<128, 64, 128, false, false, false, false>), SZ_128_64);
    SETSM((mmt<128, 64, 128, false, true,  false, true>),  SZ_128_64);
    SETSM((mmt<128, 64, 128, false, false, false, true>),  SZ_128_64);
    SETSM((mmt<64, 64, 128, true,  true,  false, true>),   SZ_64_64);
    SETSM((mmt<64, 64, 128, false, false, false, false>),  SZ_64_64);
    SETSM((mmt<64, 64, 128, false, true,  true,  false>),  SZ_64_64);
    SETSM(scores_softmax, SZ_64_128);
#undef SETSM

    // ---- operand prep (xw GEMM stays the 4th launch for ncu) ----
    cvtx_kernel<<<(NND * NF) / 256, 256>>>(x, xh, xl, emoh, emol);
    wt_kernel<<<(NF * NRel * NH) / 256, 256>>>(comp, basis, WtTh, WtTl);
    tcvt_all_kernel<<<409600 / 256, 256>>>(
        root, rootTh, rootTl, w_nbr, wnbrTh, wnbrTl, w_root, wrootTh, wrootTl,
        Wm, WmTh, WmTl, Wl, WlTh, WlTl);

    // xw = x @ Wt  [8192,1024], K=512  (MI=2: warp tile 32x64)
    mmt<128, 64, 128, false, false, false, false>
        <<<dim3(16, 64, 1), 128, SZ_128_64>>>(
        xh, xl, 512, 0, WtTh, WtTl, 512, 0,
        xw, nullptr, nullptr, 1024, 0, nullptr, 0, nullptr, 512);

    // ---- CSR build ----
    zero_cnt_kernel<<<NND / 256, 256>>>(cnt);
    hist_kernel<<<NE / 256, 256>>>(ei, cnt);
    scan_kernel<<<1, 1024>>>(cnt, off, cur);
    fill_kernel<<<NE / 256, 256>>>(ei, et, cur, eidx);

    rgcn_gather<<<NND, 64>>>(off, eidx, xw, agg);

    // h1 = agg + x@root + bias1 -> pairs  (K=512)
    mmt<64, 64, 128, true, true, false, true>
        <<<dim3(1, 128, 1), 128, SZ_64_64>>>(
        xh, xl, 512, 0, rootTh, rootTl, 512, 0,
        nullptr, h1h, h1l, 64, 0, agg, 64, bias1, 512);

    // y = h1 @ w_nbr  (fp32, K=64)
    mmt<64, 64, 128, false, false, false, false>
        <<<dim3(1, 128, 1), 128, SZ_64_64>>>(
        h1h, h1l, 64, 0, wnbrTh, wnbrTl, 64, 0,
        y, nullptr, nullptr, 64, 0, nullptr, 0, nullptr, 64);

    gc_gather<<<NND, 64>>>(off, eidx, y, nb);

    // h2 = nb + h1@w_root + bias2 -> emo pairs cols [512,576)  (K=64)
    mmt<64, 64, 128, true, true, false, true>
        <<<dim3(1, 128, 1), 128, SZ_64_64>>>(
        h1h, h1l, 64, 0, wrootTh, wrootTl, 64, 0,
        nullptr, emoh + NF, emol + NF, NDm, 0, nb, 64, bias2, 64);

    emoT_kernel<<<dim3(NDm / 32, NL / 32, NBc), dim3(32, 8)>>>(emoh, emol, emoTh, emoTl);

    // Q = emo @ Wm + bm -> pairs  (K=576, MI=2)
    mmt<128, 64, 128, false, true, false, true>
        <<<dim3(9, 64, 1), 128, SZ_128_64>>>(
        emoh, emol, NDm, 0, WmTh, WmTl, NDm, 0,
        nullptr, Qh, Ql, NDm, 0, nullptr, 0, bm, NDm);

    // fused scores + softmax -> bf16 pairs
    scores_softmax<<<dim3(1, 2, NBc), 128, SZ_64_128>>>(
        Qh, Ql, emoh, emol, umask, Sh, Sl);

    // att = alpha @ emo -> pairs  (B = emoT, K=128, MI=2)
    mmt<128, 64, 128, false, false, false, true>
        <<<dim3(9, 1, NBc), 128, SZ_128_64>>>(
        Sh, Sl, NL, (long long)NL * NL, emoTh, emoTl, NL, (long long)NDm * NL,
        nullptr, atth, attl, NDm, (long long)NL * NDm,
        nullptr, 0, nullptr, NL);

    // hidden = relu(att @ Wl + bl)  (fp32, K=576)
    mmt<64, 64, 128, false, true, true, false>
        <<<dim3(1, 128, 1), 128, SZ_64_64>>>(
        atth, attl, NDm, 0, WlTh, WlTl, NDm, 0,
        hid, nullptr, nullptr, 64, 0, nullptr, 0, bl, NDm);

    head_kernel<<<NND / 128, 128>>>(hid, Ws, bs, out);

    (void)in_sizes; (void)n_in; (void)out_size;
}

// round 9
// speedup vs baseline: 2.7788x; 1.0674x over previous
#include <cuda_runtime.h>
#include <cuda_bf16.h>
#include <math.h>
#include <cstdint>

// ---- problem constants ----
#define NND 8192
#define NF  512
#define NH  64
#define NRel 16
#define NBase 30
#define NE  524288
#define NBc 64
#define NL  128
#define NDm 576
#define NC  7
#define KC  64          // K chunk (bf16) per pipeline stage; 128B rows

typedef __nv_bfloat16 bf16;
typedef unsigned int u32;

// ---- static device scratch ----
__device__ __align__(16) bf16 g_WtTh[1024 * 512];
__device__ __align__(16) bf16 g_WtTl[1024 * 512];
__device__ __align__(16) bf16 g_rootTh[64 * 512];
__device__ __align__(16) bf16 g_rootTl[64 * 512];
__device__ __align__(16) bf16 g_wcatTh[64 * 128];   // [n][k]: k<64 w_root, k>=64 w_nbr
__device__ __align__(16) bf16 g_wcatTl[64 * 128];
__device__ __align__(16) bf16 g_WmTh[576 * 576];
__device__ __align__(16) bf16 g_WmTl[576 * 576];
__device__ __align__(16) bf16 g_WlTh[64 * 576];
__device__ __align__(16) bf16 g_WlTl[64 * 576];
__device__ __align__(16) bf16 g_emoh[(size_t)NND * NDm];
__device__ __align__(16) bf16 g_emol[(size_t)NND * NDm];
__device__ __align__(16) bf16 g_a2h[NND * 128];     // cols [0,64)=h1, [64,128)=agg(h1)
__device__ __align__(16) bf16 g_a2l[NND * 128];
__device__ __align__(16) u32  g_h1p[NND * NH];      // packed (hi,lo) bf16x2 of h1
__device__ __align__(16) bf16 g_Qh[(size_t)NND * NDm];
__device__ __align__(16) bf16 g_Ql[(size_t)NND * NDm];
__device__ __align__(16) bf16 g_Sh[NND * NL];
__device__ __align__(16) bf16 g_Sl[NND * NL];
__device__ __align__(16) bf16 g_eWTh[NBc * NH * NL];  // [b][n][q]
__device__ __align__(16) bf16 g_eWTl[NBc * NH * NL];

__device__ __align__(16) float g_xw[(size_t)NND * NRel * NH];
__device__ __align__(16) float g_agg[NND * NH];
__device__ __align__(16) float g_hid[NND * NH];
// CSR
__device__ int g_cnt[NND];
__device__ int g_off[NND + 1];
__device__ int g_cur[NND];
__device__ int g_eidx[NE];

__device__ __forceinline__ void split_pair(float v, bf16& h, bf16& l) {
    h = __float2bfloat16(v);
    l = __float2bfloat16(v - __bfloat162float(h));
}

__device__ __forceinline__ u32 smem_u32(const void* p) {
    u32 a;
    asm("{ .reg .u64 t; cvta.to.shared.u64 t, %1; cvt.u32.u64 %0, t; }"
        : "=r"(a) : "l"(p));
    return a;
}

__device__ __forceinline__ void mma16816(float* d, const u32* a, const u32* b) {
    asm volatile(
        "mma.sync.aligned.m16n8k16.row.col.f32.bf16.bf16.f32 "
        "{%0,%1,%2,%3}, {%4,%5,%6,%7}, {%8,%9}, {%0,%1,%2,%3};"
        : "+f"(d[0]), "+f"(d[1]), "+f"(d[2]), "+f"(d[3])
        : "r"(a[0]), "r"(a[1]), "r"(a[2]), "r"(a[3]), "r"(b[0]), "r"(b[1]));
}

#define LDSM4(r, addr) \
    asm volatile("ldmatrix.sync.aligned.m8n8.x4.shared.b16 {%0,%1,%2,%3}, [%4];" \
        : "=r"((r)[0]), "=r"((r)[1]), "=r"((r)[2]), "=r"((r)[3]) : "r"(addr))

#define CPA(d, s) \
    asm volatile("cp.async.cg.shared.global [%0], [%1], 16;" :: "r"(d), "l"(s) : "memory")
#define CPC() asm volatile("cp.async.commit_group;" ::: "memory")
#define CPW0() asm volatile("cp.async.wait_group 0;" ::: "memory")
#define CPW1() asm volatile("cp.async.wait_group 1;" ::: "memory")

// ============================================================
// Pipelined warp-MMA 3xBF16 GEMM: C[M,N] = A @ B^T
// Single-barrier 2-stage cp.async pipeline, SW128-swizzled SMEM.
// OUT_T: write pair output transposed per conversation: [m/128][n][m%128].
// Cp (if non-null, with OUT_PAIR): also write packed (hi,lo) u32 at [m*64+n].
// ============================================================
template <int BM, int NT, int THREADS,
          bool ADD_D, bool BIAS, bool RELU, bool OUT_PAIR, bool OUT_T>
__global__ void __launch_bounds__(THREADS, 2)
mmt(const bf16* __restrict__ Ah, const bf16* __restrict__ Al, int lda, long long sA,
    const bf16* __restrict__ Bh, const bf16* __restrict__ Bl, int ldb, long long sB,
    float* __restrict__ C, bf16* __restrict__ Ch, bf16* __restrict__ Cl,
    u32* __restrict__ Cp,
    int ldc, long long sC,
    const float* __restrict__ D, int ldd,
    const float* __restrict__ bias,
    int K)
{
    constexpr int WARPS = THREADS / 32;
    constexpr int WN = NT / 64;
    constexpr int WMC = WARPS / WN;
    constexpr int WM = BM / WMC;
    constexpr int MI = WM / 16;
    constexpr int STAGE_ROWS = 2 * (BM + NT);
    constexpr int STAGE_B = STAGE_ROWS * 128;
    constexpr int CHUNKS = STAGE_ROWS * 8 / THREADS;

    extern __shared__ char smem[];
    const u32 sb0 = smem_u32(smem) + 512;

    const int tid = threadIdx.x;
    const int wid = tid >> 5, lane = tid & 31;
    const int warpM = wid % WMC, warpN = wid / WMC;
    const int bz = blockIdx.z;
    const int m0 = blockIdx.y * BM;
    const int n0 = blockIdx.x * NT;

    const char* pAh = (const char*)(Ah + sA * bz + (size_t)m0 * lda);
    const char* pAl = (const char*)(Al + sA * bz + (size_t)m0 * lda);
    const char* pBh = (const char*)(Bh + sB * bz + (size_t)n0 * ldb);
    const char* pBl = (const char*)(Bl + sB * bz + (size_t)n0 * ldb);
    const size_t ldab = (size_t)lda * 2;
    const size_t ldbb = (size_t)ldb * 2;

    float acc[MI][8][4];
#pragma unroll
    for (int i = 0; i < MI; i++)
#pragma unroll
        for (int j = 0; j < 8; j++)
#pragma unroll
            for (int q = 0; q < 4; q++) acc[i][j][q] = 0.f;

    const int S = K / KC;

    auto load_stage = [&](int s) {
        const size_t kcb = (size_t)s * KC * 2;
        const u32 dst0 = sb0 + (u32)(s & 1) * STAGE_B;
#pragma unroll
        for (int f = 0; f < CHUNKS; f++) {
            int idx = tid + f * THREADS;
            int row = idx >> 3;
            u32 cb = (u32)(idx & 7) << 4;
            u32 sw = cb ^ (((u32)(row & 7)) << 4);
            const char* src;
            if (row < BM)               src = pAh + (size_t)row * ldab + kcb + cb;
            else if (row < 2 * BM)      src = pAl + (size_t)(row - BM) * ldab + kcb + cb;
            else if (row < 2 * BM + NT) src = pBh + (size_t)(row - 2 * BM) * ldbb + kcb + cb;
            else                        src = pBl + (size_t)(row - 2 * BM - NT) * ldbb + kcb + cb;
            CPA(dst0 + (u32)row * 128 + sw, src);
        }
    };

    load_stage(0);
    CPC();

    const u32 xorv = ((u32)(lane & 7)) << 4;
    const u32 aRow = (u32)(warpM * WM + (lane & 15));
    const u32 aCol0 = ((u32)(lane >> 4) & 1) * 16;
    const u32 bRow = (u32)(warpN * 64 + ((lane & 7) | ((lane & 16) >> 1)));
    const u32 bCol0 = ((u32)(lane >> 3) & 1) * 16;

    for (int s = 0; s < S; s++) {
        CPW0();
        __syncthreads();        // stage s visible to all; all done computing s-1
        if (s + 1 < S) { load_stage(s + 1); CPC(); }

        const u32 base = sb0 + (u32)(s & 1) * STAGE_B;
        const u32 aH = base + aRow * 128;
        const u32 aL = aH + (u32)BM * 128;
        const u32 bH = base + (u32)(2 * BM) * 128 + bRow * 128;
        const u32 bL = bH + (u32)NT * 128;

#pragma unroll
        for (int ks = 0; ks < KC / 16; ks++) {
            const u32 kb = (u32)ks * 32;
            const u32 acol = (aCol0 + kb) ^ xorv;
            const u32 bcol = (bCol0 + kb) ^ xorv;
            u32 ah[MI][4], al[MI][4];
#pragma unroll
            for (int mi = 0; mi < MI; mi++) {
                LDSM4(ah[mi], aH + (u32)mi * (16 * 128) + acol);
                LDSM4(al[mi], aL + (u32)mi * (16 * 128) + acol);
            }
#pragma unroll
            for (int nt = 0; nt < 4; nt++) {
                u32 bh[4], bl[4];
                LDSM4(bh, bH + (u32)nt * (16 * 128) + bcol);
                LDSM4(bl, bL + (u32)nt * (16 * 128) + bcol);
#pragma unroll
                for (int mi = 0; mi < MI; mi++)
#pragma unroll
                    for (int half = 0; half < 2; half++) {
                        float* a4 = acc[mi][nt * 2 + half];
                        mma16816(a4, ah[mi], &bh[half * 2]);
                        mma16816(a4, ah[mi], &bl[half * 2]);
                        mma16816(a4, al[mi], &bh[half * 2]);
                    }
            }
        }
    }

    // ---- epilogue ----
#pragma unroll
    for (int mi = 0; mi < MI; mi++) {
        const int rm = m0 + warpM * WM + mi * 16 + (lane >> 2);
#pragma unroll
        for (int ni = 0; ni < 8; ni++) {
            const int n = n0 + warpN * 64 + ni * 8 + (lane & 3) * 2;
#pragma unroll
            for (int half = 0; half < 2; half++) {
                const int m = rm + half * 8;
                float v0 = acc[mi][ni][half * 2];
                float v1 = acc[mi][ni][half * 2 + 1];
                if (BIAS) { v0 += bias[n]; v1 += bias[n + 1]; }
                if (ADD_D) {
                    v0 += D[(size_t)m * ldd + n];
                    v1 += D[(size_t)m * ldd + n + 1];
                }
                if (RELU) { v0 = fmaxf(v0, 0.f); v1 = fmaxf(v1, 0.f); }
                if (OUT_PAIR) {
                    bf16 h0, l0, h1c, l1c;
                    split_pair(v0, h0, l0);
                    split_pair(v1, h1c, l1c);
                    if (OUT_T) {
                        // eWT[b][n][q]: b=m>>7, q=m&127
                        size_t o = ((size_t)(m >> 7) * 64 + n) * 128 + (m & 127);
                        Ch[o] = h0; Ch[o + 128] = h1c;
                        Cl[o] = l0; Cl[o + 128] = l1c;
                    } else {
                        const size_t o = (size_t)sC * bz + (size_t)m * ldc + n;
                        *(__nv_bfloat162*)&Ch[o] = __nv_bfloat162(h0, h1c);
                        *(__nv_bfloat162*)&Cl[o] = __nv_bfloat162(l0, l1c);
                        if (Cp) {
                            __nv_bfloat162 p0(h0, l0), p1(h1c, l1c);
                            uint2 u; u.x = *(u32*)&p0; u.y = *(u32*)&p1;
                            *(uint2*)&Cp[(size_t)m * 64 + n] = u;
                        }
                    }
                } else {
                    float2 f2; f2.x = v0; f2.y = v1;
                    *(float2*)&C[(size_t)sC * bz + (size_t)m * ldc + n] = f2;
                }
            }
        }
    }
}

// ============================================================
// Fused scores kernel: S = tanh((Q.M)*u^2) -> softmax -> *u -> renorm
// ============================================================
__global__ void __launch_bounds__(128, 2)
scores_softmax(const bf16* __restrict__ Qh, const bf16* __restrict__ Ql,
               const bf16* __restrict__ Mh, const bf16* __restrict__ Ml,
               const float* __restrict__ um,
               bf16* __restrict__ Sh, bf16* __restrict__ Sl)
{
    constexpr int BM = 64, NT = 128, THREADS = 128;
    constexpr int STAGE_ROWS = 2 * (BM + NT);
    constexpr int STAGE_B = STAGE_ROWS * 128;
    constexpr int CHUNKS = STAGE_ROWS * 8 / THREADS;

    extern __shared__ char smem[];
    float* ums = (float*)smem;
    float* sbuf = (float*)(smem + 512);
    const u32 sb0 = smem_u32(smem) + 512;

    const int tid = threadIdx.x;
    const int wid = tid >> 5, lane = tid & 31;
    const int warpM = wid & 1, warpN = wid >> 1;
    const int bz = blockIdx.z;
    const int m0 = blockIdx.y * BM;

    const char* pAh = (const char*)(Qh + (size_t)bz * NL * NDm + (size_t)m0 * NDm);
    const char* pAl = (const char*)(Ql + (size_t)bz * NL * NDm + (size_t)m0 * NDm);
    const char* pBh = (const char*)(Mh + (size_t)bz * NL * NDm);
    const char* pBl = (const char*)(Ml + (size_t)bz * NL * NDm);
    const size_t ldab = (size_t)NDm * 2;

    if (tid < NT) ums[tid] = um[bz * NL + tid];

    float acc[2][8][4];
#pragma unroll
    for (int i = 0; i < 2; i++)
#pragma unroll
        for (int j = 0; j < 8; j++)
#pragma unroll
            for (int q = 0; q < 4; q++) acc[i][j][q] = 0.f;

    const int S = NDm / KC;

    auto load_stage = [&](int s) {
        const size_t kcb = (size_t)s * KC * 2;
        const u32 dst0 = sb0 + (u32)(s & 1) * STAGE_B;
#pragma unroll
        for (int f = 0; f < CHUNKS; f++) {
            int idx = tid + f * THREADS;
            int row = idx >> 3;
            u32 cb = (u32)(idx & 7) << 4;
            u32 sw = cb ^ (((u32)(row & 7)) << 4);
            const char* src;
            if (row < BM)               src = pAh + (size_t)row * ldab + kcb + cb;
            else if (row < 2 * BM)      src = pAl + (size_t)(row - BM) * ldab + kcb + cb;
            else if (row < 2 * BM + NT) src = pBh + (size_t)(row - 2 * BM) * ldab + kcb + cb;
            else                        src = pBl + (size_t)(row - 2 * BM - NT) * ldab + kcb + cb;
            CPA(dst0 + (u32)row * 128 + sw, src);
        }
    };

    load_stage(0);
    CPC();

    const u32 xorv = ((u32)(lane & 7)) << 4;
    const u32 aRow = (u32)(warpM * 32 + (lane & 15));
    const u32 aCol0 = ((u32)(lane >> 4) & 1) * 16;
    const u32 bRow = (u32)(warpN * 64 + ((lane & 7) | ((lane & 16) >> 1)));
    const u32 bCol0 = ((u32)(lane >> 3) & 1) * 16;

    for (int s = 0; s < S; s++) {
        CPW0();
        __syncthreads();
        if (s + 1 < S) { load_stage(s + 1); CPC(); }

        const u32 base = sb0 + (u32)(s & 1) * STAGE_B;
        const u32 aH = base + aRow * 128;
        const u32 aL = aH + (u32)BM * 128;
        const u32 bH = base + (u32)(2 * BM) * 128 + bRow * 128;
        const u32 bL = bH + (u32)NT * 128;

#pragma unroll
        for (int ks = 0; ks < KC / 16; ks++) {
            const u32 kb = (u32)ks * 32;
            const u32 acol = (aCol0 + kb) ^ xorv;
            const u32 bcol = (bCol0 + kb) ^ xorv;
            u32 ah[2][4], al[2][4];
#pragma unroll
            for (int mi = 0; mi < 2; mi++) {
                LDSM4(ah[mi], aH + (u32)mi * (16 * 128) + acol);
                LDSM4(al[mi], aL + (u32)mi * (16 * 128) + acol);
            }
#pragma unroll
            for (int nt = 0; nt < 4; nt++) {
                u32 bh[4], bl[4];
                LDSM4(bh, bH + (u32)nt * (16 * 128) + bcol);
                LDSM4(bl, bL + (u32)nt * (16 * 128) + bcol);
#pragma unroll
                for (int mi = 0; mi < 2; mi++)
#pragma unroll
                    for (int half = 0; half < 2; half++) {
                        float* a4 = acc[mi][nt * 2 + half];
                        mma16816(a4, ah[mi], &bh[half * 2]);
                        mma16816(a4, ah[mi], &bl[half * 2]);
                        mma16816(a4, al[mi], &bh[half * 2]);
                    }
            }
        }
    }
    __syncthreads();   // all warps done with last stage before sbuf aliasing

    // ---- tanh(score*u^2) into smem (stride 132) ----
#pragma unroll
    for (int mi = 0; mi < 2; mi++) {
#pragma unroll
        for (int ni = 0; ni < 8; ni++) {
            const int col = warpN * 64 + ni * 8 + (lane & 3) * 2;
            const float u0 = ums[col], u1 = ums[col + 1];
#pragma unroll
            for (int half = 0; half < 2; half++) {
                const int row = warpM * 32 + mi * 16 + (lane >> 2) + half * 8;
                float v0 = tanhf(acc[mi][ni][half * 2] * u0 * u0);
                float v1 = tanhf(acc[mi][ni][half * 2 + 1] * u1 * u1);
                float2 f2; f2.x = v0; f2.y = v1;
                *(float2*)&sbuf[row * 132 + col] = f2;
            }
        }
    }
    __syncthreads();

    // ---- per-row softmax ----
    for (int r8 = 0; r8 < 16; r8++) {
        const int row = wid * 16 + r8;
        float4 v = *(const float4*)&sbuf[row * 132 + lane * 4];
        float mx = fmaxf(fmaxf(v.x, v.y), fmaxf(v.z, v.w));
#pragma unroll
        for (int o = 16; o > 0; o >>= 1)
            mx = fmaxf(mx, __shfl_xor_sync(0xffffffffu, mx, o));
        float e0 = expf(v.x - mx), e1 = expf(v.y - mx);
        float e2 = expf(v.z - mx), e3 = expf(v.w - mx);
        float sum1 = e0 + e1 + e2 + e3;
#pragma unroll
        for (int o = 16; o > 0; o >>= 1)
            sum1 += __shfl_xor_sync(0xffffffffu, sum1, o);
        const int col = lane * 4;
        float a0 = (e0 / sum1) * ums[col];
        float a1 = (e1 / sum1) * ums[col + 1];
        float a2 = (e2 / sum1) * ums[col + 2];
        float a3 = (e3 / sum1) * ums[col + 3];
        float sum2 = a0 + a1 + a2 + a3;
#pragma unroll
        for (int o = 16; o > 0; o >>= 1)
            sum2 += __shfl_xor_sync(0xffffffffu, sum2, o);
        float inv = 1.f / sum2;
        bf16 h0, l0, h1, l1, h2, l2, h3, l3;
        split_pair(a0 * inv, h0, l0);
        split_pair(a1 * inv, h1, l1);
        split_pair(a2 * inv, h2, l2);
        split_pair(a3 * inv, h3, l3);
        const size_t o0 = (size_t)(bz * NL + m0 + row) * NL + col;
        *(__nv_bfloat162*)&Sh[o0]     = __nv_bfloat162(h0, h1);
        *(__nv_bfloat162*)&Sh[o0 + 2] = __nv_bfloat162(h2, h3);
        *(__nv_bfloat162*)&Sl[o0]     = __nv_bfloat162(l0, l1);
        *(__nv_bfloat162*)&Sl[o0 + 2] = __nv_bfloat162(l2, l3);
    }
}

// ============================================================
// conversion kernels
// ============================================================
__global__ void cvtx_kernel(const float* __restrict__ x,
                            bf16* __restrict__ eh, bf16* __restrict__ el)
{
    int i = blockIdx.x * 256 + threadIdx.x;     // 8192*512
    bf16 h, l; split_pair(x[i], h, l);
    int row = i >> 9, c = i & 511;
    size_t eo = (size_t)row * NDm + c;
    eh[eo] = h; el[eo] = l;
}

// batched transpose+split: root, w_root/w_nbr (stacked), Wm, Wl
__global__ void tcvt_all_kernel(
    const float* __restrict__ root, bf16* __restrict__ rTh, bf16* __restrict__ rTl,
    const float* __restrict__ wr, const float* __restrict__ wn,
    bf16* __restrict__ wcTh, bf16* __restrict__ wcTl,
    const float* __restrict__ Wm, bf16* __restrict__ WmTh, bf16* __restrict__ WmTl,
    const float* __restrict__ Wl, bf16* __restrict__ WlTh, bf16* __restrict__ WlTl)
{
    int i = blockIdx.x * 256 + threadIdx.x;
    if (i < 32768) {
        int rr = i / 64, cc = i % 64;
        bf16 h, l; split_pair(root[i], h, l);
        rTh[(size_t)cc * 512 + rr] = h; rTl[(size_t)cc * 512 + rr] = l;
    } else if (i < 36864) {
        int j = i - 32768, rr = j / 64, cc = j % 64;
        bf16 h, l; split_pair(wr[j], h, l);
        wcTh[cc * 128 + rr] = h; wcTl[cc * 128 + rr] = l;
    } else if (i < 40960) {
        int j = i - 36864, rr = j / 64, cc = j % 64;
        bf16 h, l; split_pair(wn[j], h, l);
        wcTh[cc * 128 + 64 + rr] = h; wcTl[cc * 128 + 64 + rr] = l;
    } else if (i < 372736) {
        int j = i - 40960, rr = j / 576, cc = j % 576;
        bf16 h, l; split_pair(Wm[j], h, l);
        WmTh[(size_t)cc * 576 + rr] = h; WmTl[(size_t)cc * 576 + rr] = l;
    } else if (i < 409600) {
        int j = i - 372736, rr = j / 64, cc = j % 64;
        bf16 h, l; split_pair(Wl[j], h, l);
        WlTh[(size_t)cc * 576 + rr] = h; WlTl[(size_t)cc * 576 + rr] = l;
    }
}

__global__ void wt_kernel(const float* __restrict__ comp,
                          const float* __restrict__ basis,
                          bf16* __restrict__ Wh, bf16* __restrict__ Wl)
{
    int idx = blockIdx.x * 256 + threadIdx.x;   // 524288
    int h = idx & 63, rr = (idx >> 6) & 15, k = idx >> 10;
    float acc = 0.f;
#pragma unroll
    for (int b = 0; b < NBase; b++)
        acc = fmaf(comp[rr * NBase + b], basis[((size_t)b * NF + k) * NH + h], acc);
    bf16 hh, ll; split_pair(acc, hh, ll);
    size_t o = (size_t)(rr * 64 + h) * 512 + k;
    Wh[o] = hh; Wl[o] = ll;
}

// ---- CSR build ----
__global__ void zero_cnt_kernel(int* cnt)
{
    int i = blockIdx.x * 256 + threadIdx.x;
    if (i < NND) cnt[i] = 0;
}
__global__ void hist_kernel(const int* __restrict__ ei, int* __restrict__ cnt)
{
    int i = blockIdx.x * 256 + threadIdx.x;
    if (i < NE) atomicAdd(&cnt[ei[NE + i]], 1);
}
// scan: per-thread serial 8 + shfl warp scans
__global__ void __launch_bounds__(1024)
scan_kernel(const int* __restrict__ cnt, int* __restrict__ off, int* __restrict__ cur)
{
    __shared__ int wsum[32];
    int t = threadIdx.x;
    int c[8], pre[8], p = 0;
#pragma unroll
    for (int j = 0; j < 8; j++) { c[j] = cnt[t * 8 + j]; pre[j] = p; p += c[j]; }
    const int tot = p;
    const int lane = t & 31, w = t >> 5;
    int sc = tot;
#pragma unroll
    for (int o = 1; o < 32; o <<= 1) {
        int v = __shfl_up_sync(0xffffffffu, sc, o);
        if (lane >= o) sc += v;
    }
    if (lane == 31) wsum[w] = sc;
    __syncthreads();
    if (w == 0) {
        int v = wsum[lane];
#pragma unroll
        for (int o = 1; o < 32; o <<= 1) {
            int x = __shfl_up_sync(0xffffffffu, v, o);
            if (lane >= o) v += x;
        }
        wsum[lane] = v;
    }
    __syncthreads();
    const int base = (w ? wsum[w - 1] : 0) + (sc - tot);
#pragma unroll
    for (int j = 0; j < 8; j++) {
        off[t * 8 + j + 1] = base + pre[j] + c[j];
        cur[t * 8 + j] = base + pre[j];
    }
    if (t == 0) off[0] = 0;
}
__global__ void fill_kernel(const int* __restrict__ ei, const int* __restrict__ et,
                            int* __restrict__ cur, int* __restrict__ eidx)
{
    int i = blockIdx.x * 256 + threadIdx.x;
    if (i >= NE) return;
    int dst = ei[NE + i];
    int pos = atomicAdd(&cur[dst], 1);
    eidx[pos] = ei[i] * 16 + et[i];
}

// ---- CSR gathers ----
__global__ void __launch_bounds__(64)
rgcn_gather(const int* __restrict__ off, const int* __restrict__ eidx,
            const float* __restrict__ xw, float* __restrict__ agg)
{
    const int n = blockIdx.x, h = threadIdx.x;
    const int beg = off[n], end = off[n + 1];
    float acc = 0.f;
    int e = beg;
    for (; e + 4 <= end; e += 4) {
        int p0 = eidx[e], p1 = eidx[e + 1], p2 = eidx[e + 2], p3 = eidx[e + 3];
        acc += xw[(size_t)(p0 >> 4) * 1024 + (p0 & 15) * 64 + h]
             + xw[(size_t)(p1 >> 4) * 1024 + (p1 & 15) * 64 + h]
             + xw[(size_t)(p2 >> 4) * 1024 + (p2 & 15) * 64 + h]
             + xw[(size_t)(p3 >> 4) * 1024 + (p3 & 15) * 64 + h];
    }
    for (; e < end; e++) {
        int p = eidx[e];
        acc += xw[(size_t)(p >> 4) * 1024 + (p & 15) * 64 + h];
    }
    agg[n * NH + h] = acc / fmaxf((float)(end - beg), 1.f);
}

// gather sum of h1 (packed pairs) -> a2 pair cols [64,128)
__global__ void __launch_bounds__(64)
gc_gather(const int* __restrict__ off, const int* __restrict__ eidx,
          const u32* __restrict__ h1p, bf16* __restrict__ a2h, bf16* __restrict__ a2l)
{
    const int n = blockIdx.x, h = threadIdx.x;
    const int beg = off[n], end = off[n + 1];
    float acc = 0.f;
    int e = beg;
    for (; e + 4 <= end; e += 4) {
        u32 q0 = h1p[(eidx[e] >> 4) * 64 + h];
        u32 q1 = h1p[(eidx[e + 1] >> 4) * 64 + h];
        u32 q2 = h1p[(eidx[e + 2] >> 4) * 64 + h];
        u32 q3 = h1p[(eidx[e + 3] >> 4) * 64 + h];
        __nv_bfloat162 t0 = *(__nv_bfloat162*)&q0, t1 = *(__nv_bfloat162*)&q1;
        __nv_bfloat162 t2 = *(__nv_bfloat162*)&q2, t3 = *(__nv_bfloat162*)&q3;
        acc += __bfloat162float(t0.x) + __bfloat162float(t0.y)
             + __bfloat162float(t1.x) + __bfloat162float(t1.y)
             + __bfloat162float(t2.x) + __bfloat162float(t2.y)
             + __bfloat162float(t3.x) + __bfloat162float(t3.y);
    }
    for (; e < end; e++) {
        u32 q = h1p[(eidx[e] >> 4) * 64 + h];
        __nv_bfloat162 t = *(__nv_bfloat162*)&q;
        acc += __bfloat162float(t.x) + __bfloat162float(t.y);
    }
    bf16 hh, ll; split_pair(acc, hh, ll);
    a2h[n * 128 + 64 + h] = hh;
    a2l[n * 128 + 64 + h] = ll;
}

// head: logits = hid @ Ws + bs ; log_softmax
__global__ void head_kernel(const float* __restrict__ hid, const float* __restrict__ Ws,
                            const float* __restrict__ bsv, float* __restrict__ out)
{
    int n = blockIdx.x * blockDim.x + threadIdx.x;
    if (n >= NND) return;
    float lg[NC];
#pragma unroll
    for (int c = 0; c < NC; c++) lg[c] = bsv[c];
    const float* h = hid + (size_t)n * NH;
#pragma unroll 8
    for (int k = 0; k < NH; k++) {
        float hv = h[k];
#pragma unroll
        for (int c = 0; c < NC; c++) lg[c] = fmaf(hv, Ws[k * NC + c], lg[c]);
    }
    float mx = lg[0];
#pragma unroll
    for (int c = 1; c < NC; c++) mx = fmaxf(mx, lg[c]);
    float ssum = 0.f;
#pragma unroll
    for (int c = 0; c < NC; c++) ssum += expf(lg[c] - mx);
    float lse = mx + logf(ssum);
#pragma unroll
    for (int c = 0; c < NC; c++) out[(size_t)n * NC + c] = lg[c] - lse;
}

// ============================================================
extern "C" void kernel_launch(void* const* d_in, const int* in_sizes, int n_in,
                              void* d_out, int out_size)
{
    const float* x      = (const float*)d_in[0];
    const int*   ei     = (const int*)d_in[1];
    const int*   et     = (const int*)d_in[3];
    const float* umask  = (const float*)d_in[5];
    const float* basis  = (const float*)d_in[8];
    const float* comp   = (const float*)d_in[9];
    const float* root   = (const float*)d_in[10];
    const float* bias1  = (const float*)d_in[11];
    const float* w_nbr  = (const float*)d_in[12];
    const float* w_root = (const float*)d_in[13];
    const float* bias2  = (const float*)d_in[14];
    const float* Wm     = (const float*)d_in[15];
    const float* bm     = (const float*)d_in[16];
    const float* Wl     = (const float*)d_in[17];
    const float* bl     = (const float*)d_in[18];
    const float* Ws     = (const float*)d_in[19];
    const float* bs     = (const float*)d_in[20];
    float* out = (float*)d_out;

#define SYM(T, v, s) T* v; cudaGetSymbolAddress((void**)&v, s)
    SYM(bf16, WtTh, g_WtTh); SYM(bf16, WtTl, g_WtTl);
    SYM(bf16, rootTh, g_rootTh); SYM(bf16, rootTl, g_rootTl);
    SYM(bf16, wcatTh, g_wcatTh); SYM(bf16, wcatTl, g_wcatTl);
    SYM(bf16, WmTh, g_WmTh); SYM(bf16, WmTl, g_WmTl);
    SYM(bf16, WlTh, g_WlTh); SYM(bf16, WlTl, g_WlTl);
    SYM(bf16, emoh, g_emoh); SYM(bf16, emol, g_emol);
    SYM(bf16, a2h, g_a2h); SYM(bf16, a2l, g_a2l);
    SYM(u32, h1p, g_h1p);
    SYM(bf16, Qh, g_Qh); SYM(bf16, Ql, g_Ql);
    SYM(bf16, Sh, g_Sh); SYM(bf16, Sl, g_Sl);
    SYM(bf16, eWTh, g_eWTh); SYM(bf16, eWTl, g_eWTl);
    SYM(float, xw, g_xw); SYM(float, agg, g_agg); SYM(float, hid, g_hid);
    SYM(int, cnt, g_cnt); SYM(int, off, g_off); SYM(int, cur, g_cur);
    SYM(int, eidx, g_eidx);
#undef SYM

    const int SZ_128_64 = 512 + 2 * 2 * (128 + 64) * 128;   // 98816
    const int SZ_64_128 = 512 + 2 * 2 * (64 + 128) * 128;   // 98816
    const int SZ_64_64  = 512 + 2 * 2 * (64 + 64) * 128;    // 66048

#define SETSM(KERN, SZ) cudaFuncSetAttribute((const void*)(KERN), \
    cudaFuncAttributeMaxDynamicSharedMemorySize, SZ)
    SETSM((mmt<128, 64, 128, false, false, false, false, false>), SZ_128_64);
    SETSM((mmt<64, 64, 128, true,  true,  false, true,  false>),  SZ_64_64);
    SETSM((mmt<64, 64, 128, false, true,  false, true,  false>),  SZ_64_64);
    SETSM((mmt<128, 64, 128, false, true,  false, true,  false>), SZ_128_64);
    SETSM((mmt<64, 64, 128, false, false, false, true,  true>),   SZ_64_64);
    SETSM((mmt<128, 64, 128, false, true,  true,  false, false>), SZ_128_64);
    SETSM(scores_softmax, SZ_64_128);
#undef SETSM

    // ---- operand prep (xw GEMM stays the 4th launch for ncu) ----
    cvtx_kernel<<<(NND * NF) / 256, 256>>>(x, emoh, emol);
    wt_kernel<<<(NF * NRel * NH) / 256, 256>>>(comp, basis, WtTh, WtTl);
    tcvt_all_kernel<<<409600 / 256, 256>>>(
        root, rootTh, rootTl, w_root, w_nbr, wcatTh, wcatTl,
        Wm, WmTh, WmTl, Wl, WlTh, WlTl);

    // xw = x @ Wt  (A = emo cols [0,512), lda=576)
    mmt<128, 64, 128, false, false, false, false, false>
        <<<dim3(16, 64, 1), 128, SZ_128_64>>>(
        emoh, emol, NDm, 0, WtTh, WtTl, 512, 0,
        xw, nullptr, nullptr, nullptr, 1024, 0, nullptr, 0, nullptr, 512);

    // ---- CSR build ----
    zero_cnt_kernel<<<NND / 256, 256>>>(cnt);
    hist_kernel<<<NE / 256, 256>>>(ei, cnt);
    scan_kernel<<<1, 1024>>>(cnt, off, cur);
    fill_kernel<<<NE / 256, 256>>>(ei, et, cur, eidx);

    rgcn_gather<<<NND, 64>>>(off, eidx, xw, agg);

    // h1 = agg + x@root + bias1 -> a2 cols [0,64) pairs + packed h1p
    mmt<64, 64, 128, true, true, false, true, false>
        <<<dim3(1, 128, 1), 128, SZ_64_64>>>(
        emoh, emol, NDm, 0, rootTh, rootTl, 512, 0,
        nullptr, a2h, a2l, h1p, 128, 0, agg, 64, bias1, 512);

    // gather(h1) -> a2 cols [64,128) pairs   (GraphConv, linearity)
    gc_gather<<<NND, 64>>>(off, eidx, h1p, a2h, a2l);

    // h2 = [h1 | aggH1] @ [w_root; w_nbr] + bias2 -> emo cols [512,576)
    mmt<64, 64, 128, false, true, false, true, false>
        <<<dim3(1, 128, 1), 128, SZ_64_64>>>(
        a2h, a2l, 128, 0, wcatTh, wcatTl, 128, 0,
        nullptr, emoh + NF, emol + NF, nullptr, NDm, 0, nullptr, 0, bias2, 128);

    // Q = emo @ Wm + bm -> pairs
    mmt<128, 64, 128, false, true, false, true, false>
        <<<dim3(9, 64, 1), 128, SZ_128_64>>>(
        emoh, emol, NDm, 0, WmTh, WmTl, NDm, 0,
        nullptr, Qh, Ql, nullptr, NDm, 0, nullptr, 0, bm, NDm);

    // eW = emo @ Wl -> per-conversation TRANSPOSED pairs eWT[b][n][q]
    mmt<64, 64, 128, false, false, false, true, true>
        <<<dim3(1, 128, 1), 128, SZ_64_64>>>(
        emoh, emol, NDm, 0, WlTh, WlTl, NDm, 0,
        nullptr, eWTh, eWTl, nullptr, 0, 0, nullptr, 0, nullptr, NDm);

    // fused scores + softmax -> bf16 pairs
    scores_softmax<<<dim3(1, 2, NBc), 128, SZ_64_128>>>(
        Qh, Ql, emoh, emol, umask, Sh, Sl);

    // hidden = relu(alpha @ eWT + bl)   (batched, K=128, N=64)
    mmt<128, 64, 128, false, true, true, false, false>
        <<<dim3(1, 1, NBc), 128, SZ_128_64>>>(
        Sh, Sl, NL, (long long)NL * NL, eWTh, eWTl, NL, (long long)NH * NL,
        hid, nullptr, nullptr, nullptr, NH, (long long)NL * NH, nullptr, 0, bl, NL);

    head_kernel<<<NND / 128, 128>>>(hid, Ws, bs, out);

    (void)in_sizes; (void)n_in; (void)out_size;
}